// round 1
// baseline (speedup 1.0000x reference)
#include <cuda_runtime.h>

#define Bn 8
#define Tn 2048
#define Cn 768
#define NHn 12
#define HSn 64
#define BHn (Bn*NHn)        // 96
#define NSEG 255
#define LMIN 16
#define NTOK (BHn*Tn)       // 196608
#define NEG_INF __int_as_float(0xff800000u)

// ---------------- device scratch (static; no runtime allocation) ----------------
__device__ float g_q [BHn*Tn*HSn];
__device__ float g_k [BHn*Tn*HSn];
__device__ float g_v0[BHn*Tn*HSn];
__device__ float g_v [BHn*Tn*HSn];
__device__ float g_kc[BHn*Tn*HSn];
__device__ float g_vc[BHn*Tn*HSn];
__device__ float g_Ks[BHn*NSEG*HSn];
__device__ float g_Vs[BHn*NSEG*HSn];
__device__ float g_y [Bn*Tn*Cn];
__device__ float g_WvT[HSn*HSn*HSn];   // [4096][64]  WvT[i*64+j][e] = Wv[e][i*64+j]
__device__ int   g_lidx[NSEG];
__device__ int   g_ridx[NSEG];

// ---------------- segment index tables ----------------
__global__ void init_sets_kernel() {
    int s = threadIdx.x;
    if (s < NSEG) {
        int v = 0, rem = s;
        while (rem >= (128 >> v)) { rem -= (128 >> v); v++; }
        int L = LMIN << v;
        g_lidx[s] = rem * L;
        g_ridx[s] = (rem + 1) * L - 1;
    }
}

// ---------------- Wv transpose: (64, 4096) -> (4096, 64) ----------------
__global__ void wvt_kernel(const float* __restrict__ Wv) {
    int idx = blockIdx.x * 256 + threadIdx.x;      // < 262144
    int kidx = idx >> 6, e = idx & 63;
    g_WvT[idx] = Wv[e * 4096 + kidx];
}

// ---------------- qkv GEMM: (16384x768) @ (2304x768)^T, scatter to per-head ----------------
__global__ void __launch_bounds__(256) qkv_gemm(const float* __restrict__ x,
                                                const float* __restrict__ W) {
    __shared__ float As[16][64];
    __shared__ float Bs[16][64];
    const int n0 = blockIdx.x * 64, m0 = blockIdx.y * 64;
    const int tid = threadIdx.x, tx = tid & 15, ty = tid >> 4;
    const int lr = tid >> 2, lc = (tid & 3) << 2;
    float acc[4][4] = {};
    const float* aptr = x + (m0 + lr) * Cn + lc;
    const float* bptr = W + (n0 + lr) * Cn + lc;
    for (int k0 = 0; k0 < Cn; k0 += 16) {
        float4 a4 = *(const float4*)(aptr + k0);
        float4 b4 = *(const float4*)(bptr + k0);
        As[lc + 0][lr] = a4.x; As[lc + 1][lr] = a4.y; As[lc + 2][lr] = a4.z; As[lc + 3][lr] = a4.w;
        Bs[lc + 0][lr] = b4.x; Bs[lc + 1][lr] = b4.y; Bs[lc + 2][lr] = b4.z; Bs[lc + 3][lr] = b4.w;
        __syncthreads();
#pragma unroll
        for (int kk = 0; kk < 16; kk++) {
            float4 av = *(const float4*)&As[kk][ty << 2];
            float4 bv = *(const float4*)&Bs[kk][tx << 2];
            float a[4] = {av.x, av.y, av.z, av.w};
            float b[4] = {bv.x, bv.y, bv.z, bv.w};
#pragma unroll
            for (int i = 0; i < 4; i++)
#pragma unroll
                for (int j = 0; j < 4; j++) acc[i][j] += a[i] * b[j];
        }
        __syncthreads();
    }
#pragma unroll
    for (int i = 0; i < 4; i++) {
        int m = m0 + (ty << 2) + i;
        int b = m >> 11, t = m & 2047;
#pragma unroll
        for (int j = 0; j < 4; j++) {
            int n = n0 + (tx << 2) + j;
            int which = n / Cn, cc = n - which * Cn;
            int h = cc >> 6, d = cc & 63;
            float* dst = (which == 0) ? g_q : (which == 1) ? g_k : g_v0;
            dst[((b * NHn + h) * Tn + t) * HSn + d] = acc[i][j];
        }
    }
}

// ---------------- v-mix: v[t,e] = sum_{i,j} k[t,i]*v0[t,j]*Wv[e,i*64+j] + bv[e] ----------------
// GEMM with on-the-fly A: block = 64 tokens x 64 e, K = 4096 (i outer, j inner)
__global__ void __launch_bounds__(256) vmix_kernel(const float* __restrict__ bv) {
    __shared__ float kt [64][64];   // kt[i][tok]
    __shared__ float v0t[64][64];   // v0t[j][tok]
    __shared__ float Ws [64][64];   // Ws[j][e] for current i
    const int tok0 = blockIdx.x * 64;
    const int tid = threadIdx.x, tx = tid & 15, ty = tid >> 4;
#pragma unroll
    for (int p = 0; p < 16; p++) {
        int idx = tid + p * 256;
        int t = idx >> 6, d = idx & 63;
        float kv  = g_k [(tok0 + t) * HSn + d];
        float v0v = g_v0[(tok0 + t) * HSn + d];
        kt [d][t] = kv;
        v0t[d][t] = v0v;
    }
    float acc[4][4] = {};
    for (int i = 0; i < 64; i++) {
        __syncthreads();
#pragma unroll
        for (int p = 0; p < 4; p++) {
            int idx = tid + p * 256;
            int j = idx >> 4, e4 = (idx & 15) << 2;
            *(float4*)&Ws[j][e4] = *(const float4*)(g_WvT + (i * 64 + j) * 64 + e4);
        }
        __syncthreads();
        float4 kv4 = *(const float4*)&kt[i][ty << 2];
        float ki[4] = {kv4.x, kv4.y, kv4.z, kv4.w};
#pragma unroll 16
        for (int j = 0; j < 64; j++) {
            float4 a4 = *(const float4*)&v0t[j][ty << 2];
            float4 b4 = *(const float4*)&Ws[j][tx << 2];
            float a[4] = {ki[0] * a4.x, ki[1] * a4.y, ki[2] * a4.z, ki[3] * a4.w};
            float b[4] = {b4.x, b4.y, b4.z, b4.w};
#pragma unroll
            for (int q = 0; q < 4; q++)
#pragma unroll
                for (int r = 0; r < 4; r++) acc[q][r] += a[q] * b[r];
        }
    }
#pragma unroll
    for (int q = 0; q < 4; q++) {
        int t = tok0 + (ty << 2) + q;
#pragma unroll
        for (int r = 0; r < 4; r++) {
            int e = (tx << 2) + r;
            g_v[t * HSn + e] = acc[q][r] + bv[e];
        }
    }
}

// ---------------- cumsum over t for k and v ----------------
__global__ void cumsum_kernel() {
    int bh = blockIdx.x, d = threadIdx.x;
    const float* src = blockIdx.y ? g_v : g_k;
    float*       dst = blockIdx.y ? g_vc : g_kc;
    int base = bh * Tn * HSn + d;
    float acc = 0.f;
    for (int t = 0; t < Tn; t++) {
        acc += src[base + t * HSn];
        dst[base + t * HSn] = acc;
    }
}

// ---------------- segment sums ----------------
__global__ void seg_kernel() {
    int s = blockIdx.x, bh = blockIdx.y, d = threadIdx.x;
    int l = g_lidx[s], r = g_ridx[s];
    int base = bh * Tn * HSn + d;
    float kr = g_kc[base + r * HSn];
    float vr = g_vc[base + r * HSn];
    if (l >= 1) {
        kr -= g_kc[base + (l - 1) * HSn];
        vr -= g_vc[base + (l - 1) * HSn];
    }
    int o = (bh * NSEG + s) * HSn + d;
    g_Ks[o] = kr;
    g_Vs[o] = vr;
}

// ---------------- attention: logits + softmax + AV, fused per (bh, 32-token tile) ----------------
__global__ void __launch_bounds__(256) attn_kernel() {
    __shared__ float qst[64][32];      // q transposed: qst[d][t_local]
    __shared__ float lg[32][257];      // logits / probs, [t_local][s + tail]
    const int bh = blockIdx.y, t0 = blockIdx.x * 32;
    const int tid = threadIdx.x;
    const float scale = 0.125f;        // 1/sqrt(64)
    const int qbase = (bh * Tn + t0) * HSn;

    for (int p = 0; p < 8; p++) {
        int idx = tid + p * 256;
        int t = idx >> 6, d = idx & 63;
        qst[d][t] = g_q[qbase + idx];
    }
    __syncthreads();

    // phase 2: segment logits. s uniform per warp; t_local = lane.
    for (int idx = tid; idx < 32 * NSEG; idx += 256) {
        int tl = idx & 31, s = idx >> 5;
        int tg = t0 + tl;
        int r = g_ridx[s];
        float val = NEG_INF;
        if (t0 + 31 >= r) {   // warp-uniform: at least one token in tile sees this segment
            const float* Kp = g_Ks + (bh * NSEG + s) * HSn;
            float acc = 0.f;
#pragma unroll
            for (int d = 0; d < 64; d += 4) {
                float4 k4 = *(const float4*)(Kp + d);
                acc += qst[d + 0][tl] * k4.x + qst[d + 1][tl] * k4.y
                     + qst[d + 2][tl] * k4.z + qst[d + 3][tl] * k4.w;
            }
            if (tg >= r) val = acc * scale;
        }
        lg[tl][s] = val;
    }

    // tail logit
    if (tid < 32) {
        int tl = tid, tg = t0 + tl;
        int lt = tg & ~(LMIN - 1);
        const float* kc  = g_kc + (bh * Tn + tg) * HSn;
        int lm = (lt >= 1) ? (lt - 1) : 0;
        const float* kcl = g_kc + (bh * Tn + lm) * HSn;
        bool sub = (lt >= 1);
        float acc = 0.f;
#pragma unroll
        for (int d = 0; d < 64; d++) {
            float kv = kc[d];
            if (sub) kv -= kcl[d];
            acc += qst[d][tl] * kv;
        }
        lg[tl][255] = acc * scale;
    }
    __syncthreads();

    // phase 3: softmax over 256 entries, warp per 4 tokens
    int warp = tid >> 5, lane = tid & 31;
#pragma unroll
    for (int u = 0; u < 4; u++) {
        int t = warp * 4 + u;
        float m = NEG_INF;
        for (int s = lane; s < 256; s += 32) m = fmaxf(m, lg[t][s]);
#pragma unroll
        for (int o = 16; o; o >>= 1) m = fmaxf(m, __shfl_xor_sync(0xffffffffu, m, o));
        float sum = 0.f;
        for (int s = lane; s < 256; s += 32) {
            float p = __expf(lg[t][s] - m);
            lg[t][s] = p;
            sum += p;
        }
#pragma unroll
        for (int o = 16; o; o >>= 1) sum += __shfl_xor_sync(0xffffffffu, sum, o);
        float inv = 1.0f / sum;
        for (int s = lane; s < 256; s += 32) lg[t][s] *= inv;
    }
    __syncthreads();

    // phase 4: out = att @ V + att_tail * V_tail; skip invalid segments via per-level prefix
    const float* Vbase = g_Vs + bh * NSEG * HSn;
    for (int p = 0; p < 8; p++) {
        int idx = tid + p * 256;
        int tl = idx >> 6, d = idx & 63;
        int tg = t0 + tl;
        float acc = 0.f;
#pragma unroll
        for (int v = 0; v < 8; v++) {
            int start = 256 - (256 >> v);
            int cnt = (tg + 1) >> (4 + v);
            for (int ii = 0; ii < cnt; ii++) {
                int s = start + ii;
                acc += lg[tl][s] * Vbase[s * HSn + d];
            }
        }
        int lt = tg & ~(LMIN - 1);
        float vt = g_vc[(bh * Tn + tg) * HSn + d];
        if (lt >= 1) vt -= g_vc[(bh * Tn + lt - 1) * HSn + d];
        acc += lg[tl][255] * vt;
        int b = bh / NHn, h = bh - b * NHn;
        g_y[(b * Tn + tg) * Cn + h * HSn + d] = acc;
    }
}

// ---------------- output projection: (16384x768) @ (768x768)^T ----------------
__global__ void __launch_bounds__(256) proj_gemm(const float* __restrict__ W,
                                                 float* __restrict__ out) {
    __shared__ float As[16][64];
    __shared__ float Bs[16][64];
    const int n0 = blockIdx.x * 64, m0 = blockIdx.y * 64;
    const int tid = threadIdx.x, tx = tid & 15, ty = tid >> 4;
    const int lr = tid >> 2, lc = (tid & 3) << 2;
    float acc[4][4] = {};
    const float* aptr = g_y + (m0 + lr) * Cn + lc;
    const float* bptr = W + (n0 + lr) * Cn + lc;
    for (int k0 = 0; k0 < Cn; k0 += 16) {
        float4 a4 = *(const float4*)(aptr + k0);
        float4 b4 = *(const float4*)(bptr + k0);
        As[lc + 0][lr] = a4.x; As[lc + 1][lr] = a4.y; As[lc + 2][lr] = a4.z; As[lc + 3][lr] = a4.w;
        Bs[lc + 0][lr] = b4.x; Bs[lc + 1][lr] = b4.y; Bs[lc + 2][lr] = b4.z; Bs[lc + 3][lr] = b4.w;
        __syncthreads();
#pragma unroll
        for (int kk = 0; kk < 16; kk++) {
            float4 av = *(const float4*)&As[kk][ty << 2];
            float4 bv = *(const float4*)&Bs[kk][tx << 2];
            float a[4] = {av.x, av.y, av.z, av.w};
            float b[4] = {bv.x, bv.y, bv.z, bv.w};
#pragma unroll
            for (int i = 0; i < 4; i++)
#pragma unroll
                for (int j = 0; j < 4; j++) acc[i][j] += a[i] * b[j];
        }
        __syncthreads();
    }
#pragma unroll
    for (int i = 0; i < 4; i++) {
        int m = m0 + (ty << 2) + i;
#pragma unroll
        for (int j = 0; j < 4; j++) {
            int n = n0 + (tx << 2) + j;
            out[m * Cn + n] = acc[i][j];
        }
    }
}

// ---------------- launch ----------------
extern "C" void kernel_launch(void* const* d_in, const int* in_sizes, int n_in,
                              void* d_out, int out_size) {
    const float* x     = (const float*)d_in[0];
    const float* Wqkv  = (const float*)d_in[1];
    const float* Wproj = (const float*)d_in[2];
    const float* Wv    = (const float*)d_in[3];
    const float* bv    = (const float*)d_in[4];
    float* out = (float*)d_out;

    init_sets_kernel<<<1, 256>>>();
    wvt_kernel<<<1024, 256>>>(Wv);
    qkv_gemm<<<dim3(36, 256), 256>>>(x, Wqkv);
    vmix_kernel<<<NTOK / 64, 256>>>(bv);
    cumsum_kernel<<<dim3(BHn, 2), 64>>>();
    seg_kernel<<<dim3(NSEG, BHn), 64>>>();
    attn_kernel<<<dim3(Tn / 32, BHn), 256>>>();
    proj_gemm<<<dim3(Cn / 64, 256), 256>>>(Wproj, out);
}

// round 2
// speedup vs baseline: 1.8766x; 1.8766x over previous
#include <cuda_runtime.h>
#include <cuda_bf16.h>

#define Bn 8
#define Tn 2048
#define Cn 768
#define NHn 12
#define HSn 64
#define BHn (Bn*NHn)        // 96
#define NSEG 255
#define LMIN 16
#define NTOK (BHn*Tn)       // 196608
#define NEG_INF __int_as_float(0xff800000u)

// ---------------- device scratch ----------------
__device__ float g_q    [NTOK*HSn];
__device__ float g_k    [NTOK*HSn];
__device__ float g_v0   [NTOK*HSn];
__device__ float g_v    [NTOK*HSn];
__device__ float g_ktail[NTOK*HSn];
__device__ float g_vtail[NTOK*HSn];
__device__ float g_Ks   [BHn*NSEG*HSn];
__device__ float g_Vs   [BHn*NSEG*HSn];
__device__ float g_y    [Bn*Tn*Cn];
__device__ __nv_bfloat16 g_xh [Bn*Tn*Cn],   g_xl [Bn*Tn*Cn];
__device__ __nv_bfloat16 g_wqh[3*Cn*Cn],    g_wql[3*Cn*Cn];
__device__ __nv_bfloat16 g_wvh[HSn*HSn*HSn],g_wvl[HSn*HSn*HSn];
__device__ __nv_bfloat16 g_wph[Cn*Cn],      g_wpl[Cn*Cn];
__device__ int g_ridx[NSEG];

// ---------------- helpers ----------------
__device__ __forceinline__ void mma_bf16(float* c, const unsigned* a, const unsigned* b) {
    asm volatile(
        "mma.sync.aligned.m16n8k16.row.col.f32.bf16.bf16.f32 "
        "{%0,%1,%2,%3}, {%4,%5,%6,%7}, {%8,%9}, {%0,%1,%2,%3};\n"
        : "+f"(c[0]), "+f"(c[1]), "+f"(c[2]), "+f"(c[3])
        : "r"(a[0]), "r"(a[1]), "r"(a[2]), "r"(a[3]), "r"(b[0]), "r"(b[1]));
}

__device__ __forceinline__ void ldfragA(unsigned* a, const unsigned* S, int r, int kw, int tg) {
    a[0] = S[r * 20 + kw + tg];
    a[1] = S[(r + 8) * 20 + kw + tg];
    a[2] = S[r * 20 + kw + tg + 4];
    a[3] = S[(r + 8) * 20 + kw + tg + 4];
}
__device__ __forceinline__ void ldfragB(unsigned* b, const unsigned* S, int n, int kw, int tg) {
    b[0] = S[n * 20 + kw + tg];
    b[1] = S[n * 20 + kw + tg + 4];
}

// ---------------- init segment r-index ----------------
__global__ void init_sets_kernel() {
    int s = threadIdx.x;
    if (s < NSEG) {
        int v = 0, rem = s;
        while (rem >= (128 >> v)) { rem -= (128 >> v); v++; }
        int L = LMIN << v;
        g_ridx[s] = (rem + 1) * L - 1;
    }
}

// ---------------- split fp32 -> bf16 hi/lo ----------------
__global__ void split_kernel(const float* __restrict__ src, int which, int n) {
    int i = blockIdx.x * 256 + threadIdx.x;
    if (i >= n) return;
    __nv_bfloat16 *h, *l;
    switch (which) {
        case 0: h = g_xh;  l = g_xl;  break;
        case 1: h = g_wqh; l = g_wql; break;
        case 2: h = g_wvh; l = g_wvl; break;
        default:h = g_wph; l = g_wpl; break;
    }
    float x = src[i];
    __nv_bfloat16 hh = __float2bfloat16(x);
    h[i] = hh;
    l[i] = __float2bfloat16(x - __bfloat162float(hh));
}

// ---------------- qkv GEMM (tensor core, bf16x3): 16384x2304x768 ----------------
__global__ void __launch_bounds__(256) qkv_mma() {
    __shared__ unsigned Ah[128 * 20], Al[128 * 20];
    __shared__ unsigned Bh[64 * 20],  Bl[64 * 20];
    const int m0 = blockIdx.y * 128, n0 = blockIdx.x * 64;
    const int tid = threadIdx.x, wid = tid >> 5, lane = tid & 31;
    const int wm = wid >> 1, wn = wid & 1;
    const int g = lane >> 2, tg = lane & 3;
    const unsigned* xh32 = (const unsigned*)g_xh;
    const unsigned* xl32 = (const unsigned*)g_xl;
    const unsigned* wh32 = (const unsigned*)g_wqh;
    const unsigned* wl32 = (const unsigned*)g_wql;
    float c[2][4][4];
#pragma unroll
    for (int i = 0; i < 2; i++)
#pragma unroll
        for (int j = 0; j < 4; j++)
#pragma unroll
            for (int r = 0; r < 4; r++) c[i][j][r] = 0.f;

    for (int k0 = 0; k0 < Cn; k0 += 32) {
#pragma unroll
        for (int p = 0; p < 8; p++) {
            int idx = tid + p * 256;
            int r = idx >> 4, wc = idx & 15;
            int gi = (m0 + r) * (Cn / 2) + (k0 >> 1) + wc;
            Ah[r * 20 + wc] = xh32[gi];
            Al[r * 20 + wc] = xl32[gi];
        }
#pragma unroll
        for (int p = 0; p < 4; p++) {
            int idx = tid + p * 256;
            int n = idx >> 4, wc = idx & 15;
            int gi = (n0 + n) * (Cn / 2) + (k0 >> 1) + wc;
            Bh[n * 20 + wc] = wh32[gi];
            Bl[n * 20 + wc] = wl32[gi];
        }
        __syncthreads();
#pragma unroll
        for (int ks = 0; ks < 2; ks++) {
            int kw = ks * 8;
            unsigned ah[2][4], al[2][4], bh[4][2], bl[4][2];
#pragma unroll
            for (int mt = 0; mt < 2; mt++) {
                int r = wm * 32 + mt * 16 + g;
                ldfragA(ah[mt], Ah, r, kw, tg);
                ldfragA(al[mt], Al, r, kw, tg);
            }
#pragma unroll
            for (int nt = 0; nt < 4; nt++) {
                int n = wn * 32 + nt * 8 + g;
                ldfragB(bh[nt], Bh, n, kw, tg);
                ldfragB(bl[nt], Bl, n, kw, tg);
            }
#pragma unroll
            for (int mt = 0; mt < 2; mt++)
#pragma unroll
                for (int nt = 0; nt < 4; nt++) {
                    mma_bf16(c[mt][nt], ah[mt], bh[nt]);
                    mma_bf16(c[mt][nt], ah[mt], bl[nt]);
                    mma_bf16(c[mt][nt], al[mt], bh[nt]);
                }
        }
        __syncthreads();
    }
    // epilogue: scatter to g_q / g_k / g_v0 in [b,h,t,d] layout
#pragma unroll
    for (int mt = 0; mt < 2; mt++) {
#pragma unroll
        for (int nt = 0; nt < 4; nt++) {
#pragma unroll
            for (int rr = 0; rr < 2; rr++) {
                int m = m0 + wm * 32 + mt * 16 + g + rr * 8;
                int b = m >> 11, t = m & 2047;
#pragma unroll
                for (int cc = 0; cc < 2; cc++) {
                    int n = n0 + wn * 32 + nt * 8 + 2 * tg + cc;
                    int which = (n >= 2 * Cn) ? 2 : (n >= Cn ? 1 : 0);
                    int col = n - which * Cn;
                    int h = col >> 6, d = col & 63;
                    float* dst = (which == 0) ? g_q : (which == 1) ? g_k : g_v0;
                    dst[((b * NHn + h) * Tn + t) * HSn + d] = c[mt][nt][rr * 2 + cc];
                }
            }
        }
    }
}

// ---------------- vmix (tensor core, bf16x3): 196608x64x4096, A on-the-fly ----------------
__global__ void __launch_bounds__(128) vmix_mma(const float* __restrict__ bv) {
    __shared__ float v0s[64 * 64];
    __shared__ __nv_bfloat16 AhH[64 * 40], AlH[64 * 40];
    __shared__ unsigned Bh[64 * 20], Bl[64 * 20];
    const int tok0 = blockIdx.x * 64;
    const int tid = threadIdx.x, wid = tid >> 5, lane = tid & 31;
    const int wm = wid >> 1, wn = wid & 1;
    const int g = lane >> 2, tg = lane & 3;
    const unsigned* wvh32 = (const unsigned*)g_wvh;
    const unsigned* wvl32 = (const unsigned*)g_wvl;

#pragma unroll
    for (int p = 0; p < 32; p++) {
        int idx = tid + p * 128;
        v0s[idx] = g_v0[tok0 * HSn + idx];
    }
    __syncthreads();

    float c[2][4][4];
#pragma unroll
    for (int i = 0; i < 2; i++)
#pragma unroll
        for (int j = 0; j < 4; j++)
#pragma unroll
            for (int r = 0; r < 4; r++) c[i][j][r] = 0.f;

    const unsigned* Ah32 = (const unsigned*)AhH;
    const unsigned* Al32 = (const unsigned*)AlH;

    for (int ch = 0; ch < 128; ch++) {
        const int i = ch >> 1, jb = (ch & 1) * 32;
#pragma unroll
        for (int p = 0; p < 16; p++) {
            int idx = tid + p * 128;
            int t = idx >> 5, kk = idx & 31;
            float a = g_k[(tok0 + t) * HSn + i] * v0s[t * 64 + jb + kk];
            __nv_bfloat16 hh = __float2bfloat16(a);
            AhH[t * 40 + kk] = hh;
            AlH[t * 40 + kk] = __float2bfloat16(a - __bfloat162float(hh));
        }
#pragma unroll
        for (int p = 0; p < 8; p++) {
            int idx = tid + p * 128;
            int e = idx >> 4, wc = idx & 15;
            int gi = e * (HSn * HSn / 2) + ch * 16 + wc;
            Bh[e * 20 + wc] = wvh32[gi];
            Bl[e * 20 + wc] = wvl32[gi];
        }
        __syncthreads();
#pragma unroll
        for (int ks = 0; ks < 2; ks++) {
            int kw = ks * 8;
            unsigned ah[2][4], al[2][4], bh[4][2], bl[4][2];
#pragma unroll
            for (int mt = 0; mt < 2; mt++) {
                int r = wm * 32 + mt * 16 + g;
                ldfragA(ah[mt], Ah32, r, kw, tg);
                ldfragA(al[mt], Al32, r, kw, tg);
            }
#pragma unroll
            for (int nt = 0; nt < 4; nt++) {
                int n = wn * 32 + nt * 8 + g;
                ldfragB(bh[nt], Bh, n, kw, tg);
                ldfragB(bl[nt], Bl, n, kw, tg);
            }
#pragma unroll
            for (int mt = 0; mt < 2; mt++)
#pragma unroll
                for (int nt = 0; nt < 4; nt++) {
                    mma_bf16(c[mt][nt], ah[mt], bh[nt]);
                    mma_bf16(c[mt][nt], ah[mt], bl[nt]);
                    mma_bf16(c[mt][nt], al[mt], bh[nt]);
                }
        }
        __syncthreads();
    }
#pragma unroll
    for (int mt = 0; mt < 2; mt++)
#pragma unroll
        for (int nt = 0; nt < 4; nt++)
#pragma unroll
            for (int rr = 0; rr < 2; rr++) {
                int t = tok0 + wm * 32 + mt * 16 + g + rr * 8;
#pragma unroll
                for (int cc = 0; cc < 2; cc++) {
                    int e = wn * 32 + nt * 8 + 2 * tg + cc;
                    g_v[t * HSn + e] = c[mt][nt][rr * 2 + cc] + bv[e];
                }
            }
}

// ---------------- local scans: tails + level-0 segment sums ----------------
__global__ void scan_kernel() {
    int blk = blockIdx.x;
    int bh = blk >> 4, tb = blk & 15;
    const float* src = blockIdx.y ? g_v : g_k;
    float* tail = blockIdx.y ? g_vtail : g_ktail;
    float* seg  = blockIdx.y ? g_Vs : g_Ks;
    int d = threadIdx.x & 63, grp = threadIdx.x >> 6;   // 8 groups of 16 tokens
    int t0 = tb * 128 + grp * 16;
    int base = (bh * Tn + t0) * HSn + d;
    float acc = 0.f;
#pragma unroll
    for (int i = 0; i < 16; i++) {
        acc += src[base + i * HSn];
        tail[base + i * HSn] = acc;
    }
    int s0 = t0 >> 4;
    seg[(bh * NSEG + s0) * HSn + d] = acc;
}

// ---------------- level merge: levels 1..7 ----------------
__global__ void merge_kernel() {
    int bh = blockIdx.x;
    float* seg = blockIdx.y ? g_Vs : g_Ks;
    float* base = seg + bh * NSEG * HSn;
    for (int v = 1; v <= 7; v++) {
        int cnt = 128 >> v;
        int cs = 256 - (256 >> v);
        int ps = 256 - (256 >> (v - 1));
        __syncthreads();
        for (int idx = threadIdx.x; idx < cnt * HSn; idx += 256) {
            int i = idx >> 6, d = idx & 63;
            base[(cs + i) * HSn + d] =
                base[(ps + 2 * i) * HSn + d] + base[(ps + 2 * i + 1) * HSn + d];
        }
    }
}

// ---------------- attention: logits + softmax + AV ----------------
__global__ void __launch_bounds__(256) attn_kernel() {
    __shared__ float qst[64][32];
    __shared__ float lg[32][257];
    const int bh = blockIdx.y, t0 = blockIdx.x * 32;
    const int tid = threadIdx.x;
    const float scale = 0.125f;
    const int qbase = (bh * Tn + t0) * HSn;

    for (int p = 0; p < 8; p++) {
        int idx = tid + p * 256;
        int t = idx >> 6, d = idx & 63;
        qst[d][t] = g_q[qbase + idx];
    }
    __syncthreads();

    for (int idx = tid; idx < 32 * NSEG; idx += 256) {
        int tl = idx & 31, s = idx >> 5;
        int tg = t0 + tl;
        int r = g_ridx[s];
        float val = NEG_INF;
        if (t0 + 31 >= r) {
            const float* Kp = g_Ks + (bh * NSEG + s) * HSn;
            float acc = 0.f;
#pragma unroll
            for (int d = 0; d < 64; d += 4) {
                float4 k4 = *(const float4*)(Kp + d);
                acc += qst[d + 0][tl] * k4.x + qst[d + 1][tl] * k4.y
                     + qst[d + 2][tl] * k4.z + qst[d + 3][tl] * k4.w;
            }
            if (tg >= r) val = acc * scale;
        }
        lg[tl][s] = val;
    }

    if (tid < 32) {
        int tl = tid, tg = t0 + tl;
        const float* kt = g_ktail + (bh * Tn + tg) * HSn;
        float acc = 0.f;
#pragma unroll
        for (int d = 0; d < 64; d++) acc += qst[d][tl] * kt[d];
        lg[tl][255] = acc * scale;
    }
    __syncthreads();

    int warp = tid >> 5, lane = tid & 31;
#pragma unroll
    for (int u = 0; u < 4; u++) {
        int t = warp * 4 + u;
        float m = NEG_INF;
        for (int s = lane; s < 256; s += 32) m = fmaxf(m, lg[t][s]);
#pragma unroll
        for (int o = 16; o; o >>= 1) m = fmaxf(m, __shfl_xor_sync(0xffffffffu, m, o));
        float sum = 0.f;
        for (int s = lane; s < 256; s += 32) {
            float p = __expf(lg[t][s] - m);
            lg[t][s] = p;
            sum += p;
        }
#pragma unroll
        for (int o = 16; o; o >>= 1) sum += __shfl_xor_sync(0xffffffffu, sum, o);
        float inv = 1.0f / sum;
        for (int s = lane; s < 256; s += 32) lg[t][s] *= inv;
    }
    __syncthreads();

    const float* Vbase = g_Vs + bh * NSEG * HSn;
    for (int p = 0; p < 8; p++) {
        int idx = tid + p * 256;
        int tl = idx >> 6, d = idx & 63;
        int tg = t0 + tl;
        float acc = 0.f;
#pragma unroll
        for (int v = 0; v < 8; v++) {
            int start = 256 - (256 >> v);
            int cnt = (tg + 1) >> (4 + v);
            for (int ii = 0; ii < cnt; ii++) {
                int s = start + ii;
                acc += lg[tl][s] * Vbase[s * HSn + d];
            }
        }
        float vt = g_vtail[(bh * Tn + tg) * HSn + d];
        acc += lg[tl][255] * vt;
        int b = bh / NHn, h = bh - b * NHn;
        g_y[(b * Tn + tg) * Cn + h * HSn + d] = acc;
    }
}

// ---------------- proj GEMM (tensor core, bf16x3): 16384x768x768 ----------------
__global__ void __launch_bounds__(256) proj_mma(float* __restrict__ out) {
    __shared__ unsigned Ah[128 * 20], Al[128 * 20];
    __shared__ unsigned Bh[64 * 20],  Bl[64 * 20];
    const int m0 = blockIdx.y * 128, n0 = blockIdx.x * 64;
    const int tid = threadIdx.x, wid = tid >> 5, lane = tid & 31;
    const int wm = wid >> 1, wn = wid & 1;
    const int g = lane >> 2, tg = lane & 3;
    const unsigned* wh32 = (const unsigned*)g_wph;
    const unsigned* wl32 = (const unsigned*)g_wpl;
    float c[2][4][4];
#pragma unroll
    for (int i = 0; i < 2; i++)
#pragma unroll
        for (int j = 0; j < 4; j++)
#pragma unroll
            for (int r = 0; r < 4; r++) c[i][j][r] = 0.f;

    for (int k0 = 0; k0 < Cn; k0 += 32) {
#pragma unroll
        for (int p = 0; p < 8; p++) {
            int idx = tid + p * 256;
            int r = idx >> 4, wc = idx & 15;
            float2 a2 = *(const float2*)(g_y + (m0 + r) * Cn + k0 + wc * 2);
            __nv_bfloat16 h0 = __float2bfloat16(a2.x);
            __nv_bfloat16 h1 = __float2bfloat16(a2.y);
            __nv_bfloat16 l0 = __float2bfloat16(a2.x - __bfloat162float(h0));
            __nv_bfloat16 l1 = __float2bfloat16(a2.y - __bfloat162float(h1));
            Ah[r * 20 + wc] = ((unsigned)__bfloat16_as_ushort(h1) << 16) | __bfloat16_as_ushort(h0);
            Al[r * 20 + wc] = ((unsigned)__bfloat16_as_ushort(l1) << 16) | __bfloat16_as_ushort(l0);
        }
#pragma unroll
        for (int p = 0; p < 4; p++) {
            int idx = tid + p * 256;
            int n = idx >> 4, wc = idx & 15;
            int gi = (n0 + n) * (Cn / 2) + (k0 >> 1) + wc;
            Bh[n * 20 + wc] = wh32[gi];
            Bl[n * 20 + wc] = wl32[gi];
        }
        __syncthreads();
#pragma unroll
        for (int ks = 0; ks < 2; ks++) {
            int kw = ks * 8;
            unsigned ah[2][4], al[2][4], bh[4][2], bl[4][2];
#pragma unroll
            for (int mt = 0; mt < 2; mt++) {
                int r = wm * 32 + mt * 16 + g;
                ldfragA(ah[mt], Ah, r, kw, tg);
                ldfragA(al[mt], Al, r, kw, tg);
            }
#pragma unroll
            for (int nt = 0; nt < 4; nt++) {
                int n = wn * 32 + nt * 8 + g;
                ldfragB(bh[nt], Bh, n, kw, tg);
                ldfragB(bl[nt], Bl, n, kw, tg);
            }
#pragma unroll
            for (int mt = 0; mt < 2; mt++)
#pragma unroll
                for (int nt = 0; nt < 4; nt++) {
                    mma_bf16(c[mt][nt], ah[mt], bh[nt]);
                    mma_bf16(c[mt][nt], ah[mt], bl[nt]);
                    mma_bf16(c[mt][nt], al[mt], bh[nt]);
                }
        }
        __syncthreads();
    }
#pragma unroll
    for (int mt = 0; mt < 2; mt++)
#pragma unroll
        for (int nt = 0; nt < 4; nt++)
#pragma unroll
            for (int rr = 0; rr < 2; rr++) {
                int m = m0 + wm * 32 + mt * 16 + g + rr * 8;
#pragma unroll
                for (int cc = 0; cc < 2; cc++) {
                    int n = n0 + wn * 32 + nt * 8 + 2 * tg + cc;
                    out[m * Cn + n] = c[mt][nt][rr * 2 + cc];
                }
            }
}

// ---------------- launch ----------------
extern "C" void kernel_launch(void* const* d_in, const int* in_sizes, int n_in,
                              void* d_out, int out_size) {
    const float* x     = (const float*)d_in[0];
    const float* Wqkv  = (const float*)d_in[1];
    const float* Wproj = (const float*)d_in[2];
    const float* Wv    = (const float*)d_in[3];
    const float* bv    = (const float*)d_in[4];
    float* out = (float*)d_out;

    init_sets_kernel<<<1, 256>>>();
    split_kernel<<<(Bn*Tn*Cn + 255) / 256, 256>>>(x, 0, Bn*Tn*Cn);
    split_kernel<<<(3*Cn*Cn + 255) / 256, 256>>>(Wqkv, 1, 3*Cn*Cn);
    split_kernel<<<(HSn*HSn*HSn + 255) / 256, 256>>>(Wv, 2, HSn*HSn*HSn);
    split_kernel<<<(Cn*Cn + 255) / 256, 256>>>(Wproj, 3, Cn*Cn);
    qkv_mma<<<dim3(36, 128), 256>>>();
    vmix_mma<<<NTOK / 64, 128>>>(bv);
    scan_kernel<<<dim3(BHn * 16, 2), 512>>>();
    merge_kernel<<<dim3(BHn, 2), 256>>>();
    attn_kernel<<<dim3(Tn / 32, BHn), 256>>>();
    proj_mma<<<dim3(Cn / 64, 128), 256>>>(out);
}

// round 3
// speedup vs baseline: 2.2771x; 1.2135x over previous
#include <cuda_runtime.h>
#include <cuda_bf16.h>
#include <cuda_fp16.h>

#define Bn 8
#define Tn 2048
#define Cn 768
#define NHn 12
#define HSn 64
#define BHn (Bn*NHn)        // 96
#define NSEG 255
#define LMIN 16
#define NTOK (BHn*Tn)       // 196608
#define NEG_INF __int_as_float(0xff800000u)

// ---------------- device scratch ----------------
__device__ float g_q    [NTOK*HSn];
__device__ float g_k    [NTOK*HSn];
__device__ float g_v0   [NTOK*HSn];
__device__ float g_v    [NTOK*HSn];
__device__ float g_ktail[NTOK*HSn];
__device__ float g_vtail[NTOK*HSn];
__device__ float g_Ks   [BHn*NSEG*HSn];
__device__ float g_Vs   [BHn*NSEG*HSn];
__device__ __nv_bfloat16 g_yh [Bn*Tn*Cn], g_yl [Bn*Tn*Cn];
__device__ __nv_bfloat16 g_xh [Bn*Tn*Cn], g_xl [Bn*Tn*Cn];
__device__ __nv_bfloat16 g_wqh[3*Cn*Cn],  g_wql[3*Cn*Cn];
__device__ __nv_bfloat16 g_wph[Cn*Cn],    g_wpl[Cn*Cn];
__device__ half g_wvh16[HSn*HSn*HSn], g_wvl16[HSn*HSn*HSn];
__device__ int g_ridx[NSEG];

// ---------------- PTX helpers ----------------
__device__ __forceinline__ unsigned sptr(const void* p) {
    return (unsigned)__cvta_generic_to_shared(p);
}
#define CP16(dst, src) asm volatile("cp.async.ca.shared.global [%0], [%1], 16;\n" :: "r"(dst), "l"(src))
#define CPCOMMIT()     asm volatile("cp.async.commit_group;\n")
#define CPWAIT0()      asm volatile("cp.async.wait_group 0;\n")

__device__ __forceinline__ void ldsm4(unsigned* r, unsigned addr) {
    asm volatile("ldmatrix.sync.aligned.m8n8.x4.shared.b16 {%0,%1,%2,%3}, [%4];\n"
                 : "=r"(r[0]), "=r"(r[1]), "=r"(r[2]), "=r"(r[3]) : "r"(addr));
}
__device__ __forceinline__ void mma_bf16(float* c, const unsigned* a, const unsigned* b) {
    asm volatile(
        "mma.sync.aligned.m16n8k16.row.col.f32.bf16.bf16.f32 "
        "{%0,%1,%2,%3}, {%4,%5,%6,%7}, {%8,%9}, {%0,%1,%2,%3};\n"
        : "+f"(c[0]), "+f"(c[1]), "+f"(c[2]), "+f"(c[3])
        : "r"(a[0]), "r"(a[1]), "r"(a[2]), "r"(a[3]), "r"(b[0]), "r"(b[1]));
}
__device__ __forceinline__ void mma_f16(float* c, const unsigned* a, const unsigned* b) {
    asm volatile(
        "mma.sync.aligned.m16n8k16.row.col.f32.f16.f16.f32 "
        "{%0,%1,%2,%3}, {%4,%5,%6,%7}, {%8,%9}, {%0,%1,%2,%3};\n"
        : "+f"(c[0]), "+f"(c[1]), "+f"(c[2]), "+f"(c[3])
        : "r"(a[0]), "r"(a[1]), "r"(a[2]), "r"(a[3]), "r"(b[0]), "r"(b[1]));
}

// ---------------- init segment r-index ----------------
__global__ void init_sets_kernel() {
    int s = threadIdx.x;
    if (s < NSEG) {
        int v = 0, rem = s;
        while (rem >= (128 >> v)) { rem -= (128 >> v); v++; }
        int L = LMIN << v;
        g_ridx[s] = (rem + 1) * L - 1;
    }
}

// ---------------- split fp32 -> hi/lo (bf16 for x/Wq/Wp, fp16 for Wv) ----------------
__global__ void split_kernel(const float* __restrict__ src, int which, int n) {
    int i = blockIdx.x * 256 + threadIdx.x;
    if (i >= n) return;
    float x = src[i];
    if (which == 2) {
        half hh = __float2half_rn(x);
        g_wvh16[i] = hh;
        g_wvl16[i] = __float2half_rn(x - __half2float(hh));
        return;
    }
    __nv_bfloat16 *h, *l;
    switch (which) {
        case 0: h = g_xh;  l = g_xl;  break;
        case 1: h = g_wqh; l = g_wql; break;
        default:h = g_wph; l = g_wpl; break;
    }
    __nv_bfloat16 hh = __float2bfloat16(x);
    h[i] = hh;
    l[i] = __float2bfloat16(x - __bfloat162float(hh));
}

// ================= qkv GEMM: 16384 x 2304 x 768, bf16x3, ldmatrix + cp.async =================
// dyn smem words: Ah[2][2560] @0, Al[2][2560] @5120, Bh[2][1280] @10240, Bl[2][1280] @12800
#define QKV_SMEM_BYTES (15360*4)
__global__ void __launch_bounds__(256) qkv_mma() {
    extern __shared__ unsigned sm[];
    const unsigned s_base = sptr(sm);
    const int m0 = blockIdx.y * 128, n0 = blockIdx.x * 64;
    const int tid = threadIdx.x, wid = tid >> 5, lane = tid & 31;
    const int wm = wid >> 1, wn = wid & 1;
    const int g = lane >> 2, tg = lane & 3;
    const int laneA = (lane & 15) * 20 + (lane >> 4) * 4;
    const int laneB = ((lane & 7) + ((lane >> 4) << 3)) * 20 + ((lane >> 3) & 1) * 4;
    const unsigned* xh32 = (const unsigned*)g_xh;
    const unsigned* xl32 = (const unsigned*)g_xl;
    const unsigned* wh32 = (const unsigned*)g_wqh;
    const unsigned* wl32 = (const unsigned*)g_wql;

    auto prefetch = [&](int kc, int buf) {
        const int k0w = kc * 16;
#pragma unroll
        for (int p = 0; p < 2; p++) {
            int idx = tid + p * 256;
            int row = idx >> 2, c4 = idx & 3;
            unsigned d = (row * 20 + c4 * 4) * 4;
            CP16(s_base + buf * 2560 * 4 + d,            xh32 + (m0 + row) * 384 + k0w + c4 * 4);
            CP16(s_base + (5120 + buf * 2560) * 4 + d,   xl32 + (m0 + row) * 384 + k0w + c4 * 4);
        }
        {
            int row = tid >> 2, c4 = tid & 3;
            unsigned d = (row * 20 + c4 * 4) * 4;
            CP16(s_base + (10240 + buf * 1280) * 4 + d,  wh32 + (n0 + row) * 384 + k0w + c4 * 4);
            CP16(s_base + (12800 + buf * 1280) * 4 + d,  wl32 + (n0 + row) * 384 + k0w + c4 * 4);
        }
    };

    float c[2][4][4];
#pragma unroll
    for (int i = 0; i < 2; i++)
#pragma unroll
        for (int j = 0; j < 4; j++)
#pragma unroll
            for (int r = 0; r < 4; r++) c[i][j][r] = 0.f;

    prefetch(0, 0);
    CPCOMMIT();
    for (int kc = 0; kc < 24; kc++) {
        const int buf = kc & 1;
        CPWAIT0();
        __syncthreads();
        if (kc < 23) { prefetch(kc + 1, buf ^ 1); CPCOMMIT(); }
        const unsigned ahb = s_base + (buf * 2560) * 4;
        const unsigned alb = s_base + (5120 + buf * 2560) * 4;
        const unsigned bhb = s_base + (10240 + buf * 1280) * 4;
        const unsigned blb = s_base + (12800 + buf * 1280) * 4;
#pragma unroll
        for (int ks = 0; ks < 2; ks++) {
            const int kw = ks * 8;
            unsigned ah[2][4], al[2][4], bh[4][2], bl[4][2];
#pragma unroll
            for (int mt = 0; mt < 2; mt++) {
                unsigned off = ((wm * 32 + mt * 16) * 20 + kw + laneA) * 4;
                ldsm4(ah[mt], ahb + off);
                ldsm4(al[mt], alb + off);
            }
#pragma unroll
            for (int ntp = 0; ntp < 2; ntp++) {
                unsigned off = ((wn * 32 + ntp * 16) * 20 + kw + laneB) * 4;
                unsigned r[4];
                ldsm4(r, bhb + off);
                bh[2*ntp][0] = r[0]; bh[2*ntp][1] = r[1]; bh[2*ntp+1][0] = r[2]; bh[2*ntp+1][1] = r[3];
                ldsm4(r, blb + off);
                bl[2*ntp][0] = r[0]; bl[2*ntp][1] = r[1]; bl[2*ntp+1][0] = r[2]; bl[2*ntp+1][1] = r[3];
            }
#pragma unroll
            for (int mt = 0; mt < 2; mt++)
#pragma unroll
                for (int nt = 0; nt < 4; nt++) {
                    mma_bf16(c[mt][nt], ah[mt], bh[nt]);
                    mma_bf16(c[mt][nt], ah[mt], bl[nt]);
                    mma_bf16(c[mt][nt], al[mt], bh[nt]);
                }
        }
    }
    // epilogue: scatter to g_q / g_k / g_v0 in [b,h,t,d] layout
#pragma unroll
    for (int mt = 0; mt < 2; mt++)
#pragma unroll
        for (int nt = 0; nt < 4; nt++)
#pragma unroll
            for (int rr = 0; rr < 2; rr++) {
                int m = m0 + wm * 32 + mt * 16 + g + rr * 8;
                int b = m >> 11, t = m & 2047;
#pragma unroll
                for (int cc = 0; cc < 2; cc++) {
                    int n = n0 + wn * 32 + nt * 8 + 2 * tg + cc;
                    int which = (n >= 2 * Cn) ? 2 : (n >= Cn ? 1 : 0);
                    int col = n - which * Cn;
                    int h = col >> 6, d = col & 63;
                    float* dst = (which == 0) ? g_q : (which == 1) ? g_k : g_v0;
                    dst[((b * NHn + h) * Tn + t) * HSn + d] = c[mt][nt][rr * 2 + cc];
                }
            }
}

// ================= vmix: 196608 x 64 x 4096, fp16x2 (A single, Wv hi/lo) =================
// dyn smem words: v0s float @0 (4096), kts @4096 (4096), As half [2][1280w] @8192,
//                 Bh [2][1280] @10752, Bl [2][1280] @13312  -> 15872 words
#define VMIX_SMEM_BYTES (15872*4)
__global__ void __launch_bounds__(256) vmix_mma(const float* __restrict__ bv) {
    extern __shared__ unsigned sm[];
    float* smf = (float*)sm;
    const unsigned s_base = sptr(sm);
    const int tok0 = blockIdx.x * 64;
    const int tid = threadIdx.x, wid = tid >> 5, lane = tid & 31;
    const int wm = wid >> 1, wn = wid & 1;
    const int g = lane >> 2, tg = lane & 3;
    const int laneA = (lane & 15) * 20 + (lane >> 4) * 4;
    const int laneB = ((lane & 7) + ((lane >> 4) << 3)) * 20 + ((lane >> 3) & 1) * 4;
    const unsigned* wvh32 = (const unsigned*)g_wvh16;
    const unsigned* wvl32 = (const unsigned*)g_wvl16;

    // load v0 and k tiles (64 tokens x 64 dims each)
#pragma unroll
    for (int p = 0; p < 4; p++) {
        int idx = (tid + p * 256) * 4;
        *(float4*)&smf[idx]        = *(const float4*)(g_v0 + tok0 * HSn + idx);
        *(float4*)&smf[4096 + idx] = *(const float4*)(g_k  + tok0 * HSn + idx);
    }

    auto prefetchB = [&](int ch, int buf) {
        int row = tid >> 2, c4 = tid & 3;
        unsigned d = (row * 20 + c4 * 4) * 4;
        const int src = row * 2048 + ch * 16 + c4 * 4;
        CP16(s_base + (10752 + buf * 1280) * 4 + d, wvh32 + src);
        CP16(s_base + (13312 + buf * 1280) * 4 + d, wvl32 + src);
    };

    prefetchB(0, 0);
    CPCOMMIT();
    __syncthreads();   // v0s/kts ready

    float c[4][4];
#pragma unroll
    for (int j = 0; j < 4; j++)
#pragma unroll
        for (int r = 0; r < 4; r++) c[j][r] = 0.f;

    const int tA = tid >> 2, cb = (tid & 3) * 8;  // A-gen: token, j-offset (8 cols)
    for (int ch = 0; ch < 128; ch++) {
        const int buf = ch & 1;
        const int i = ch >> 1, jb = (ch & 1) * 32;
        // generate A tile (64 tokens x 32 k) fp16 into As[buf]
        {
            float kk = smf[4096 + tA * 64 + i];
            float4 u0 = *(const float4*)&smf[tA * 64 + jb + cb];
            float4 u1 = *(const float4*)&smf[tA * 64 + jb + cb + 4];
            __half2 p0 = __floats2half2_rn(kk * u0.x, kk * u0.y);
            __half2 p1 = __floats2half2_rn(kk * u0.z, kk * u0.w);
            __half2 p2 = __floats2half2_rn(kk * u1.x, kk * u1.y);
            __half2 p3 = __floats2half2_rn(kk * u1.z, kk * u1.w);
            uint4 w;
            w.x = *(unsigned*)&p0; w.y = *(unsigned*)&p1;
            w.z = *(unsigned*)&p2; w.w = *(unsigned*)&p3;
            *(uint4*)&sm[8192 + buf * 1280 + tA * 20 + (cb >> 1)] = w;
        }
        CPWAIT0();
        __syncthreads();
        if (ch < 127) { prefetchB(ch + 1, buf ^ 1); CPCOMMIT(); }
        const unsigned asb = s_base + (8192 + buf * 1280) * 4;
        const unsigned bhb = s_base + (10752 + buf * 1280) * 4;
        const unsigned blb = s_base + (13312 + buf * 1280) * 4;
#pragma unroll
        for (int ks = 0; ks < 2; ks++) {
            const int kw = ks * 8;
            unsigned a[4], bh[4][2], bl[4][2];
            ldsm4(a, asb + ((wm * 16) * 20 + kw + laneA) * 4);
#pragma unroll
            for (int ntp = 0; ntp < 2; ntp++) {
                unsigned off = ((wn * 32 + ntp * 16) * 20 + kw + laneB) * 4;
                unsigned r[4];
                ldsm4(r, bhb + off);
                bh[2*ntp][0] = r[0]; bh[2*ntp][1] = r[1]; bh[2*ntp+1][0] = r[2]; bh[2*ntp+1][1] = r[3];
                ldsm4(r, blb + off);
                bl[2*ntp][0] = r[0]; bl[2*ntp][1] = r[1]; bl[2*ntp+1][0] = r[2]; bl[2*ntp+1][1] = r[3];
            }
#pragma unroll
            for (int nt = 0; nt < 4; nt++) {
                mma_f16(c[nt], a, bh[nt]);
                mma_f16(c[nt], a, bl[nt]);
            }
        }
    }
#pragma unroll
    for (int nt = 0; nt < 4; nt++)
#pragma unroll
        for (int rr = 0; rr < 2; rr++) {
            int t = tok0 + wm * 16 + g + rr * 8;
#pragma unroll
            for (int cc = 0; cc < 2; cc++) {
                int e = wn * 32 + nt * 8 + 2 * tg + cc;
                g_v[t * HSn + e] = c[nt][rr * 2 + cc] + bv[e];
            }
        }
}

// ---------------- local scans: tails + level-0 segment sums ----------------
__global__ void scan_kernel() {
    int blk = blockIdx.x;
    int bh = blk >> 4, tb = blk & 15;
    const float* src = blockIdx.y ? g_v : g_k;
    float* tail = blockIdx.y ? g_vtail : g_ktail;
    float* seg  = blockIdx.y ? g_Vs : g_Ks;
    int d = threadIdx.x & 63, grp = threadIdx.x >> 6;
    int t0 = tb * 128 + grp * 16;
    int base = (bh * Tn + t0) * HSn + d;
    float acc = 0.f;
#pragma unroll
    for (int i = 0; i < 16; i++) {
        acc += src[base + i * HSn];
        tail[base + i * HSn] = acc;
    }
    int s0 = t0 >> 4;
    seg[(bh * NSEG + s0) * HSn + d] = acc;
}

// ---------------- level merge: levels 1..7 ----------------
__global__ void merge_kernel() {
    int bh = blockIdx.x;
    float* seg = blockIdx.y ? g_Vs : g_Ks;
    float* base = seg + bh * NSEG * HSn;
    for (int v = 1; v <= 7; v++) {
        int cnt = 128 >> v;
        int cs = 256 - (256 >> v);
        int ps = 256 - (256 >> (v - 1));
        __syncthreads();
        for (int idx = threadIdx.x; idx < cnt * HSn; idx += 256) {
            int i = idx >> 6, d = idx & 63;
            base[(cs + i) * HSn + d] =
                base[(ps + 2 * i) * HSn + d] + base[(ps + 2 * i + 1) * HSn + d];
        }
    }
}

// ---------------- attention: logits + softmax + AV (fp32) ----------------
__global__ void __launch_bounds__(256) attn_kernel() {
    __shared__ float qst[64][32];
    __shared__ float lg[32][257];
    const int bh = blockIdx.y, t0 = blockIdx.x * 32;
    const int tid = threadIdx.x;
    const float scale = 0.125f;
    const int qbase = (bh * Tn + t0) * HSn;

    for (int p = 0; p < 8; p++) {
        int idx = tid + p * 256;
        int t = idx >> 6, d = idx & 63;
        qst[d][t] = g_q[qbase + idx];
    }
    __syncthreads();

    for (int idx = tid; idx < 32 * NSEG; idx += 256) {
        int tl = idx & 31, s = idx >> 5;
        int tg2 = t0 + tl;
        int r = g_ridx[s];
        float val = NEG_INF;
        if (t0 + 31 >= r) {
            const float* Kp = g_Ks + (bh * NSEG + s) * HSn;
            float acc = 0.f;
#pragma unroll
            for (int d = 0; d < 64; d += 4) {
                float4 k4 = *(const float4*)(Kp + d);
                acc += qst[d + 0][tl] * k4.x + qst[d + 1][tl] * k4.y
                     + qst[d + 2][tl] * k4.z + qst[d + 3][tl] * k4.w;
            }
            if (tg2 >= r) val = acc * scale;
        }
        lg[tl][s] = val;
    }

    if (tid < 32) {
        int tl = tid, tg2 = t0 + tl;
        const float* kt = g_ktail + (bh * Tn + tg2) * HSn;
        float acc = 0.f;
#pragma unroll
        for (int d = 0; d < 64; d++) acc += qst[d][tl] * kt[d];
        lg[tl][255] = acc * scale;
    }
    __syncthreads();

    int warp = tid >> 5, lane = tid & 31;
#pragma unroll
    for (int u = 0; u < 4; u++) {
        int t = warp * 4 + u;
        float m = NEG_INF;
        for (int s = lane; s < 256; s += 32) m = fmaxf(m, lg[t][s]);
#pragma unroll
        for (int o = 16; o; o >>= 1) m = fmaxf(m, __shfl_xor_sync(0xffffffffu, m, o));
        float sum = 0.f;
        for (int s = lane; s < 256; s += 32) {
            float p = __expf(lg[t][s] - m);
            lg[t][s] = p;
            sum += p;
        }
#pragma unroll
        for (int o = 16; o; o >>= 1) sum += __shfl_xor_sync(0xffffffffu, sum, o);
        float inv = 1.0f / sum;
        for (int s = lane; s < 256; s += 32) lg[t][s] *= inv;
    }
    __syncthreads();

    const float* Vbase = g_Vs + bh * NSEG * HSn;
    for (int p = 0; p < 8; p++) {
        int idx = tid + p * 256;
        int tl = idx >> 6, d = idx & 63;
        int tg2 = t0 + tl;
        float acc = 0.f;
#pragma unroll
        for (int v = 0; v < 8; v++) {
            int start = 256 - (256 >> v);
            int cnt = (tg2 + 1) >> (4 + v);
            for (int ii = 0; ii < cnt; ii++) {
                int s = start + ii;
                acc += lg[tl][s] * Vbase[s * HSn + d];
            }
        }
        float vt = g_vtail[(bh * Tn + tg2) * HSn + d];
        acc += lg[tl][255] * vt;
        int b = bh / NHn, h = bh - b * NHn;
        int off = (b * Tn + tg2) * Cn + h * HSn + d;
        __nv_bfloat16 hh = __float2bfloat16(acc);
        g_yh[off] = hh;
        g_yl[off] = __float2bfloat16(acc - __bfloat162float(hh));
    }
}

// ================= proj GEMM: 16384 x 768 x 768, bf16x3, ldmatrix + cp.async =================
__global__ void __launch_bounds__(256) proj_mma(float* __restrict__ out) {
    extern __shared__ unsigned sm[];
    const unsigned s_base = sptr(sm);
    const int m0 = blockIdx.y * 128, n0 = blockIdx.x * 64;
    const int tid = threadIdx.x, wid = tid >> 5, lane = tid & 31;
    const int wm = wid >> 1, wn = wid & 1;
    const int g = lane >> 2, tg = lane & 3;
    const int laneA = (lane & 15) * 20 + (lane >> 4) * 4;
    const int laneB = ((lane & 7) + ((lane >> 4) << 3)) * 20 + ((lane >> 3) & 1) * 4;
    const unsigned* yh32 = (const unsigned*)g_yh;
    const unsigned* yl32 = (const unsigned*)g_yl;
    const unsigned* wh32 = (const unsigned*)g_wph;
    const unsigned* wl32 = (const unsigned*)g_wpl;

    auto prefetch = [&](int kc, int buf) {
        const int k0w = kc * 16;
#pragma unroll
        for (int p = 0; p < 2; p++) {
            int idx = tid + p * 256;
            int row = idx >> 2, c4 = idx & 3;
            unsigned d = (row * 20 + c4 * 4) * 4;
            CP16(s_base + buf * 2560 * 4 + d,           yh32 + (m0 + row) * 384 + k0w + c4 * 4);
            CP16(s_base + (5120 + buf * 2560) * 4 + d,  yl32 + (m0 + row) * 384 + k0w + c4 * 4);
        }
        {
            int row = tid >> 2, c4 = tid & 3;
            unsigned d = (row * 20 + c4 * 4) * 4;
            CP16(s_base + (10240 + buf * 1280) * 4 + d, wh32 + (n0 + row) * 384 + k0w + c4 * 4);
            CP16(s_base + (12800 + buf * 1280) * 4 + d, wl32 + (n0 + row) * 384 + k0w + c4 * 4);
        }
    };

    float c[2][4][4];
#pragma unroll
    for (int i = 0; i < 2; i++)
#pragma unroll
        for (int j = 0; j < 4; j++)
#pragma unroll
            for (int r = 0; r < 4; r++) c[i][j][r] = 0.f;

    prefetch(0, 0);
    CPCOMMIT();
    for (int kc = 0; kc < 24; kc++) {
        const int buf = kc & 1;
        CPWAIT0();
        __syncthreads();
        if (kc < 23) { prefetch(kc + 1, buf ^ 1); CPCOMMIT(); }
        const unsigned ahb = s_base + (buf * 2560) * 4;
        const unsigned alb = s_base + (5120 + buf * 2560) * 4;
        const unsigned bhb = s_base + (10240 + buf * 1280) * 4;
        const unsigned blb = s_base + (12800 + buf * 1280) * 4;
#pragma unroll
        for (int ks = 0; ks < 2; ks++) {
            const int kw = ks * 8;
            unsigned ah[2][4], al[2][4], bh[4][2], bl[4][2];
#pragma unroll
            for (int mt = 0; mt < 2; mt++) {
                unsigned off = ((wm * 32 + mt * 16) * 20 + kw + laneA) * 4;
                ldsm4(ah[mt], ahb + off);
                ldsm4(al[mt], alb + off);
            }
#pragma unroll
            for (int ntp = 0; ntp < 2; ntp++) {
                unsigned off = ((wn * 32 + ntp * 16) * 20 + kw + laneB) * 4;
                unsigned r[4];
                ldsm4(r, bhb + off);
                bh[2*ntp][0] = r[0]; bh[2*ntp][1] = r[1]; bh[2*ntp+1][0] = r[2]; bh[2*ntp+1][1] = r[3];
                ldsm4(r, blb + off);
                bl[2*ntp][0] = r[0]; bl[2*ntp][1] = r[1]; bl[2*ntp+1][0] = r[2]; bl[2*ntp+1][1] = r[3];
            }
#pragma unroll
            for (int mt = 0; mt < 2; mt++)
#pragma unroll
                for (int nt = 0; nt < 4; nt++) {
                    mma_bf16(c[mt][nt], ah[mt], bh[nt]);
                    mma_bf16(c[mt][nt], ah[mt], bl[nt]);
                    mma_bf16(c[mt][nt], al[mt], bh[nt]);
                }
        }
    }
#pragma unroll
    for (int mt = 0; mt < 2; mt++)
#pragma unroll
        for (int nt = 0; nt < 4; nt++)
#pragma unroll
            for (int rr = 0; rr < 2; rr++) {
                int m = m0 + wm * 32 + mt * 16 + g + rr * 8;
#pragma unroll
                for (int cc = 0; cc < 2; cc++) {
                    int n = n0 + wn * 32 + nt * 8 + 2 * tg + cc;
                    out[m * Cn + n] = c[mt][nt][rr * 2 + cc];
                }
            }
}

// ---------------- launch ----------------
extern "C" void kernel_launch(void* const* d_in, const int* in_sizes, int n_in,
                              void* d_out, int out_size) {
    const float* x     = (const float*)d_in[0];
    const float* Wqkv  = (const float*)d_in[1];
    const float* Wproj = (const float*)d_in[2];
    const float* Wv    = (const float*)d_in[3];
    const float* bv    = (const float*)d_in[4];
    float* out = (float*)d_out;

    cudaFuncSetAttribute(qkv_mma,  cudaFuncAttributeMaxDynamicSharedMemorySize, QKV_SMEM_BYTES);
    cudaFuncSetAttribute(vmix_mma, cudaFuncAttributeMaxDynamicSharedMemorySize, VMIX_SMEM_BYTES);
    cudaFuncSetAttribute(proj_mma, cudaFuncAttributeMaxDynamicSharedMemorySize, QKV_SMEM_BYTES);

    init_sets_kernel<<<1, 256>>>();
    split_kernel<<<(Bn*Tn*Cn + 255) / 256, 256>>>(x, 0, Bn*Tn*Cn);
    split_kernel<<<(3*Cn*Cn + 255) / 256, 256>>>(Wqkv, 1, 3*Cn*Cn);
    split_kernel<<<(HSn*HSn*HSn + 255) / 256, 256>>>(Wv, 2, HSn*HSn*HSn);
    split_kernel<<<(Cn*Cn + 255) / 256, 256>>>(Wproj, 3, Cn*Cn);
    qkv_mma<<<dim3(36, 128), 256, QKV_SMEM_BYTES>>>();
    vmix_mma<<<NTOK / 64, 256, VMIX_SMEM_BYTES>>>(bv);
    scan_kernel<<<dim3(BHn * 16, 2), 512>>>();
    merge_kernel<<<dim3(BHn, 2), 256>>>();
    attn_kernel<<<dim3(Tn / 32, BHn), 256>>>();
    proj_mma<<<dim3(Cn / 64, 128), 256, QKV_SMEM_BYTES>>>(out);
}

// round 5
// speedup vs baseline: 2.6130x; 1.1475x over previous
#include <cuda_runtime.h>
#include <cuda_bf16.h>
#include <cuda_fp16.h>

#define Bn 8
#define Tn 2048
#define Cn 768
#define NHn 12
#define HSn 64
#define BHn (Bn*NHn)        // 96
#define NSEG 255
#define LMIN 16
#define NTOK (BHn*Tn)       // 196608
#define NEG_INF __int_as_float(0xff800000u)

// ---------------- device scratch ----------------
__device__ float g_q    [NTOK*HSn];
__device__ float g_k    [NTOK*HSn];
__device__ float g_v0   [NTOK*HSn];
__device__ float g_v    [NTOK*HSn];
__device__ float g_ktail[NTOK*HSn];
__device__ float g_vtail[NTOK*HSn];
__device__ float g_Ks   [BHn*NSEG*HSn];
__device__ float g_Vs   [BHn*NSEG*HSn];
__device__ __nv_bfloat16 g_yh [Bn*Tn*Cn], g_yl [Bn*Tn*Cn];
__device__ __nv_bfloat16 g_xh [Bn*Tn*Cn], g_xl [Bn*Tn*Cn];
__device__ half          g_x16[Bn*Tn*Cn];
__device__ __nv_bfloat16 g_wqh[3*Cn*Cn],  g_wql[3*Cn*Cn];
__device__ half          g_wq16[3*Cn*Cn];
__device__ __nv_bfloat16 g_wph[Cn*Cn],    g_wpl[Cn*Cn];
__device__ half g_wv16[HSn*HSn*HSn];
__device__ int g_ridx[NSEG];

// ---------------- PTX helpers ----------------
__device__ __forceinline__ unsigned sptr(const void* p) {
    return (unsigned)__cvta_generic_to_shared(p);
}
#define CP16(dst, src) asm volatile("cp.async.ca.shared.global [%0], [%1], 16;\n" :: "r"(dst), "l"(src))
#define CPCOMMIT()     asm volatile("cp.async.commit_group;\n")
#define CPWAIT0()      asm volatile("cp.async.wait_group 0;\n")

__device__ __forceinline__ void ldsm4(unsigned* r, unsigned addr) {
    asm volatile("ldmatrix.sync.aligned.m8n8.x4.shared.b16 {%0,%1,%2,%3}, [%4];\n"
                 : "=r"(r[0]), "=r"(r[1]), "=r"(r[2]), "=r"(r[3]) : "r"(addr));
}
__device__ __forceinline__ void mma_bf16(float* c, const unsigned* a, const unsigned* b) {
    asm volatile(
        "mma.sync.aligned.m16n8k16.row.col.f32.bf16.bf16.f32 "
        "{%0,%1,%2,%3}, {%4,%5,%6,%7}, {%8,%9}, {%0,%1,%2,%3};\n"
        : "+f"(c[0]), "+f"(c[1]), "+f"(c[2]), "+f"(c[3])
        : "r"(a[0]), "r"(a[1]), "r"(a[2]), "r"(a[3]), "r"(b[0]), "r"(b[1]));
}
__device__ __forceinline__ void mma_f16(float* c, const unsigned* a, const unsigned* b) {
    asm volatile(
        "mma.sync.aligned.m16n8k16.row.col.f32.f16.f16.f32 "
        "{%0,%1,%2,%3}, {%4,%5,%6,%7}, {%8,%9}, {%0,%1,%2,%3};\n"
        : "+f"(c[0]), "+f"(c[1]), "+f"(c[2]), "+f"(c[3])
        : "r"(a[0]), "r"(a[1]), "r"(a[2]), "r"(a[3]), "r"(b[0]), "r"(b[1]));
}

// ---------------- init segment r-index ----------------
__global__ void init_sets_kernel() {
    int s = threadIdx.x;
    if (s < NSEG) {
        int v = 0, rem = s;
        while (rem >= (128 >> v)) { rem -= (128 >> v); v++; }
        int L = LMIN << v;
        g_ridx[s] = (rem + 1) * L - 1;
    }
}

// ---------------- split fp32 -> hi/lo bf16 + fp16 variants ----------------
__global__ void split_kernel(const float* __restrict__ src, int which, int n) {
    int i = blockIdx.x * 256 + threadIdx.x;
    if (i >= n) return;
    float x = src[i];
    if (which == 2) { g_wv16[i] = __float2half_rn(x); return; }
    __nv_bfloat16 *h, *l;
    switch (which) {
        case 0: h = g_xh;  l = g_xl;  g_x16[i]  = __float2half_rn(x); break;
        case 1: h = g_wqh; l = g_wql; g_wq16[i] = __float2half_rn(x); break;
        default:h = g_wph; l = g_wpl; break;
    }
    __nv_bfloat16 hh = __float2bfloat16(x);
    h[i] = hh;
    l[i] = __float2bfloat16(x - __bfloat162float(hh));
}

// ================= qk GEMM: 16384 x 1536 x 768, bf16x3 =================
// dyn smem words: Ah[2][2560] @0, Al[2][2560] @5120, Bh[2][1280] @10240, Bl[2][1280] @12800
#define QKV_SMEM_BYTES (15360*4)
__global__ void __launch_bounds__(256) qk_mma() {
    extern __shared__ unsigned sm[];
    const unsigned s_base = sptr(sm);
    const int m0 = blockIdx.y * 128, n0 = blockIdx.x * 64;
    const int tid = threadIdx.x, wid = tid >> 5, lane = tid & 31;
    const int wm = wid >> 1, wn = wid & 1;
    const int g = lane >> 2, tg = lane & 3;
    const int laneA = (lane & 15) * 20 + (lane >> 4) * 4;
    const int laneB = ((lane & 7) + ((lane >> 4) << 3)) * 20 + ((lane >> 3) & 1) * 4;
    const unsigned* xh32 = (const unsigned*)g_xh;
    const unsigned* xl32 = (const unsigned*)g_xl;
    const unsigned* wh32 = (const unsigned*)g_wqh;
    const unsigned* wl32 = (const unsigned*)g_wql;

    auto prefetch = [&](int kc, int buf) {
        const int k0w = kc * 16;
#pragma unroll
        for (int p = 0; p < 2; p++) {
            int idx = tid + p * 256;
            int row = idx >> 2, c4 = idx & 3;
            unsigned d = (row * 20 + c4 * 4) * 4;
            CP16(s_base + buf * 2560 * 4 + d,            xh32 + (m0 + row) * 384 + k0w + c4 * 4);
            CP16(s_base + (5120 + buf * 2560) * 4 + d,   xl32 + (m0 + row) * 384 + k0w + c4 * 4);
        }
        {
            int row = tid >> 2, c4 = tid & 3;
            unsigned d = (row * 20 + c4 * 4) * 4;
            CP16(s_base + (10240 + buf * 1280) * 4 + d,  wh32 + (n0 + row) * 384 + k0w + c4 * 4);
            CP16(s_base + (12800 + buf * 1280) * 4 + d,  wl32 + (n0 + row) * 384 + k0w + c4 * 4);
        }
    };

    float c[2][4][4];
#pragma unroll
    for (int i = 0; i < 2; i++)
#pragma unroll
        for (int j = 0; j < 4; j++)
#pragma unroll
            for (int r = 0; r < 4; r++) c[i][j][r] = 0.f;

    prefetch(0, 0);
    CPCOMMIT();
    for (int kc = 0; kc < 24; kc++) {
        const int buf = kc & 1;
        CPWAIT0();
        __syncthreads();
        if (kc < 23) { prefetch(kc + 1, buf ^ 1); CPCOMMIT(); }
        const unsigned ahb = s_base + (buf * 2560) * 4;
        const unsigned alb = s_base + (5120 + buf * 2560) * 4;
        const unsigned bhb = s_base + (10240 + buf * 1280) * 4;
        const unsigned blb = s_base + (12800 + buf * 1280) * 4;
#pragma unroll
        for (int ks = 0; ks < 2; ks++) {
            const int kw = ks * 8;
            unsigned ah[2][4], al[2][4], bh[4][2], bl[4][2];
#pragma unroll
            for (int mt = 0; mt < 2; mt++) {
                unsigned off = ((wm * 32 + mt * 16) * 20 + kw + laneA) * 4;
                ldsm4(ah[mt], ahb + off);
                ldsm4(al[mt], alb + off);
            }
#pragma unroll
            for (int ntp = 0; ntp < 2; ntp++) {
                unsigned off = ((wn * 32 + ntp * 16) * 20 + kw + laneB) * 4;
                unsigned r[4];
                ldsm4(r, bhb + off);
                bh[2*ntp][0] = r[0]; bh[2*ntp][1] = r[1]; bh[2*ntp+1][0] = r[2]; bh[2*ntp+1][1] = r[3];
                ldsm4(r, blb + off);
                bl[2*ntp][0] = r[0]; bl[2*ntp][1] = r[1]; bl[2*ntp+1][0] = r[2]; bl[2*ntp+1][1] = r[3];
            }
#pragma unroll
            for (int mt = 0; mt < 2; mt++)
#pragma unroll
                for (int nt = 0; nt < 4; nt++) {
                    mma_bf16(c[mt][nt], ah[mt], bh[nt]);
                    mma_bf16(c[mt][nt], ah[mt], bl[nt]);
                    mma_bf16(c[mt][nt], al[mt], bh[nt]);
                }
        }
    }
#pragma unroll
    for (int mt = 0; mt < 2; mt++)
#pragma unroll
        for (int nt = 0; nt < 4; nt++)
#pragma unroll
            for (int rr = 0; rr < 2; rr++) {
                int m = m0 + wm * 32 + mt * 16 + g + rr * 8;
                int b = m >> 11, t = m & 2047;
#pragma unroll
                for (int cc = 0; cc < 2; cc++) {
                    int n = n0 + wn * 32 + nt * 8 + 2 * tg + cc;
                    int which = (n >= Cn) ? 1 : 0;
                    int col = n - which * Cn;
                    int h = col >> 6, d = col & 63;
                    float* dst = which ? g_k : g_q;
                    dst[((b * NHn + h) * Tn + t) * HSn + d] = c[mt][nt][rr * 2 + cc];
                }
            }
}

// ================= v0 GEMM: 16384 x 768 x 768, single fp16 =================
// dyn smem words: A[2][2560] @0, B[2][1280] @5120  -> 7680 words
#define V0_SMEM_BYTES (7680*4)
__global__ void __launch_bounds__(256) v0_mma() {
    extern __shared__ unsigned sm[];
    const unsigned s_base = sptr(sm);
    const int m0 = blockIdx.y * 128, n0 = blockIdx.x * 64;
    const int tid = threadIdx.x, wid = tid >> 5, lane = tid & 31;
    const int wm = wid >> 1, wn = wid & 1;
    const int g = lane >> 2, tg = lane & 3;
    const int laneA = (lane & 15) * 20 + (lane >> 4) * 4;
    const int laneB = ((lane & 7) + ((lane >> 4) << 3)) * 20 + ((lane >> 3) & 1) * 4;
    const unsigned* x32 = (const unsigned*)g_x16;
    const unsigned* w32 = (const unsigned*)(g_wq16 + 2 * Cn * Cn);  // v0 rows

    auto prefetch = [&](int kc, int buf) {
        const int k0w = kc * 16;
#pragma unroll
        for (int p = 0; p < 2; p++) {
            int idx = tid + p * 256;
            int row = idx >> 2, c4 = idx & 3;
            unsigned d = (row * 20 + c4 * 4) * 4;
            CP16(s_base + buf * 2560 * 4 + d, x32 + (m0 + row) * 384 + k0w + c4 * 4);
        }
        {
            int row = tid >> 2, c4 = tid & 3;
            unsigned d = (row * 20 + c4 * 4) * 4;
            CP16(s_base + (5120 + buf * 1280) * 4 + d, w32 + (n0 + row) * 384 + k0w + c4 * 4);
        }
    };

    float c[2][4][4];
#pragma unroll
    for (int i = 0; i < 2; i++)
#pragma unroll
        for (int j = 0; j < 4; j++)
#pragma unroll
            for (int r = 0; r < 4; r++) c[i][j][r] = 0.f;

    prefetch(0, 0);
    CPCOMMIT();
    for (int kc = 0; kc < 24; kc++) {
        const int buf = kc & 1;
        CPWAIT0();
        __syncthreads();
        if (kc < 23) { prefetch(kc + 1, buf ^ 1); CPCOMMIT(); }
        const unsigned ab = s_base + (buf * 2560) * 4;
        const unsigned bb = s_base + (5120 + buf * 1280) * 4;
#pragma unroll
        for (int ks = 0; ks < 2; ks++) {
            const int kw = ks * 8;
            unsigned a[2][4], b[4][2];
#pragma unroll
            for (int mt = 0; mt < 2; mt++)
                ldsm4(a[mt], ab + ((wm * 32 + mt * 16) * 20 + kw + laneA) * 4);
#pragma unroll
            for (int ntp = 0; ntp < 2; ntp++) {
                unsigned r[4];
                ldsm4(r, bb + ((wn * 32 + ntp * 16) * 20 + kw + laneB) * 4);
                b[2*ntp][0] = r[0]; b[2*ntp][1] = r[1]; b[2*ntp+1][0] = r[2]; b[2*ntp+1][1] = r[3];
            }
#pragma unroll
            for (int mt = 0; mt < 2; mt++)
#pragma unroll
                for (int nt = 0; nt < 4; nt++)
                    mma_f16(c[mt][nt], a[mt], b[nt]);
        }
    }
#pragma unroll
    for (int mt = 0; mt < 2; mt++)
#pragma unroll
        for (int nt = 0; nt < 4; nt++)
#pragma unroll
            for (int rr = 0; rr < 2; rr++) {
                int m = m0 + wm * 32 + mt * 16 + g + rr * 8;
                int b2 = m >> 11, t = m & 2047;
#pragma unroll
                for (int cc = 0; cc < 2; cc++) {
                    int n = n0 + wn * 32 + nt * 8 + 2 * tg + cc;
                    int h = n >> 6, d = n & 63;
                    g_v0[((b2 * NHn + h) * Tn + t) * HSn + d] = c[mt][nt][rr * 2 + cc];
                }
            }
}

// ================= vmix: 196608 x 64 x 4096, single fp16 x single fp16 =================
// dyn smem words: v0s float @0 (4096), kts @4096 (4096), As half [2][1280w] @8192,
//                 Bh [2][1280] @10752  -> 13312 words
#define VMIX_SMEM_BYTES (13312*4)
__global__ void __launch_bounds__(256) vmix_mma(const float* __restrict__ bv) {
    extern __shared__ unsigned sm[];
    float* smf = (float*)sm;
    const unsigned s_base = sptr(sm);
    const int tok0 = blockIdx.x * 64;
    const int tid = threadIdx.x, wid = tid >> 5, lane = tid & 31;
    const int wm = wid >> 1, wn = wid & 1;
    const int g = lane >> 2, tg = lane & 3;
    const int laneA = (lane & 15) * 20 + (lane >> 4) * 4;
    const int laneB = ((lane & 7) + ((lane >> 4) << 3)) * 20 + ((lane >> 3) & 1) * 4;
    const unsigned* wv32 = (const unsigned*)g_wv16;

#pragma unroll
    for (int p = 0; p < 4; p++) {
        int idx = (tid + p * 256) * 4;
        *(float4*)&smf[idx]        = *(const float4*)(g_v0 + tok0 * HSn + idx);
        *(float4*)&smf[4096 + idx] = *(const float4*)(g_k  + tok0 * HSn + idx);
    }

    auto prefetchB = [&](int ch, int buf) {
        int row = tid >> 2, c4 = tid & 3;
        unsigned d = (row * 20 + c4 * 4) * 4;
        CP16(s_base + (10752 + buf * 1280) * 4 + d, wv32 + row * 2048 + ch * 16 + c4 * 4);
    };

    prefetchB(0, 0);
    CPCOMMIT();
    __syncthreads();   // v0s/kts ready

    float c[4][4];
#pragma unroll
    for (int j = 0; j < 4; j++)
#pragma unroll
        for (int r = 0; r < 4; r++) c[j][r] = 0.f;

    const int tA = tid >> 2, cb = (tid & 3) * 8;
    for (int ch = 0; ch < 128; ch++) {
        const int buf = ch & 1;
        const int i = ch >> 1, jb = (ch & 1) * 32;
        {
            float kk = smf[4096 + tA * 64 + i];
            float4 u0 = *(const float4*)&smf[tA * 64 + jb + cb];
            float4 u1 = *(const float4*)&smf[tA * 64 + jb + cb + 4];
            __half2 p0 = __floats2half2_rn(kk * u0.x, kk * u0.y);
            __half2 p1 = __floats2half2_rn(kk * u0.z, kk * u0.w);
            __half2 p2 = __floats2half2_rn(kk * u1.x, kk * u1.y);
            __half2 p3 = __floats2half2_rn(kk * u1.z, kk * u1.w);
            uint4 w;
            w.x = *(unsigned*)&p0; w.y = *(unsigned*)&p1;
            w.z = *(unsigned*)&p2; w.w = *(unsigned*)&p3;
            *(uint4*)&sm[8192 + buf * 1280 + tA * 20 + (cb >> 1)] = w;
        }
        CPWAIT0();
        __syncthreads();
        if (ch < 127) { prefetchB(ch + 1, buf ^ 1); CPCOMMIT(); }
        const unsigned asb = s_base + (8192 + buf * 1280) * 4;
        const unsigned bhb = s_base + (10752 + buf * 1280) * 4;
#pragma unroll
        for (int ks = 0; ks < 2; ks++) {
            const int kw = ks * 8;
            unsigned a[4], b[4][2];
            ldsm4(a, asb + ((wm * 16) * 20 + kw + laneA) * 4);
#pragma unroll
            for (int ntp = 0; ntp < 2; ntp++) {
                unsigned r[4];
                ldsm4(r, bhb + ((wn * 32 + ntp * 16) * 20 + kw + laneB) * 4);
                b[2*ntp][0] = r[0]; b[2*ntp][1] = r[1]; b[2*ntp+1][0] = r[2]; b[2*ntp+1][1] = r[3];
            }
#pragma unroll
            for (int nt = 0; nt < 4; nt++)
                mma_f16(c[nt], a, b[nt]);
        }
    }
#pragma unroll
    for (int nt = 0; nt < 4; nt++)
#pragma unroll
        for (int rr = 0; rr < 2; rr++) {
            int t = tok0 + wm * 16 + g + rr * 8;
#pragma unroll
            for (int cc = 0; cc < 2; cc++) {
                int e = wn * 32 + nt * 8 + 2 * tg + cc;
                g_v[t * HSn + e] = c[nt][rr * 2 + cc] + bv[e];
            }
        }
}

// ---------------- local scans: tails + level-0 segment sums ----------------
__global__ void scan_kernel() {
    int blk = blockIdx.x;
    int bh = blk >> 4, tb = blk & 15;
    const float* src = blockIdx.y ? g_v : g_k;
    float* tail = blockIdx.y ? g_vtail : g_ktail;
    float* seg  = blockIdx.y ? g_Vs : g_Ks;
    int d = threadIdx.x & 63, grp = threadIdx.x >> 6;
    int t0 = tb * 128 + grp * 16;
    int base = (bh * Tn + t0) * HSn + d;
    float acc = 0.f;
#pragma unroll
    for (int i = 0; i < 16; i++) {
        acc += src[base + i * HSn];
        tail[base + i * HSn] = acc;
    }
    int s0 = t0 >> 4;
    seg[(bh * NSEG + s0) * HSn + d] = acc;
}

// ---------------- level merge: levels 1..7 ----------------
__global__ void merge_kernel() {
    int bh = blockIdx.x;
    float* seg = blockIdx.y ? g_Vs : g_Ks;
    float* base = seg + bh * NSEG * HSn;
    for (int v = 1; v <= 7; v++) {
        int cnt = 128 >> v;
        int cs = 256 - (256 >> v);
        int ps = 256 - (256 >> (v - 1));
        __syncthreads();
        for (int idx = threadIdx.x; idx < cnt * HSn; idx += 256) {
            int i = idx >> 6, d = idx & 63;
            base[(cs + i) * HSn + d] =
                base[(ps + 2 * i) * HSn + d] + base[(ps + 2 * i + 1) * HSn + d];
        }
    }
}

// ---------------- attention: logits + softmax + AV (fp32) ----------------
__global__ void __launch_bounds__(256) attn_kernel() {
    __shared__ float qst[64][32];
    __shared__ float lg[32][257];
    const int bh = blockIdx.y, t0 = blockIdx.x * 32;
    const int tid = threadIdx.x;
    const float scale = 0.125f;
    const int qbase = (bh * Tn + t0) * HSn;

    for (int p = 0; p < 8; p++) {
        int idx = tid + p * 256;
        int t = idx >> 6, d = idx & 63;
        qst[d][t] = g_q[qbase + idx];
    }
    __syncthreads();

    for (int idx = tid; idx < 32 * NSEG; idx += 256) {
        int tl = idx & 31, s = idx >> 5;
        int tg2 = t0 + tl;
        int r = g_ridx[s];
        float val = NEG_INF;
        if (t0 + 31 >= r) {
            const float* Kp = g_Ks + (bh * NSEG + s) * HSn;
            float acc = 0.f;
#pragma unroll
            for (int d = 0; d < 64; d += 4) {
                float4 k4 = *(const float4*)(Kp + d);
                acc += qst[d + 0][tl] * k4.x + qst[d + 1][tl] * k4.y
                     + qst[d + 2][tl] * k4.z + qst[d + 3][tl] * k4.w;
            }
            if (tg2 >= r) val = acc * scale;
        }
        lg[tl][s] = val;
    }

    if (tid < 32) {
        int tl = tid, tg2 = t0 + tl;
        const float* kt = g_ktail + (bh * Tn + tg2) * HSn;
        float acc = 0.f;
#pragma unroll
        for (int d = 0; d < 64; d++) acc += qst[d][tl] * kt[d];
        lg[tl][255] = acc * scale;
    }
    __syncthreads();

    int warp = tid >> 5, lane = tid & 31;
#pragma unroll
    for (int u = 0; u < 4; u++) {
        int t = warp * 4 + u;
        float m = NEG_INF;
        for (int s = lane; s < 256; s += 32) m = fmaxf(m, lg[t][s]);
#pragma unroll
        for (int o = 16; o; o >>= 1) m = fmaxf(m, __shfl_xor_sync(0xffffffffu, m, o));
        float sum = 0.f;
        for (int s = lane; s < 256; s += 32) {
            float p = __expf(lg[t][s] - m);
            lg[t][s] = p;
            sum += p;
        }
#pragma unroll
        for (int o = 16; o; o >>= 1) sum += __shfl_xor_sync(0xffffffffu, sum, o);
        float inv = 1.0f / sum;
        for (int s = lane; s < 256; s += 32) lg[t][s] *= inv;
    }
    __syncthreads();

    const float* Vbase = g_Vs + bh * NSEG * HSn;
    for (int p = 0; p < 8; p++) {
        int idx = tid + p * 256;
        int tl = idx >> 6, d = idx & 63;
        int tg2 = t0 + tl;
        float acc = 0.f;
#pragma unroll
        for (int v = 0; v < 8; v++) {
            int start = 256 - (256 >> v);
            int cnt = (tg2 + 1) >> (4 + v);
            for (int ii = 0; ii < cnt; ii++) {
                int s = start + ii;
                acc += lg[tl][s] * Vbase[s * HSn + d];
            }
        }
        float vt = g_vtail[(bh * Tn + tg2) * HSn + d];
        acc += lg[tl][255] * vt;
        int b = bh / NHn, h = bh - b * NHn;
        int off = (b * Tn + tg2) * Cn + h * HSn + d;
        __nv_bfloat16 hh = __float2bfloat16(acc);
        g_yh[off] = hh;
        g_yl[off] = __float2bfloat16(acc - __bfloat162float(hh));
    }
}

// ================= proj GEMM: 16384 x 768 x 768, bf16x3 =================
__global__ void __launch_bounds__(256) proj_mma(float* __restrict__ out) {
    extern __shared__ unsigned sm[];
    const unsigned s_base = sptr(sm);
    const int m0 = blockIdx.y * 128, n0 = blockIdx.x * 64;
    const int tid = threadIdx.x, wid = tid >> 5, lane = tid & 31;
    const int wm = wid >> 1, wn = wid & 1;
    const int g = lane >> 2, tg = lane & 3;
    const int laneA = (lane & 15) * 20 + (lane >> 4) * 4;
    const int laneB = ((lane & 7) + ((lane >> 4) << 3)) * 20 + ((lane >> 3) & 1) * 4;
    const unsigned* yh32 = (const unsigned*)g_yh;
    const unsigned* yl32 = (const unsigned*)g_yl;
    const unsigned* wh32 = (const unsigned*)g_wph;
    const unsigned* wl32 = (const unsigned*)g_wpl;

    auto prefetch = [&](int kc, int buf) {
        const int k0w = kc * 16;
#pragma unroll
        for (int p = 0; p < 2; p++) {
            int idx = tid + p * 256;
            int row = idx >> 2, c4 = idx & 3;
            unsigned d = (row * 20 + c4 * 4) * 4;
            CP16(s_base + buf * 2560 * 4 + d,           yh32 + (m0 + row) * 384 + k0w + c4 * 4);
            CP16(s_base + (5120 + buf * 2560) * 4 + d,  yl32 + (m0 + row) * 384 + k0w + c4 * 4);
        }
        {
            int row = tid >> 2, c4 = tid & 3;
            unsigned d = (row * 20 + c4 * 4) * 4;
            CP16(s_base + (10240 + buf * 1280) * 4 + d, wh32 + (n0 + row) * 384 + k0w + c4 * 4);
            CP16(s_base + (12800 + buf * 1280) * 4 + d, wl32 + (n0 + row) * 384 + k0w + c4 * 4);
        }
    };

    float c[2][4][4];
#pragma unroll
    for (int i = 0; i < 2; i++)
#pragma unroll
        for (int j = 0; j < 4; j++)
#pragma unroll
            for (int r = 0; r < 4; r++) c[i][j][r] = 0.f;

    prefetch(0, 0);
    CPCOMMIT();
    for (int kc = 0; kc < 24; kc++) {
        const int buf = kc & 1;
        CPWAIT0();
        __syncthreads();
        if (kc < 23) { prefetch(kc + 1, buf ^ 1); CPCOMMIT(); }
        const unsigned ahb = s_base + (buf * 2560) * 4;
        const unsigned alb = s_base + (5120 + buf * 2560) * 4;
        const unsigned bhb = s_base + (10240 + buf * 1280) * 4;
        const unsigned blb = s_base + (12800 + buf * 1280) * 4;
#pragma unroll
        for (int ks = 0; ks < 2; ks++) {
            const int kw = ks * 8;
            unsigned ah[2][4], al[2][4], bh[4][2], bl[4][2];
#pragma unroll
            for (int mt = 0; mt < 2; mt++) {
                unsigned off = ((wm * 32 + mt * 16) * 20 + kw + laneA) * 4;
                ldsm4(ah[mt], ahb + off);
                ldsm4(al[mt], alb + off);
            }
#pragma unroll
            for (int ntp = 0; ntp < 2; ntp++) {
                unsigned off = ((wn * 32 + ntp * 16) * 20 + kw + laneB) * 4;
                unsigned r[4];
                ldsm4(r, bhb + off);
                bh[2*ntp][0] = r[0]; bh[2*ntp][1] = r[1]; bh[2*ntp+1][0] = r[2]; bh[2*ntp+1][1] = r[3];
                ldsm4(r, blb + off);
                bl[2*ntp][0] = r[0]; bl[2*ntp][1] = r[1]; bl[2*ntp+1][0] = r[2]; bl[2*ntp+1][1] = r[3];
            }
#pragma unroll
            for (int mt = 0; mt < 2; mt++)
#pragma unroll
                for (int nt = 0; nt < 4; nt++) {
                    mma_bf16(c[mt][nt], ah[mt], bh[nt]);
                    mma_bf16(c[mt][nt], ah[mt], bl[nt]);
                    mma_bf16(c[mt][nt], al[mt], bh[nt]);
                }
        }
    }
#pragma unroll
    for (int mt = 0; mt < 2; mt++)
#pragma unroll
        for (int nt = 0; nt < 4; nt++)
#pragma unroll
            for (int rr = 0; rr < 2; rr++) {
                int m = m0 + wm * 32 + mt * 16 + g + rr * 8;
#pragma unroll
                for (int cc = 0; cc < 2; cc++) {
                    int n = n0 + wn * 32 + nt * 8 + 2 * tg + cc;
                    out[m * Cn + n] = c[mt][nt][rr * 2 + cc];
                }
            }
}

// ---------------- launch ----------------
extern "C" void kernel_launch(void* const* d_in, const int* in_sizes, int n_in,
                              void* d_out, int out_size) {
    const float* x     = (const float*)d_in[0];
    const float* Wqkv  = (const float*)d_in[1];
    const float* Wproj = (const float*)d_in[2];
    const float* Wv    = (const float*)d_in[3];
    const float* bv    = (const float*)d_in[4];
    float* out = (float*)d_out;

    cudaFuncSetAttribute(qk_mma,   cudaFuncAttributeMaxDynamicSharedMemorySize, QKV_SMEM_BYTES);
    cudaFuncSetAttribute(v0_mma,   cudaFuncAttributeMaxDynamicSharedMemorySize, V0_SMEM_BYTES);
    cudaFuncSetAttribute(vmix_mma, cudaFuncAttributeMaxDynamicSharedMemorySize, VMIX_SMEM_BYTES);
    cudaFuncSetAttribute(proj_mma, cudaFuncAttributeMaxDynamicSharedMemorySize, QKV_SMEM_BYTES);

    init_sets_kernel<<<1, 256>>>();
    split_kernel<<<(Bn*Tn*Cn + 255) / 256, 256>>>(x, 0, Bn*Tn*Cn);
    split_kernel<<<(3*Cn*Cn + 255) / 256, 256>>>(Wqkv, 1, 3*Cn*Cn);
    split_kernel<<<(HSn*HSn*HSn + 255) / 256, 256>>>(Wv, 2, HSn*HSn*HSn);
    split_kernel<<<(Cn*Cn + 255) / 256, 256>>>(Wproj, 3, Cn*Cn);
    qk_mma<<<dim3(24, 128), 256, QKV_SMEM_BYTES>>>();
    v0_mma<<<dim3(12, 128), 256, V0_SMEM_BYTES>>>();
    vmix_mma<<<NTOK / 64, 256, VMIX_SMEM_BYTES>>>(bv);
    scan_kernel<<<dim3(BHn * 16, 2), 512>>>();
    merge_kernel<<<dim3(BHn, 2), 256>>>();
    attn_kernel<<<dim3(Tn / 32, BHn), 256>>>();
    proj_mma<<<dim3(Cn / 64, 128), 256, QKV_SMEM_BYTES>>>(out);
}

// round 6
// speedup vs baseline: 2.9272x; 1.1203x over previous
#include <cuda_runtime.h>
#include <cuda_bf16.h>
#include <cuda_fp16.h>

#define Bn 8
#define Tn 2048
#define Cn 768
#define NHn 12
#define HSn 64
#define BHn (Bn*NHn)        // 96
#define NSEG 255
#define LMIN 16
#define NTOK (BHn*Tn)       // 196608
#define NEG_INF __int_as_float(0xff800000u)

// ---------------- device scratch ----------------
__device__ float g_q    [NTOK*HSn];
__device__ float g_k    [NTOK*HSn];
__device__ float g_v0   [NTOK*HSn];
__device__ float g_v    [NTOK*HSn];
__device__ float g_ktail[NTOK*HSn];
__device__ float g_vtail[NTOK*HSn];
__device__ float g_Ks   [BHn*NSEG*HSn];
__device__ float g_Vs   [BHn*NSEG*HSn];
__device__ __nv_bfloat16 g_yh [Bn*Tn*Cn], g_yl [Bn*Tn*Cn];
__device__ __nv_bfloat16 g_xh [Bn*Tn*Cn], g_xl [Bn*Tn*Cn];
__device__ half          g_x16[Bn*Tn*Cn];
__device__ __nv_bfloat16 g_wqh[3*Cn*Cn],  g_wql[3*Cn*Cn];
__device__ half          g_wq16[3*Cn*Cn];
__device__ __nv_bfloat16 g_wph[Cn*Cn],    g_wpl[Cn*Cn];
__device__ half g_wv16[HSn*HSn*HSn];
__device__ int g_ridx[NSEG];

// ---------------- PTX helpers ----------------
__device__ __forceinline__ unsigned sptr(const void* p) {
    return (unsigned)__cvta_generic_to_shared(p);
}
#define CP16(dst, src) asm volatile("cp.async.ca.shared.global [%0], [%1], 16;\n" :: "r"(dst), "l"(src))
#define CPCOMMIT()     asm volatile("cp.async.commit_group;\n")
#define CPWAIT0()      asm volatile("cp.async.wait_group 0;\n")

__device__ __forceinline__ void ldsm4(unsigned* r, unsigned addr) {
    asm volatile("ldmatrix.sync.aligned.m8n8.x4.shared.b16 {%0,%1,%2,%3}, [%4];\n"
                 : "=r"(r[0]), "=r"(r[1]), "=r"(r[2]), "=r"(r[3]) : "r"(addr));
}
__device__ __forceinline__ void mma_bf16(float* c, const unsigned* a, const unsigned* b) {
    asm volatile(
        "mma.sync.aligned.m16n8k16.row.col.f32.bf16.bf16.f32 "
        "{%0,%1,%2,%3}, {%4,%5,%6,%7}, {%8,%9}, {%0,%1,%2,%3};\n"
        : "+f"(c[0]), "+f"(c[1]), "+f"(c[2]), "+f"(c[3])
        : "r"(a[0]), "r"(a[1]), "r"(a[2]), "r"(a[3]), "r"(b[0]), "r"(b[1]));
}
__device__ __forceinline__ void mma_f16(float* c, const unsigned* a, const unsigned* b) {
    asm volatile(
        "mma.sync.aligned.m16n8k16.row.col.f32.f16.f16.f32 "
        "{%0,%1,%2,%3}, {%4,%5,%6,%7}, {%8,%9}, {%0,%1,%2,%3};\n"
        : "+f"(c[0]), "+f"(c[1]), "+f"(c[2]), "+f"(c[3])
        : "r"(a[0]), "r"(a[1]), "r"(a[2]), "r"(a[3]), "r"(b[0]), "r"(b[1]));
}

// ---------------- init segment r-index ----------------
__global__ void init_sets_kernel() {
    int s = threadIdx.x;
    if (s < NSEG) {
        int v = 0, rem = s;
        while (rem >= (128 >> v)) { rem -= (128 >> v); v++; }
        int L = LMIN << v;
        g_ridx[s] = (rem + 1) * L - 1;
    }
}

// ---------------- split fp32 -> hi/lo bf16 + fp16 variants ----------------
__global__ void split_kernel(const float* __restrict__ src, int which, int n) {
    int i = blockIdx.x * 256 + threadIdx.x;
    if (i >= n) return;
    float x = src[i];
    if (which == 2) { g_wv16[i] = __float2half_rn(x); return; }
    __nv_bfloat16 *h, *l;
    switch (which) {
        case 0: h = g_xh;  l = g_xl;  g_x16[i]  = __float2half_rn(x); break;
        case 1: h = g_wqh; l = g_wql; g_wq16[i] = __float2half_rn(x); break;
        default:h = g_wph; l = g_wpl; break;
    }
    __nv_bfloat16 hh = __float2bfloat16(x);
    h[i] = hh;
    l[i] = __float2bfloat16(x - __bfloat162float(hh));
}

// ================= big GEMM (bf16x3, 128x128 tiles): qk (mode 0) / proj (mode 1) =================
// dyn smem words: AH[2][2560] @0, AL[2][2560] @5120, BH[2][2560] @10240, BL[2][2560] @15360
#define GB_SMEM_BYTES (20480*4)
__global__ void __launch_bounds__(256) gemm_big(int mode, float* __restrict__ outp) {
    extern __shared__ unsigned sm[];
    const unsigned s_base = sptr(sm);
    const int m0 = blockIdx.y * 128, n0 = blockIdx.x * 128;
    const int tid = threadIdx.x, wid = tid >> 5, lane = tid & 31;
    const int wm = wid >> 1, wn = wid & 1;
    const int g = lane >> 2, tg = lane & 3;
    const int laneA = (lane & 15) * 20 + (lane >> 4) * 4;
    const int laneB = ((lane & 7) + ((lane >> 4) << 3)) * 20 + ((lane >> 3) & 1) * 4;
    const unsigned* ah32 = (const unsigned*)(mode ? g_yh : g_xh);
    const unsigned* al32 = (const unsigned*)(mode ? g_yl : g_xl);
    const unsigned* bh32 = (const unsigned*)(mode ? g_wph : g_wqh);
    const unsigned* bl32 = (const unsigned*)(mode ? g_wpl : g_wql);

    auto prefetch = [&](int kc, int buf) {
        const int k0w = kc * 16;
#pragma unroll
        for (int p = 0; p < 2; p++) {
            int idx = tid + p * 256;
            int row = idx >> 2, c4 = idx & 3;
            unsigned d = (row * 20 + c4 * 4) * 4;
            CP16(s_base + buf * 2560 * 4 + d,             ah32 + (m0 + row) * 384 + k0w + c4 * 4);
            CP16(s_base + (5120 + buf * 2560) * 4 + d,    al32 + (m0 + row) * 384 + k0w + c4 * 4);
            CP16(s_base + (10240 + buf * 2560) * 4 + d,   bh32 + (n0 + row) * 384 + k0w + c4 * 4);
            CP16(s_base + (15360 + buf * 2560) * 4 + d,   bl32 + (n0 + row) * 384 + k0w + c4 * 4);
        }
    };

    float c[2][8][4];
#pragma unroll
    for (int i = 0; i < 2; i++)
#pragma unroll
        for (int j = 0; j < 8; j++)
#pragma unroll
            for (int r = 0; r < 4; r++) c[i][j][r] = 0.f;

    prefetch(0, 0);
    CPCOMMIT();
    for (int kc = 0; kc < 24; kc++) {
        const int buf = kc & 1;
        CPWAIT0();
        __syncthreads();
        if (kc < 23) { prefetch(kc + 1, buf ^ 1); CPCOMMIT(); }
        const unsigned ahb = s_base + (buf * 2560) * 4;
        const unsigned alb = s_base + (5120 + buf * 2560) * 4;
        const unsigned bhb = s_base + (10240 + buf * 2560) * 4;
        const unsigned blb = s_base + (15360 + buf * 2560) * 4;
#pragma unroll
        for (int ks = 0; ks < 2; ks++) {
            const int kw = ks * 8;
            unsigned ah[2][4], al[2][4], bh[8][2], bl[8][2];
#pragma unroll
            for (int mt = 0; mt < 2; mt++) {
                unsigned off = ((wm * 32 + mt * 16) * 20 + kw + laneA) * 4;
                ldsm4(ah[mt], ahb + off);
                ldsm4(al[mt], alb + off);
            }
#pragma unroll
            for (int ntp = 0; ntp < 4; ntp++) {
                unsigned off = ((wn * 64 + ntp * 16) * 20 + kw + laneB) * 4;
                unsigned r[4];
                ldsm4(r, bhb + off);
                bh[2*ntp][0] = r[0]; bh[2*ntp][1] = r[1]; bh[2*ntp+1][0] = r[2]; bh[2*ntp+1][1] = r[3];
                ldsm4(r, blb + off);
                bl[2*ntp][0] = r[0]; bl[2*ntp][1] = r[1]; bl[2*ntp+1][0] = r[2]; bl[2*ntp+1][1] = r[3];
            }
#pragma unroll
            for (int mt = 0; mt < 2; mt++)
#pragma unroll
                for (int nt = 0; nt < 8; nt++) {
                    mma_bf16(c[mt][nt], ah[mt], bh[nt]);
                    mma_bf16(c[mt][nt], ah[mt], bl[nt]);
                    mma_bf16(c[mt][nt], al[mt], bh[nt]);
                }
        }
    }
#pragma unroll
    for (int mt = 0; mt < 2; mt++)
#pragma unroll
        for (int nt = 0; nt < 8; nt++)
#pragma unroll
            for (int rr = 0; rr < 2; rr++) {
                int m = m0 + wm * 32 + mt * 16 + g + rr * 8;
#pragma unroll
                for (int cc = 0; cc < 2; cc++) {
                    int n = n0 + wn * 64 + nt * 8 + 2 * tg + cc;
                    float val = c[mt][nt][rr * 2 + cc];
                    if (mode) {
                        outp[m * Cn + n] = val;
                    } else {
                        int b = m >> 11, t = m & 2047;
                        int which = (n >= Cn) ? 1 : 0;
                        int col = n - which * Cn;
                        int h = col >> 6, d = col & 63;
                        float* dst = which ? g_k : g_q;
                        dst[((b * NHn + h) * Tn + t) * HSn + d] = val;
                    }
                }
            }
}

// ================= v0 GEMM: 16384 x 768 x 768, single fp16 =================
// dyn smem words: A[2][2560] @0, B[2][1280] @5120  -> 7680 words
#define V0_SMEM_BYTES (7680*4)
__global__ void __launch_bounds__(256) v0_mma() {
    extern __shared__ unsigned sm[];
    const unsigned s_base = sptr(sm);
    const int m0 = blockIdx.y * 128, n0 = blockIdx.x * 64;
    const int tid = threadIdx.x, wid = tid >> 5, lane = tid & 31;
    const int wm = wid >> 1, wn = wid & 1;
    const int g = lane >> 2, tg = lane & 3;
    const int laneA = (lane & 15) * 20 + (lane >> 4) * 4;
    const int laneB = ((lane & 7) + ((lane >> 4) << 3)) * 20 + ((lane >> 3) & 1) * 4;
    const unsigned* x32 = (const unsigned*)g_x16;
    const unsigned* w32 = (const unsigned*)(g_wq16 + 2 * Cn * Cn);  // v0 rows

    auto prefetch = [&](int kc, int buf) {
        const int k0w = kc * 16;
#pragma unroll
        for (int p = 0; p < 2; p++) {
            int idx = tid + p * 256;
            int row = idx >> 2, c4 = idx & 3;
            unsigned d = (row * 20 + c4 * 4) * 4;
            CP16(s_base + buf * 2560 * 4 + d, x32 + (m0 + row) * 384 + k0w + c4 * 4);
        }
        {
            int row = tid >> 2, c4 = tid & 3;
            unsigned d = (row * 20 + c4 * 4) * 4;
            CP16(s_base + (5120 + buf * 1280) * 4 + d, w32 + (n0 + row) * 384 + k0w + c4 * 4);
        }
    };

    float c[2][4][4];
#pragma unroll
    for (int i = 0; i < 2; i++)
#pragma unroll
        for (int j = 0; j < 4; j++)
#pragma unroll
            for (int r = 0; r < 4; r++) c[i][j][r] = 0.f;

    prefetch(0, 0);
    CPCOMMIT();
    for (int kc = 0; kc < 24; kc++) {
        const int buf = kc & 1;
        CPWAIT0();
        __syncthreads();
        if (kc < 23) { prefetch(kc + 1, buf ^ 1); CPCOMMIT(); }
        const unsigned ab = s_base + (buf * 2560) * 4;
        const unsigned bb = s_base + (5120 + buf * 1280) * 4;
#pragma unroll
        for (int ks = 0; ks < 2; ks++) {
            const int kw = ks * 8;
            unsigned a[2][4], b[4][2];
#pragma unroll
            for (int mt = 0; mt < 2; mt++)
                ldsm4(a[mt], ab + ((wm * 32 + mt * 16) * 20 + kw + laneA) * 4);
#pragma unroll
            for (int ntp = 0; ntp < 2; ntp++) {
                unsigned r[4];
                ldsm4(r, bb + ((wn * 32 + ntp * 16) * 20 + kw + laneB) * 4);
                b[2*ntp][0] = r[0]; b[2*ntp][1] = r[1]; b[2*ntp+1][0] = r[2]; b[2*ntp+1][1] = r[3];
            }
#pragma unroll
            for (int mt = 0; mt < 2; mt++)
#pragma unroll
                for (int nt = 0; nt < 4; nt++)
                    mma_f16(c[mt][nt], a[mt], b[nt]);
        }
    }
#pragma unroll
    for (int mt = 0; mt < 2; mt++)
#pragma unroll
        for (int nt = 0; nt < 4; nt++)
#pragma unroll
            for (int rr = 0; rr < 2; rr++) {
                int m = m0 + wm * 32 + mt * 16 + g + rr * 8;
                int b2 = m >> 11, t = m & 2047;
#pragma unroll
                for (int cc = 0; cc < 2; cc++) {
                    int n = n0 + wn * 32 + nt * 8 + 2 * tg + cc;
                    int h = n >> 6, d = n & 63;
                    g_v0[((b2 * NHn + h) * Tn + t) * HSn + d] = c[mt][nt][rr * 2 + cc];
                }
            }
}

// ================= vmix: 196608 x 64 x 4096, single fp16, 128-token tiles =================
// dyn smem words: V0 @0 (128*68=8704), K @8704 (8704), A[2] @17408 (2560 each), B[2] @22528 (1280 each)
#define VMIX_SMEM_BYTES (25088*4)
#define VP 68   // padded float pitch
__global__ void __launch_bounds__(256) vmix_mma(const float* __restrict__ bv) {
    extern __shared__ unsigned sm[];
    float* smf = (float*)sm;
    const unsigned s_base = sptr(sm);
    const int tok0 = blockIdx.x * 128;
    const int tid = threadIdx.x, wid = tid >> 5, lane = tid & 31;
    const int g = lane >> 2, tg = lane & 3;
    const int laneA = (lane & 15) * 20 + (lane >> 4) * 4;
    const int laneB = ((lane & 7) + ((lane >> 4) << 3)) * 20 + ((lane >> 3) & 1) * 4;
    const unsigned* wv32 = (const unsigned*)g_wv16;

    // stage v0 (@0) and k (@8704) tiles: 128 tokens x 64 dims, pitch VP
#pragma unroll
    for (int p = 0; p < 8; p++) {
        int q = tid + p * 256;               // quad index 0..2047
        int row = q >> 4, col = (q & 15) * 4;
        *(float4*)&smf[row * VP + col]        = *(const float4*)(g_v0 + (tok0 + row) * HSn + col);
        *(float4*)&smf[8704 + row * VP + col] = *(const float4*)(g_k  + (tok0 + row) * HSn + col);
    }

    auto prefetchB = [&](int ch, int buf) {
        int row = tid >> 2, c4 = tid & 3;
        unsigned d = (row * 20 + c4 * 4) * 4;
        CP16(s_base + (22528 + buf * 1280) * 4 + d, wv32 + row * 2048 + ch * 16 + c4 * 4);
    };

    prefetchB(0, 0);
    CPCOMMIT();
    __syncthreads();   // v0/k tiles ready

    float c[8][4];
#pragma unroll
    for (int j = 0; j < 8; j++)
#pragma unroll
        for (int r = 0; r < 4; r++) c[j][r] = 0.f;

    const int rA = tid >> 1, hA = (tid & 1) * 16;   // A-gen: row, col-half of 32-chunk
    for (int ch = 0; ch < 128; ch++) {
        const int buf = ch & 1;
        const int i = ch >> 1, jb = (ch & 1) * 32;
        // generate A tile (128 tok x 32 k) fp16
        {
            float kk = smf[8704 + rA * VP + i];
            int c0 = jb + hA;
            float4 u0 = *(const float4*)&smf[rA * VP + c0];
            float4 u1 = *(const float4*)&smf[rA * VP + c0 + 4];
            float4 u2 = *(const float4*)&smf[rA * VP + c0 + 8];
            float4 u3 = *(const float4*)&smf[rA * VP + c0 + 12];
            __half2 p0 = __floats2half2_rn(kk * u0.x, kk * u0.y);
            __half2 p1 = __floats2half2_rn(kk * u0.z, kk * u0.w);
            __half2 p2 = __floats2half2_rn(kk * u1.x, kk * u1.y);
            __half2 p3 = __floats2half2_rn(kk * u1.z, kk * u1.w);
            __half2 p4 = __floats2half2_rn(kk * u2.x, kk * u2.y);
            __half2 p5 = __floats2half2_rn(kk * u2.z, kk * u2.w);
            __half2 p6 = __floats2half2_rn(kk * u3.x, kk * u3.y);
            __half2 p7 = __floats2half2_rn(kk * u3.z, kk * u3.w);
            uint4 w0, w1;
            w0.x = *(unsigned*)&p0; w0.y = *(unsigned*)&p1;
            w0.z = *(unsigned*)&p2; w0.w = *(unsigned*)&p3;
            w1.x = *(unsigned*)&p4; w1.y = *(unsigned*)&p5;
            w1.z = *(unsigned*)&p6; w1.w = *(unsigned*)&p7;
            unsigned base = 17408 + buf * 2560 + rA * 20 + (hA >> 1);
            *(uint4*)&sm[base]     = w0;
            *(uint4*)&sm[base + 4] = w1;
        }
        CPWAIT0();
        __syncthreads();
        if (ch < 127) { prefetchB(ch + 1, buf ^ 1); CPCOMMIT(); }
        const unsigned asb = s_base + (17408 + buf * 2560) * 4;
        const unsigned bsb = s_base + (22528 + buf * 1280) * 4;
#pragma unroll
        for (int ks = 0; ks < 2; ks++) {
            const int kw = ks * 8;
            unsigned a[4], b[8][2];
            ldsm4(a, asb + ((wid * 16) * 20 + kw + laneA) * 4);
#pragma unroll
            for (int ntp = 0; ntp < 4; ntp++) {
                unsigned r[4];
                ldsm4(r, bsb + ((ntp * 16) * 20 + kw + laneB) * 4);
                b[2*ntp][0] = r[0]; b[2*ntp][1] = r[1]; b[2*ntp+1][0] = r[2]; b[2*ntp+1][1] = r[3];
            }
#pragma unroll
            for (int nt = 0; nt < 8; nt++)
                mma_f16(c[nt], a, b[nt]);
        }
        __syncthreads();
    }
#pragma unroll
    for (int nt = 0; nt < 8; nt++)
#pragma unroll
        for (int rr = 0; rr < 2; rr++) {
            int t = tok0 + wid * 16 + g + rr * 8;
#pragma unroll
            for (int cc = 0; cc < 2; cc++) {
                int e = nt * 8 + 2 * tg + cc;
                g_v[t * HSn + e] = c[nt][rr * 2 + cc] + bv[e];
            }
        }
}

// ---------------- local scans: tails + level-0 segment sums ----------------
__global__ void scan_kernel() {
    int blk = blockIdx.x;
    int bh = blk >> 4, tb = blk & 15;
    const float* src = blockIdx.y ? g_v : g_k;
    float* tail = blockIdx.y ? g_vtail : g_ktail;
    float* seg  = blockIdx.y ? g_Vs : g_Ks;
    int d = threadIdx.x & 63, grp = threadIdx.x >> 6;
    int t0 = tb * 128 + grp * 16;
    int base = (bh * Tn + t0) * HSn + d;
    float acc = 0.f;
#pragma unroll
    for (int i = 0; i < 16; i++) {
        acc += src[base + i * HSn];
        tail[base + i * HSn] = acc;
    }
    int s0 = t0 >> 4;
    seg[(bh * NSEG + s0) * HSn + d] = acc;
}

// ---------------- level merge: levels 1..7 ----------------
__global__ void merge_kernel() {
    int bh = blockIdx.x;
    float* seg = blockIdx.y ? g_Vs : g_Ks;
    float* base = seg + bh * NSEG * HSn;
    for (int v = 1; v <= 7; v++) {
        int cnt = 128 >> v;
        int cs = 256 - (256 >> v);
        int ps = 256 - (256 >> (v - 1));
        __syncthreads();
        for (int idx = threadIdx.x; idx < cnt * HSn; idx += 256) {
            int i = idx >> 6, d = idx & 63;
            base[(cs + i) * HSn + d] =
                base[(ps + 2 * i) * HSn + d] + base[(ps + 2 * i + 1) * HSn + d];
        }
    }
}

// ---------------- attention: logits + softmax + AV (fp32) ----------------
__global__ void __launch_bounds__(256) attn_kernel() {
    __shared__ float qst[64][32];
    __shared__ float lg[32][257];
    const int bh = blockIdx.y, t0 = blockIdx.x * 32;
    const int tid = threadIdx.x;
    const float scale = 0.125f;
    const int qbase = (bh * Tn + t0) * HSn;

    for (int p = 0; p < 8; p++) {
        int idx = tid + p * 256;
        int t = idx >> 6, d = idx & 63;
        qst[d][t] = g_q[qbase + idx];
    }
    __syncthreads();

    for (int idx = tid; idx < 32 * NSEG; idx += 256) {
        int tl = idx & 31, s = idx >> 5;
        int tg2 = t0 + tl;
        int r = g_ridx[s];
        float val = NEG_INF;
        if (t0 + 31 >= r) {
            const float* Kp = g_Ks + (bh * NSEG + s) * HSn;
            float acc = 0.f;
#pragma unroll
            for (int d = 0; d < 64; d += 4) {
                float4 k4 = *(const float4*)(Kp + d);
                acc += qst[d + 0][tl] * k4.x + qst[d + 1][tl] * k4.y
                     + qst[d + 2][tl] * k4.z + qst[d + 3][tl] * k4.w;
            }
            if (tg2 >= r) val = acc * scale;
        }
        lg[tl][s] = val;
    }

    if (tid < 32) {
        int tl = tid, tg2 = t0 + tl;
        const float* kt = g_ktail + (bh * Tn + tg2) * HSn;
        float acc = 0.f;
#pragma unroll
        for (int d = 0; d < 64; d++) acc += qst[d][tl] * kt[d];
        lg[tl][255] = acc * scale;
    }
    __syncthreads();

    int warp = tid >> 5, lane = tid & 31;
#pragma unroll
    for (int u = 0; u < 4; u++) {
        int t = warp * 4 + u;
        float m = NEG_INF;
        for (int s = lane; s < 256; s += 32) m = fmaxf(m, lg[t][s]);
#pragma unroll
        for (int o = 16; o; o >>= 1) m = fmaxf(m, __shfl_xor_sync(0xffffffffu, m, o));
        float sum = 0.f;
        for (int s = lane; s < 256; s += 32) {
            float p = __expf(lg[t][s] - m);
            lg[t][s] = p;
            sum += p;
        }
#pragma unroll
        for (int o = 16; o; o >>= 1) sum += __shfl_xor_sync(0xffffffffu, sum, o);
        float inv = 1.0f / sum;
        for (int s = lane; s < 256; s += 32) lg[t][s] *= inv;
    }
    __syncthreads();

    const float* Vbase = g_Vs + bh * NSEG * HSn;
    for (int p = 0; p < 8; p++) {
        int idx = tid + p * 256;
        int tl = idx >> 6, d = idx & 63;
        int tg2 = t0 + tl;
        float acc = 0.f;
#pragma unroll
        for (int v = 0; v < 8; v++) {
            int start = 256 - (256 >> v);
            int cnt = (tg2 + 1) >> (4 + v);
            for (int ii = 0; ii < cnt; ii++) {
                int s = start + ii;
                acc += lg[tl][s] * Vbase[s * HSn + d];
            }
        }
        float vt = g_vtail[(bh * Tn + tg2) * HSn + d];
        acc += lg[tl][255] * vt;
        int b = bh / NHn, h = bh - b * NHn;
        int off = (b * Tn + tg2) * Cn + h * HSn + d;
        __nv_bfloat16 hh = __float2bfloat16(acc);
        g_yh[off] = hh;
        g_yl[off] = __float2bfloat16(acc - __bfloat162float(hh));
    }
}

// ---------------- launch ----------------
extern "C" void kernel_launch(void* const* d_in, const int* in_sizes, int n_in,
                              void* d_out, int out_size) {
    const float* x     = (const float*)d_in[0];
    const float* Wqkv  = (const float*)d_in[1];
    const float* Wproj = (const float*)d_in[2];
    const float* Wv    = (const float*)d_in[3];
    const float* bv    = (const float*)d_in[4];
    float* out = (float*)d_out;

    cudaFuncSetAttribute(gemm_big, cudaFuncAttributeMaxDynamicSharedMemorySize, GB_SMEM_BYTES);
    cudaFuncSetAttribute(v0_mma,   cudaFuncAttributeMaxDynamicSharedMemorySize, V0_SMEM_BYTES);
    cudaFuncSetAttribute(vmix_mma, cudaFuncAttributeMaxDynamicSharedMemorySize, VMIX_SMEM_BYTES);

    init_sets_kernel<<<1, 256>>>();
    split_kernel<<<(Bn*Tn*Cn + 255) / 256, 256>>>(x, 0, Bn*Tn*Cn);
    split_kernel<<<(3*Cn*Cn + 255) / 256, 256>>>(Wqkv, 1, 3*Cn*Cn);
    split_kernel<<<(HSn*HSn*HSn + 255) / 256, 256>>>(Wv, 2, HSn*HSn*HSn);
    split_kernel<<<(Cn*Cn + 255) / 256, 256>>>(Wproj, 3, Cn*Cn);
    gemm_big<<<dim3(12, 128), 256, GB_SMEM_BYTES>>>(0, nullptr);   // qk
    v0_mma<<<dim3(12, 128), 256, V0_SMEM_BYTES>>>();
    vmix_mma<<<NTOK / 128, 256, VMIX_SMEM_BYTES>>>(bv);
    scan_kernel<<<dim3(BHn * 16, 2), 512>>>();
    merge_kernel<<<dim3(BHn, 2), 256>>>();
    attn_kernel<<<dim3(Tn / 32, BHn), 256>>>();
    gemm_big<<<dim3(6, 128), 256, GB_SMEM_BYTES>>>(1, out);        // proj
}

// round 7
// speedup vs baseline: 3.2763x; 1.1192x over previous
#include <cuda_runtime.h>
#include <cuda_bf16.h>
#include <cuda_fp16.h>

#define Bn 8
#define Tn 2048
#define Cn 768
#define NHn 12
#define HSn 64
#define BHn (Bn*NHn)        // 96
#define NSEG 255
#define LMIN 16
#define NTOK (BHn*Tn)       // 196608
#define NEG_INF __int_as_float(0xff800000u)

// ---------------- device scratch ----------------
__device__ float g_q    [NTOK*HSn];
__device__ float g_k    [NTOK*HSn];
__device__ float g_v0   [NTOK*HSn];
__device__ float g_v    [NTOK*HSn];
__device__ float g_ktail[NTOK*HSn];
__device__ float g_vtail[NTOK*HSn];
__device__ float g_Ks   [BHn*NSEG*HSn];
__device__ float g_Vs   [BHn*NSEG*HSn];
__device__ __nv_bfloat16 g_yh [Bn*Tn*Cn], g_yl [Bn*Tn*Cn];
__device__ __nv_bfloat16 g_xh [Bn*Tn*Cn], g_xl [Bn*Tn*Cn];
__device__ half          g_x16[Bn*Tn*Cn];
__device__ __nv_bfloat16 g_wqh[3*Cn*Cn],  g_wql[3*Cn*Cn];
__device__ half          g_wq16[3*Cn*Cn];
__device__ __nv_bfloat16 g_wph[Cn*Cn],    g_wpl[Cn*Cn];
__device__ half g_wv16[HSn*HSn*HSn];
__device__ int g_ridx[NSEG];

// ---------------- PTX helpers ----------------
__device__ __forceinline__ unsigned sptr(const void* p) {
    return (unsigned)__cvta_generic_to_shared(p);
}
#define CP16(dst, src) asm volatile("cp.async.ca.shared.global [%0], [%1], 16;\n" :: "r"(dst), "l"(src))
#define CPCOMMIT()     asm volatile("cp.async.commit_group;\n")
#define CPWAIT0()      asm volatile("cp.async.wait_group 0;\n")

__device__ __forceinline__ void ldsm4(unsigned* r, unsigned addr) {
    asm volatile("ldmatrix.sync.aligned.m8n8.x4.shared.b16 {%0,%1,%2,%3}, [%4];\n"
                 : "=r"(r[0]), "=r"(r[1]), "=r"(r[2]), "=r"(r[3]) : "r"(addr));
}
__device__ __forceinline__ void mma_bf16(float* c, const unsigned* a, const unsigned* b) {
    asm volatile(
        "mma.sync.aligned.m16n8k16.row.col.f32.bf16.bf16.f32 "
        "{%0,%1,%2,%3}, {%4,%5,%6,%7}, {%8,%9}, {%0,%1,%2,%3};\n"
        : "+f"(c[0]), "+f"(c[1]), "+f"(c[2]), "+f"(c[3])
        : "r"(a[0]), "r"(a[1]), "r"(a[2]), "r"(a[3]), "r"(b[0]), "r"(b[1]));
}
__device__ __forceinline__ void mma_f16(float* c, const unsigned* a, const unsigned* b) {
    asm volatile(
        "mma.sync.aligned.m16n8k16.row.col.f32.f16.f16.f32 "
        "{%0,%1,%2,%3}, {%4,%5,%6,%7}, {%8,%9}, {%0,%1,%2,%3};\n"
        : "+f"(c[0]), "+f"(c[1]), "+f"(c[2]), "+f"(c[3])
        : "r"(a[0]), "r"(a[1]), "r"(a[2]), "r"(a[3]), "r"(b[0]), "r"(b[1]));
}

// ---------------- init segment r-index ----------------
__global__ void init_sets_kernel() {
    int s = threadIdx.x;
    if (s < NSEG) {
        int v = 0, rem = s;
        while (rem >= (128 >> v)) { rem -= (128 >> v); v++; }
        int L = LMIN << v;
        g_ridx[s] = (rem + 1) * L - 1;
    }
}

// ---------------- split fp32 -> hi/lo bf16 + fp16 variants ----------------
__global__ void split_kernel(const float* __restrict__ src, int which, int n) {
    int i = blockIdx.x * 256 + threadIdx.x;
    if (i >= n) return;
    float x = src[i];
    if (which == 2) { g_wv16[i] = __float2half_rn(x); return; }
    __nv_bfloat16 *h, *l;
    switch (which) {
        case 0: h = g_xh;  l = g_xl;  g_x16[i]  = __float2half_rn(x); break;
        case 1: h = g_wqh; l = g_wql; g_wq16[i] = __float2half_rn(x); break;
        default:h = g_wph; l = g_wpl; break;
    }
    __nv_bfloat16 hh = __float2bfloat16(x);
    h[i] = hh;
    l[i] = __float2bfloat16(x - __bfloat162float(hh));
}

// ================= big GEMM (bf16x3, 128x128 tiles): qk (mode 0) / proj (mode 1) =================
#define GB_SMEM_BYTES (20480*4)
__global__ void __launch_bounds__(256) gemm_big(int mode, float* __restrict__ outp) {
    extern __shared__ unsigned sm[];
    const unsigned s_base = sptr(sm);
    const int m0 = blockIdx.y * 128, n0 = blockIdx.x * 128;
    const int tid = threadIdx.x, wid = tid >> 5, lane = tid & 31;
    const int wm = wid >> 1, wn = wid & 1;
    const int g = lane >> 2, tg = lane & 3;
    const int laneA = (lane & 15) * 20 + (lane >> 4) * 4;
    const int laneB = ((lane & 7) + ((lane >> 4) << 3)) * 20 + ((lane >> 3) & 1) * 4;
    const unsigned* ah32 = (const unsigned*)(mode ? g_yh : g_xh);
    const unsigned* al32 = (const unsigned*)(mode ? g_yl : g_xl);
    const unsigned* bh32 = (const unsigned*)(mode ? g_wph : g_wqh);
    const unsigned* bl32 = (const unsigned*)(mode ? g_wpl : g_wql);

    auto prefetch = [&](int kc, int buf) {
        const int k0w = kc * 16;
#pragma unroll
        for (int p = 0; p < 2; p++) {
            int idx = tid + p * 256;
            int row = idx >> 2, c4 = idx & 3;
            unsigned d = (row * 20 + c4 * 4) * 4;
            CP16(s_base + buf * 2560 * 4 + d,             ah32 + (m0 + row) * 384 + k0w + c4 * 4);
            CP16(s_base + (5120 + buf * 2560) * 4 + d,    al32 + (m0 + row) * 384 + k0w + c4 * 4);
            CP16(s_base + (10240 + buf * 2560) * 4 + d,   bh32 + (n0 + row) * 384 + k0w + c4 * 4);
            CP16(s_base + (15360 + buf * 2560) * 4 + d,   bl32 + (n0 + row) * 384 + k0w + c4 * 4);
        }
    };

    float c[2][8][4];
#pragma unroll
    for (int i = 0; i < 2; i++)
#pragma unroll
        for (int j = 0; j < 8; j++)
#pragma unroll
            for (int r = 0; r < 4; r++) c[i][j][r] = 0.f;

    prefetch(0, 0);
    CPCOMMIT();
    for (int kc = 0; kc < 24; kc++) {
        const int buf = kc & 1;
        CPWAIT0();
        __syncthreads();
        if (kc < 23) { prefetch(kc + 1, buf ^ 1); CPCOMMIT(); }
        const unsigned ahb = s_base + (buf * 2560) * 4;
        const unsigned alb = s_base + (5120 + buf * 2560) * 4;
        const unsigned bhb = s_base + (10240 + buf * 2560) * 4;
        const unsigned blb = s_base + (15360 + buf * 2560) * 4;
#pragma unroll
        for (int ks = 0; ks < 2; ks++) {
            const int kw = ks * 8;
            unsigned ah[2][4], al[2][4], bh[8][2], bl[8][2];
#pragma unroll
            for (int mt = 0; mt < 2; mt++) {
                unsigned off = ((wm * 32 + mt * 16) * 20 + kw + laneA) * 4;
                ldsm4(ah[mt], ahb + off);
                ldsm4(al[mt], alb + off);
            }
#pragma unroll
            for (int ntp = 0; ntp < 4; ntp++) {
                unsigned off = ((wn * 64 + ntp * 16) * 20 + kw + laneB) * 4;
                unsigned r[4];
                ldsm4(r, bhb + off);
                bh[2*ntp][0] = r[0]; bh[2*ntp][1] = r[1]; bh[2*ntp+1][0] = r[2]; bh[2*ntp+1][1] = r[3];
                ldsm4(r, blb + off);
                bl[2*ntp][0] = r[0]; bl[2*ntp][1] = r[1]; bl[2*ntp+1][0] = r[2]; bl[2*ntp+1][1] = r[3];
            }
#pragma unroll
            for (int mt = 0; mt < 2; mt++)
#pragma unroll
                for (int nt = 0; nt < 8; nt++) {
                    mma_bf16(c[mt][nt], ah[mt], bh[nt]);
                    mma_bf16(c[mt][nt], ah[mt], bl[nt]);
                    mma_bf16(c[mt][nt], al[mt], bh[nt]);
                }
        }
    }
#pragma unroll
    for (int mt = 0; mt < 2; mt++)
#pragma unroll
        for (int nt = 0; nt < 8; nt++)
#pragma unroll
            for (int rr = 0; rr < 2; rr++) {
                int m = m0 + wm * 32 + mt * 16 + g + rr * 8;
#pragma unroll
                for (int cc = 0; cc < 2; cc++) {
                    int n = n0 + wn * 64 + nt * 8 + 2 * tg + cc;
                    float val = c[mt][nt][rr * 2 + cc];
                    if (mode) {
                        outp[m * Cn + n] = val;
                    } else {
                        int b = m >> 11, t = m & 2047;
                        int which = (n >= Cn) ? 1 : 0;
                        int col = n - which * Cn;
                        int h = col >> 6, d = col & 63;
                        float* dst = which ? g_k : g_q;
                        dst[((b * NHn + h) * Tn + t) * HSn + d] = val;
                    }
                }
            }
}

// ================= v0 GEMM: 16384 x 768 x 768, single fp16 =================
#define V0_SMEM_BYTES (7680*4)
__global__ void __launch_bounds__(256) v0_mma() {
    extern __shared__ unsigned sm[];
    const unsigned s_base = sptr(sm);
    const int m0 = blockIdx.y * 128, n0 = blockIdx.x * 64;
    const int tid = threadIdx.x, wid = tid >> 5, lane = tid & 31;
    const int wm = wid >> 1, wn = wid & 1;
    const int g = lane >> 2, tg = lane & 3;
    const int laneA = (lane & 15) * 20 + (lane >> 4) * 4;
    const int laneB = ((lane & 7) + ((lane >> 4) << 3)) * 20 + ((lane >> 3) & 1) * 4;
    const unsigned* x32 = (const unsigned*)g_x16;
    const unsigned* w32 = (const unsigned*)(g_wq16 + 2 * Cn * Cn);  // v0 rows

    auto prefetch = [&](int kc, int buf) {
        const int k0w = kc * 16;
#pragma unroll
        for (int p = 0; p < 2; p++) {
            int idx = tid + p * 256;
            int row = idx >> 2, c4 = idx & 3;
            unsigned d = (row * 20 + c4 * 4) * 4;
            CP16(s_base + buf * 2560 * 4 + d, x32 + (m0 + row) * 384 + k0w + c4 * 4);
        }
        {
            int row = tid >> 2, c4 = tid & 3;
            unsigned d = (row * 20 + c4 * 4) * 4;
            CP16(s_base + (5120 + buf * 1280) * 4 + d, w32 + (n0 + row) * 384 + k0w + c4 * 4);
        }
    };

    float c[2][4][4];
#pragma unroll
    for (int i = 0; i < 2; i++)
#pragma unroll
        for (int j = 0; j < 4; j++)
#pragma unroll
            for (int r = 0; r < 4; r++) c[i][j][r] = 0.f;

    prefetch(0, 0);
    CPCOMMIT();
    for (int kc = 0; kc < 24; kc++) {
        const int buf = kc & 1;
        CPWAIT0();
        __syncthreads();
        if (kc < 23) { prefetch(kc + 1, buf ^ 1); CPCOMMIT(); }
        const unsigned ab = s_base + (buf * 2560) * 4;
        const unsigned bb = s_base + (5120 + buf * 1280) * 4;
#pragma unroll
        for (int ks = 0; ks < 2; ks++) {
            const int kw = ks * 8;
            unsigned a[2][4], b[4][2];
#pragma unroll
            for (int mt = 0; mt < 2; mt++)
                ldsm4(a[mt], ab + ((wm * 32 + mt * 16) * 20 + kw + laneA) * 4);
#pragma unroll
            for (int ntp = 0; ntp < 2; ntp++) {
                unsigned r[4];
                ldsm4(r, bb + ((wn * 32 + ntp * 16) * 20 + kw + laneB) * 4);
                b[2*ntp][0] = r[0]; b[2*ntp][1] = r[1]; b[2*ntp+1][0] = r[2]; b[2*ntp+1][1] = r[3];
            }
#pragma unroll
            for (int mt = 0; mt < 2; mt++)
#pragma unroll
                for (int nt = 0; nt < 4; nt++)
                    mma_f16(c[mt][nt], a[mt], b[nt]);
        }
    }
#pragma unroll
    for (int mt = 0; mt < 2; mt++)
#pragma unroll
        for (int nt = 0; nt < 4; nt++)
#pragma unroll
            for (int rr = 0; rr < 2; rr++) {
                int m = m0 + wm * 32 + mt * 16 + g + rr * 8;
                int b2 = m >> 11, t = m & 2047;
#pragma unroll
                for (int cc = 0; cc < 2; cc++) {
                    int n = n0 + wn * 32 + nt * 8 + 2 * tg + cc;
                    int h = n >> 6, d = n & 63;
                    g_v0[((b2 * NHn + h) * Tn + t) * HSn + d] = c[mt][nt][rr * 2 + cc];
                }
            }
}

// ================= vmix v2: 196608 x 64 x 4096, fp16, register A-gen, k128 chunks =================
// smem words: v0 @0 (128*68=8704), k @8704 (8704), B[2] @17408 (64*68=4352 each) -> 26112
#define VMIX_SMEM_BYTES (26112*4)
#define VPW 68
__global__ void __launch_bounds__(256) vmix_mma(const float* __restrict__ bv) {
    extern __shared__ unsigned sm[];
    float* smf = (float*)sm;
    const unsigned s_base = sptr(sm);
    const int tok0 = blockIdx.x * 128;
    const int tid = threadIdx.x, wid = tid >> 5, lane = tid & 31;
    const int g = lane >> 2, tg = lane & 3;

    // stage v0 (@0) and k (@8704), 128 rows x 64 floats, pitch VPW
#pragma unroll
    for (int p = 0; p < 8; p++) {
        int q = tid + p * 256;
        int row = q >> 4, col = (q & 15) * 4;
        *(float4*)&smf[row * VPW + col]        = *(const float4*)(g_v0 + (tok0 + row) * HSn + col);
        *(float4*)&smf[8704 + row * VPW + col] = *(const float4*)(g_k  + (tok0 + row) * HSn + col);
    }

    auto prefetchB = [&](int ch, int buf) {
#pragma unroll
        for (int p = 0; p < 4; p++) {
            int idx = tid + p * 256;
            int row = idx >> 4, c16 = idx & 15;
            CP16(s_base + (17408 + buf * 4352 + row * VPW + c16 * 4) * 4,
                 g_wv16 + row * 4096 + ch * 128 + c16 * 8);
        }
    };

    prefetchB(0, 0);
    CPCOMMIT();
    __syncthreads();   // v0/k tiles ready

    // hoist per-thread v0 fragment values (same for all chunks)
    const int r0 = wid * 16 + g, r1 = r0 + 8;
    float2 v0r[2][4][2];
#pragma unroll
    for (int s4 = 0; s4 < 4; s4++) {
        v0r[0][s4][0] = *(const float2*)&smf[r0 * VPW + s4 * 16 + 2 * tg];
        v0r[0][s4][1] = *(const float2*)&smf[r0 * VPW + s4 * 16 + 2 * tg + 8];
        v0r[1][s4][0] = *(const float2*)&smf[r1 * VPW + s4 * 16 + 2 * tg];
        v0r[1][s4][1] = *(const float2*)&smf[r1 * VPW + s4 * 16 + 2 * tg + 8];
    }

    float c[8][4];
#pragma unroll
    for (int j = 0; j < 8; j++)
#pragma unroll
        for (int r = 0; r < 4; r++) c[j][r] = 0.f;

    const int lB = (lane & 7) + ((lane >> 4) << 3);
    const int lBo = ((lane >> 3) & 1) * 4;

    for (int ch = 0; ch < 32; ch++) {
        const int buf = ch & 1;
        CPWAIT0();
        __syncthreads();
        if (ch < 31) { prefetchB(ch + 1, buf ^ 1); CPCOMMIT(); }
        const float k0a = smf[8704 + r0 * VPW + 2 * ch];
        const float k0b = smf[8704 + r0 * VPW + 2 * ch + 1];
        const float k1a = smf[8704 + r1 * VPW + 2 * ch];
        const float k1b = smf[8704 + r1 * VPW + 2 * ch + 1];
        const unsigned bbase = s_base + (17408 + buf * 4352) * 4;
#pragma unroll
        for (int s = 0; s < 8; s++) {
            const int s4 = s & 3;
            const float ka = (s < 4) ? k0a : k0b;
            const float kb = (s < 4) ? k1a : k1b;
            unsigned a[4];
            {
                __half2 h0 = __floats2half2_rn(ka * v0r[0][s4][0].x, ka * v0r[0][s4][0].y);
                __half2 h1 = __floats2half2_rn(kb * v0r[1][s4][0].x, kb * v0r[1][s4][0].y);
                __half2 h2 = __floats2half2_rn(ka * v0r[0][s4][1].x, ka * v0r[0][s4][1].y);
                __half2 h3 = __floats2half2_rn(kb * v0r[1][s4][1].x, kb * v0r[1][s4][1].y);
                a[0] = *(unsigned*)&h0; a[1] = *(unsigned*)&h1;
                a[2] = *(unsigned*)&h2; a[3] = *(unsigned*)&h3;
            }
            unsigned b[8][2];
#pragma unroll
            for (int ntp = 0; ntp < 4; ntp++) {
                unsigned r[4];
                ldsm4(r, bbase + ((ntp * 16 + lB) * VPW + s * 8 + lBo) * 4);
                b[2*ntp][0] = r[0]; b[2*ntp][1] = r[1]; b[2*ntp+1][0] = r[2]; b[2*ntp+1][1] = r[3];
            }
#pragma unroll
            for (int nt = 0; nt < 8; nt++)
                mma_f16(c[nt], a, b[nt]);
        }
    }
#pragma unroll
    for (int nt = 0; nt < 8; nt++)
#pragma unroll
        for (int rr = 0; rr < 2; rr++) {
            int t = tok0 + wid * 16 + g + rr * 8;
#pragma unroll
            for (int cc = 0; cc < 2; cc++) {
                int e = nt * 8 + 2 * tg + cc;
                g_v[t * HSn + e] = c[nt][rr * 2 + cc] + bv[e];
            }
        }
}

// ---------------- local scans: tails + level-0 segment sums ----------------
__global__ void scan_kernel() {
    int blk = blockIdx.x;
    int bh = blk >> 4, tb = blk & 15;
    const float* src = blockIdx.y ? g_v : g_k;
    float* tail = blockIdx.y ? g_vtail : g_ktail;
    float* seg  = blockIdx.y ? g_Vs : g_Ks;
    int d = threadIdx.x & 63, grp = threadIdx.x >> 6;
    int t0 = tb * 128 + grp * 16;
    int base = (bh * Tn + t0) * HSn + d;
    float acc = 0.f;
#pragma unroll
    for (int i = 0; i < 16; i++) {
        acc += src[base + i * HSn];
        tail[base + i * HSn] = acc;
    }
    int s0 = t0 >> 4;
    seg[(bh * NSEG + s0) * HSn + d] = acc;
}

// ---------------- level merge: levels 1..7 ----------------
__global__ void merge_kernel() {
    int bh = blockIdx.x;
    float* seg = blockIdx.y ? g_Vs : g_Ks;
    float* base = seg + bh * NSEG * HSn;
    for (int v = 1; v <= 7; v++) {
        int cnt = 128 >> v;
        int cs = 256 - (256 >> v);
        int ps = 256 - (256 >> (v - 1));
        __syncthreads();
        for (int idx = threadIdx.x; idx < cnt * HSn; idx += 256) {
            int i = idx >> 6, d = idx & 63;
            base[(cs + i) * HSn + d] =
                base[(ps + 2 * i) * HSn + d] + base[(ps + 2 * i + 1) * HSn + d];
        }
    }
}

// ---------------- attention: logits + softmax + AV (fp32) ----------------
__global__ void __launch_bounds__(256) attn_kernel() {
    __shared__ float qst[64][32];
    __shared__ float lg[32][257];
    const int bh = blockIdx.y, t0 = blockIdx.x * 32;
    const int tid = threadIdx.x;
    const float scale = 0.125f;
    const int qbase = (bh * Tn + t0) * HSn;

    for (int p = 0; p < 8; p++) {
        int idx = tid + p * 256;
        int t = idx >> 6, d = idx & 63;
        qst[d][t] = g_q[qbase + idx];
    }
    __syncthreads();

    for (int idx = tid; idx < 32 * NSEG; idx += 256) {
        int tl = idx & 31, s = idx >> 5;
        int tg2 = t0 + tl;
        int r = g_ridx[s];
        float val = NEG_INF;
        if (t0 + 31 >= r) {
            const float* Kp = g_Ks + (bh * NSEG + s) * HSn;
            float acc = 0.f;
#pragma unroll
            for (int d = 0; d < 64; d += 4) {
                float4 k4 = *(const float4*)(Kp + d);
                acc += qst[d + 0][tl] * k4.x + qst[d + 1][tl] * k4.y
                     + qst[d + 2][tl] * k4.z + qst[d + 3][tl] * k4.w;
            }
            if (tg2 >= r) val = acc * scale;
        }
        lg[tl][s] = val;
    }

    if (tid < 32) {
        int tl = tid, tg2 = t0 + tl;
        const float* kt = g_ktail + (bh * Tn + tg2) * HSn;
        float acc = 0.f;
#pragma unroll
        for (int d = 0; d < 64; d++) acc += qst[d][tl] * kt[d];
        lg[tl][255] = acc * scale;
    }
    __syncthreads();

    int warp = tid >> 5, lane = tid & 31;
#pragma unroll
    for (int u = 0; u < 4; u++) {
        int t = warp * 4 + u;
        float m = NEG_INF;
        for (int s = lane; s < 256; s += 32) m = fmaxf(m, lg[t][s]);
#pragma unroll
        for (int o = 16; o; o >>= 1) m = fmaxf(m, __shfl_xor_sync(0xffffffffu, m, o));
        float sum = 0.f;
        for (int s = lane; s < 256; s += 32) {
            float p = __expf(lg[t][s] - m);
            lg[t][s] = p;
            sum += p;
        }
#pragma unroll
        for (int o = 16; o; o >>= 1) sum += __shfl_xor_sync(0xffffffffu, sum, o);
        float inv = 1.0f / sum;
        for (int s = lane; s < 256; s += 32) lg[t][s] *= inv;
    }
    __syncthreads();

    const float* Vbase = g_Vs + bh * NSEG * HSn;
    for (int p = 0; p < 8; p++) {
        int idx = tid + p * 256;
        int tl = idx >> 6, d = idx & 63;
        int tg2 = t0 + tl;
        float acc = 0.f;
#pragma unroll
        for (int v = 0; v < 8; v++) {
            int start = 256 - (256 >> v);
            int cnt = (tg2 + 1) >> (4 + v);
            for (int ii = 0; ii < cnt; ii++) {
                int s = start + ii;
                acc += lg[tl][s] * Vbase[s * HSn + d];
            }
        }
        float vt = g_vtail[(bh * Tn + tg2) * HSn + d];
        acc += lg[tl][255] * vt;
        int b = bh / NHn, h = bh - b * NHn;
        int off = (b * Tn + tg2) * Cn + h * HSn + d;
        __nv_bfloat16 hh = __float2bfloat16(acc);
        g_yh[off] = hh;
        g_yl[off] = __float2bfloat16(acc - __bfloat162float(hh));
    }
}

// ---------------- launch ----------------
extern "C" void kernel_launch(void* const* d_in, const int* in_sizes, int n_in,
                              void* d_out, int out_size) {
    const float* x     = (const float*)d_in[0];
    const float* Wqkv  = (const float*)d_in[1];
    const float* Wproj = (const float*)d_in[2];
    const float* Wv    = (const float*)d_in[3];
    const float* bv    = (const float*)d_in[4];
    float* out = (float*)d_out;

    cudaFuncSetAttribute(gemm_big, cudaFuncAttributeMaxDynamicSharedMemorySize, GB_SMEM_BYTES);
    cudaFuncSetAttribute(v0_mma,   cudaFuncAttributeMaxDynamicSharedMemorySize, V0_SMEM_BYTES);
    cudaFuncSetAttribute(vmix_mma, cudaFuncAttributeMaxDynamicSharedMemorySize, VMIX_SMEM_BYTES);

    init_sets_kernel<<<1, 256>>>();
    split_kernel<<<(Bn*Tn*Cn + 255) / 256, 256>>>(x, 0, Bn*Tn*Cn);
    split_kernel<<<(3*Cn*Cn + 255) / 256, 256>>>(Wqkv, 1, 3*Cn*Cn);
    split_kernel<<<(HSn*HSn*HSn + 255) / 256, 256>>>(Wv, 2, HSn*HSn*HSn);
    split_kernel<<<(Cn*Cn + 255) / 256, 256>>>(Wproj, 3, Cn*Cn);
    gemm_big<<<dim3(12, 128), 256, GB_SMEM_BYTES>>>(0, nullptr);   // qk
    v0_mma<<<dim3(12, 128), 256, V0_SMEM_BYTES>>>();
    vmix_mma<<<NTOK / 128, 256, VMIX_SMEM_BYTES>>>(bv);
    scan_kernel<<<dim3(BHn * 16, 2), 512>>>();
    merge_kernel<<<dim3(BHn, 2), 256>>>();
    attn_kernel<<<dim3(Tn / 32, BHn), 256>>>();
    gemm_big<<<dim3(6, 128), 256, GB_SMEM_BYTES>>>(1, out);        // proj
}

// round 10
// speedup vs baseline: 4.2943x; 1.3107x over previous
#include <cuda_runtime.h>
#include <cuda_bf16.h>
#include <cuda_fp16.h>

#define Bn 8
#define Tn 2048
#define Cn 768
#define NHn 12
#define HSn 64
#define BHn (Bn*NHn)        // 96
#define NSEG 255
#define LMIN 16
#define NTOK (BHn*Tn)       // 196608
#define NEG_INF __int_as_float(0xff800000u)

// ---------------- device scratch ----------------
__device__ float g_q    [NTOK*HSn];
__device__ float g_k    [NTOK*HSn];
__device__ float g_v0   [NTOK*HSn];
__device__ float g_v    [NTOK*HSn];
__device__ float g_ktail[NTOK*HSn];
__device__ float g_vtail[NTOK*HSn];
__device__ float g_Ks   [BHn*NSEG*HSn];
__device__ float g_Vs   [BHn*NSEG*HSn];
__device__ half  g_Ksh[BHn*256*HSn], g_Ksl[BHn*256*HSn];
__device__ half  g_Vth[BHn*HSn*256], g_Vtl[BHn*HSn*256];
__device__ __nv_bfloat16 g_yh [Bn*Tn*Cn], g_yl [Bn*Tn*Cn];
__device__ __nv_bfloat16 g_xh [Bn*Tn*Cn], g_xl [Bn*Tn*Cn];
__device__ half          g_x16[Bn*Tn*Cn];
__device__ __nv_bfloat16 g_wqh[3*Cn*Cn],  g_wql[3*Cn*Cn];
__device__ half          g_wq16[3*Cn*Cn];
__device__ __nv_bfloat16 g_wph[Cn*Cn],    g_wpl[Cn*Cn];
__device__ half g_wv16[HSn*HSn*HSn];
__device__ int g_ridx[256];

// ---------------- PTX helpers ----------------
__device__ __forceinline__ unsigned sptr(const void* p) {
    return (unsigned)__cvta_generic_to_shared(p);
}
#define CP16(dst, src) asm volatile("cp.async.ca.shared.global [%0], [%1], 16;\n" :: "r"(dst), "l"(src))
#define CPCOMMIT()     asm volatile("cp.async.commit_group;\n")
#define CPWAIT0()      asm volatile("cp.async.wait_group 0;\n")

__device__ __forceinline__ void ldsm4(unsigned* r, unsigned addr) {
    asm volatile("ldmatrix.sync.aligned.m8n8.x4.shared.b16 {%0,%1,%2,%3}, [%4];\n"
                 : "=r"(r[0]), "=r"(r[1]), "=r"(r[2]), "=r"(r[3]) : "r"(addr));
}
__device__ __forceinline__ void mma_bf16(float* c, const unsigned* a, const unsigned* b) {
    asm volatile(
        "mma.sync.aligned.m16n8k16.row.col.f32.bf16.bf16.f32 "
        "{%0,%1,%2,%3}, {%4,%5,%6,%7}, {%8,%9}, {%0,%1,%2,%3};\n"
        : "+f"(c[0]), "+f"(c[1]), "+f"(c[2]), "+f"(c[3])
        : "r"(a[0]), "r"(a[1]), "r"(a[2]), "r"(a[3]), "r"(b[0]), "r"(b[1]));
}
__device__ __forceinline__ void mma_f16(float* c, const unsigned* a, const unsigned* b) {
    asm volatile(
        "mma.sync.aligned.m16n8k16.row.col.f32.f16.f16.f32 "
        "{%0,%1,%2,%3}, {%4,%5,%6,%7}, {%8,%9}, {%0,%1,%2,%3};\n"
        : "+f"(c[0]), "+f"(c[1]), "+f"(c[2]), "+f"(c[3])
        : "r"(a[0]), "r"(a[1]), "r"(a[2]), "r"(a[3]), "r"(b[0]), "r"(b[1]));
}

// ---------------- init segment r-index ----------------
__global__ void init_sets_kernel() {
    int s = threadIdx.x;
    if (s < NSEG) {
        int v = 0, rem = s;
        while (rem >= (128 >> v)) { rem -= (128 >> v); v++; }
        int L = LMIN << v;
        g_ridx[s] = (rem + 1) * L - 1;
    } else if (s == 255) {
        g_ridx[255] = 0x3fffffff;
    }
}

// ---------------- split fp32 -> hi/lo bf16 + fp16 variants ----------------
__global__ void split_kernel(const float* __restrict__ src, int which, int n) {
    int i = blockIdx.x * 256 + threadIdx.x;
    if (i >= n) return;
    float x = src[i];
    if (which == 2) { g_wv16[i] = __float2half_rn(x); return; }
    __nv_bfloat16 *h, *l;
    switch (which) {
        case 0: h = g_xh;  l = g_xl;  g_x16[i]  = __float2half_rn(x); break;
        case 1: h = g_wqh; l = g_wql; g_wq16[i] = __float2half_rn(x); break;
        default:h = g_wph; l = g_wpl; break;
    }
    __nv_bfloat16 hh = __float2bfloat16(x);
    h[i] = hh;
    l[i] = __float2bfloat16(x - __bfloat162float(hh));
}

// ================= big GEMM (bf16x3, 128x128 tiles): qk (mode 0) / proj (mode 1) =================
#define GB_SMEM_BYTES (20480*4)
__global__ void __launch_bounds__(256) gemm_big(int mode, float* __restrict__ outp) {
    extern __shared__ unsigned sm[];
    const unsigned s_base = sptr(sm);
    const int m0 = blockIdx.y * 128, n0 = blockIdx.x * 128;
    const int tid = threadIdx.x, wid = tid >> 5, lane = tid & 31;
    const int wm = wid >> 1, wn = wid & 1;
    const int g = lane >> 2, tg = lane & 3;
    const int laneA = (lane & 15) * 20 + (lane >> 4) * 4;
    const int laneB = ((lane & 7) + ((lane >> 4) << 3)) * 20 + ((lane >> 3) & 1) * 4;
    const unsigned* ah32 = (const unsigned*)(mode ? g_yh : g_xh);
    const unsigned* al32 = (const unsigned*)(mode ? g_yl : g_xl);
    const unsigned* bh32 = (const unsigned*)(mode ? g_wph : g_wqh);
    const unsigned* bl32 = (const unsigned*)(mode ? g_wpl : g_wql);

    auto prefetch = [&](int kc, int buf) {
        const int k0w = kc * 16;
#pragma unroll
        for (int p = 0; p < 2; p++) {
            int idx = tid + p * 256;
            int row = idx >> 2, c4 = idx & 3;
            unsigned d = (row * 20 + c4 * 4) * 4;
            CP16(s_base + buf * 2560 * 4 + d,             ah32 + (m0 + row) * 384 + k0w + c4 * 4);
            CP16(s_base + (5120 + buf * 2560) * 4 + d,    al32 + (m0 + row) * 384 + k0w + c4 * 4);
            CP16(s_base + (10240 + buf * 2560) * 4 + d,   bh32 + (n0 + row) * 384 + k0w + c4 * 4);
            CP16(s_base + (15360 + buf * 2560) * 4 + d,   bl32 + (n0 + row) * 384 + k0w + c4 * 4);
        }
    };

    float c[2][8][4];
#pragma unroll
    for (int i = 0; i < 2; i++)
#pragma unroll
        for (int j = 0; j < 8; j++)
#pragma unroll
            for (int r = 0; r < 4; r++) c[i][j][r] = 0.f;

    prefetch(0, 0);
    CPCOMMIT();
    for (int kc = 0; kc < 24; kc++) {
        const int buf = kc & 1;
        CPWAIT0();
        __syncthreads();
        if (kc < 23) { prefetch(kc + 1, buf ^ 1); CPCOMMIT(); }
        const unsigned ahb = s_base + (buf * 2560) * 4;
        const unsigned alb = s_base + (5120 + buf * 2560) * 4;
        const unsigned bhb = s_base + (10240 + buf * 2560) * 4;
        const unsigned blb = s_base + (15360 + buf * 2560) * 4;
#pragma unroll
        for (int ks = 0; ks < 2; ks++) {
            const int kw = ks * 8;
            unsigned ah[2][4], al[2][4], bh[8][2], bl[8][2];
#pragma unroll
            for (int mt = 0; mt < 2; mt++) {
                unsigned off = ((wm * 32 + mt * 16) * 20 + kw + laneA) * 4;
                ldsm4(ah[mt], ahb + off);
                ldsm4(al[mt], alb + off);
            }
#pragma unroll
            for (int ntp = 0; ntp < 4; ntp++) {
                unsigned off = ((wn * 64 + ntp * 16) * 20 + kw + laneB) * 4;
                unsigned r[4];
                ldsm4(r, bhb + off);
                bh[2*ntp][0] = r[0]; bh[2*ntp][1] = r[1]; bh[2*ntp+1][0] = r[2]; bh[2*ntp+1][1] = r[3];
                ldsm4(r, blb + off);
                bl[2*ntp][0] = r[0]; bl[2*ntp][1] = r[1]; bl[2*ntp+1][0] = r[2]; bl[2*ntp+1][1] = r[3];
            }
#pragma unroll
            for (int mt = 0; mt < 2; mt++)
#pragma unroll
                for (int nt = 0; nt < 8; nt++) {
                    mma_bf16(c[mt][nt], ah[mt], bh[nt]);
                    mma_bf16(c[mt][nt], ah[mt], bl[nt]);
                    mma_bf16(c[mt][nt], al[mt], bh[nt]);
                }
        }
    }
#pragma unroll
    for (int mt = 0; mt < 2; mt++)
#pragma unroll
        for (int nt = 0; nt < 8; nt++)
#pragma unroll
            for (int rr = 0; rr < 2; rr++) {
                int m = m0 + wm * 32 + mt * 16 + g + rr * 8;
#pragma unroll
                for (int cc = 0; cc < 2; cc++) {
                    int n = n0 + wn * 64 + nt * 8 + 2 * tg + cc;
                    float val = c[mt][nt][rr * 2 + cc];
                    if (mode) {
                        outp[m * Cn + n] = val;
                    } else {
                        int b = m >> 11, t = m & 2047;
                        int which = (n >= Cn) ? 1 : 0;
                        int col = n - which * Cn;
                        int h = col >> 6, d = col & 63;
                        float* dst = which ? g_k : g_q;
                        dst[((b * NHn + h) * Tn + t) * HSn + d] = val;
                    }
                }
            }
}

// ================= v0 GEMM: 16384 x 768 x 768, single fp16 =================
#define V0_SMEM_BYTES (7680*4)
__global__ void __launch_bounds__(256) v0_mma() {
    extern __shared__ unsigned sm[];
    const unsigned s_base = sptr(sm);
    const int m0 = blockIdx.y * 128, n0 = blockIdx.x * 64;
    const int tid = threadIdx.x, wid = tid >> 5, lane = tid & 31;
    const int wm = wid >> 1, wn = wid & 1;
    const int g = lane >> 2, tg = lane & 3;
    const int laneA = (lane & 15) * 20 + (lane >> 4) * 4;
    const int laneB = ((lane & 7) + ((lane >> 4) << 3)) * 20 + ((lane >> 3) & 1) * 4;
    const unsigned* x32 = (const unsigned*)g_x16;
    const unsigned* w32 = (const unsigned*)(g_wq16 + 2 * Cn * Cn);  // v0 rows

    auto prefetch = [&](int kc, int buf) {
        const int k0w = kc * 16;
#pragma unroll
        for (int p = 0; p < 2; p++) {
            int idx = tid + p * 256;
            int row = idx >> 2, c4 = idx & 3;
            unsigned d = (row * 20 + c4 * 4) * 4;
            CP16(s_base + buf * 2560 * 4 + d, x32 + (m0 + row) * 384 + k0w + c4 * 4);
        }
        {
            int row = tid >> 2, c4 = tid & 3;
            unsigned d = (row * 20 + c4 * 4) * 4;
            CP16(s_base + (5120 + buf * 1280) * 4 + d, w32 + (n0 + row) * 384 + k0w + c4 * 4);
        }
    };

    float c[2][4][4];
#pragma unroll
    for (int i = 0; i < 2; i++)
#pragma unroll
        for (int j = 0; j < 4; j++)
#pragma unroll
            for (int r = 0; r < 4; r++) c[i][j][r] = 0.f;

    prefetch(0, 0);
    CPCOMMIT();
    for (int kc = 0; kc < 24; kc++) {
        const int buf = kc & 1;
        CPWAIT0();
        __syncthreads();
        if (kc < 23) { prefetch(kc + 1, buf ^ 1); CPCOMMIT(); }
        const unsigned ab = s_base + (buf * 2560) * 4;
        const unsigned bb = s_base + (5120 + buf * 1280) * 4;
#pragma unroll
        for (int ks = 0; ks < 2; ks++) {
            const int kw = ks * 8;
            unsigned a[2][4], b[4][2];
#pragma unroll
            for (int mt = 0; mt < 2; mt++)
                ldsm4(a[mt], ab + ((wm * 32 + mt * 16) * 20 + kw + laneA) * 4);
#pragma unroll
            for (int ntp = 0; ntp < 2; ntp++) {
                unsigned r[4];
                ldsm4(r, bb + ((wn * 32 + ntp * 16) * 20 + kw + laneB) * 4);
                b[2*ntp][0] = r[0]; b[2*ntp][1] = r[1]; b[2*ntp+1][0] = r[2]; b[2*ntp+1][1] = r[3];
            }
#pragma unroll
            for (int mt = 0; mt < 2; mt++)
#pragma unroll
                for (int nt = 0; nt < 4; nt++)
                    mma_f16(c[mt][nt], a[mt], b[nt]);
        }
    }
#pragma unroll
    for (int mt = 0; mt < 2; mt++)
#pragma unroll
        for (int nt = 0; nt < 4; nt++)
#pragma unroll
            for (int rr = 0; rr < 2; rr++) {
                int m = m0 + wm * 32 + mt * 16 + g + rr * 8;
                int b2 = m >> 11, t = m & 2047;
#pragma unroll
                for (int cc = 0; cc < 2; cc++) {
                    int n = n0 + wn * 32 + nt * 8 + 2 * tg + cc;
                    int h = n >> 6, d = n & 63;
                    g_v0[((b2 * NHn + h) * Tn + t) * HSn + d] = c[mt][nt][rr * 2 + cc];
                }
            }
}

// ================= vmix v2: 196608 x 64 x 4096, fp16, register A-gen, k128 chunks =================
#define VMIX_SMEM_BYTES (26112*4)
#define VPW 68
__global__ void __launch_bounds__(256) vmix_mma(const float* __restrict__ bv) {
    extern __shared__ unsigned sm[];
    float* smf = (float*)sm;
    const unsigned s_base = sptr(sm);
    const int tok0 = blockIdx.x * 128;
    const int tid = threadIdx.x, wid = tid >> 5, lane = tid & 31;
    const int g = lane >> 2, tg = lane & 3;

#pragma unroll
    for (int p = 0; p < 8; p++) {
        int q = tid + p * 256;
        int row = q >> 4, col = (q & 15) * 4;
        *(float4*)&smf[row * VPW + col]        = *(const float4*)(g_v0 + (tok0 + row) * HSn + col);
        *(float4*)&smf[8704 + row * VPW + col] = *(const float4*)(g_k  + (tok0 + row) * HSn + col);
    }

    auto prefetchB = [&](int ch, int buf) {
#pragma unroll
        for (int p = 0; p < 4; p++) {
            int idx = tid + p * 256;
            int row = idx >> 4, c16 = idx & 15;
            CP16(s_base + (17408 + buf * 4352 + row * VPW + c16 * 4) * 4,
                 g_wv16 + row * 4096 + ch * 128 + c16 * 8);
        }
    };

    prefetchB(0, 0);
    CPCOMMIT();
    __syncthreads();

    const int r0 = wid * 16 + g, r1 = r0 + 8;
    float2 v0r[2][4][2];
#pragma unroll
    for (int s4 = 0; s4 < 4; s4++) {
        v0r[0][s4][0] = *(const float2*)&smf[r0 * VPW + s4 * 16 + 2 * tg];
        v0r[0][s4][1] = *(const float2*)&smf[r0 * VPW + s4 * 16 + 2 * tg + 8];
        v0r[1][s4][0] = *(const float2*)&smf[r1 * VPW + s4 * 16 + 2 * tg];
        v0r[1][s4][1] = *(const float2*)&smf[r1 * VPW + s4 * 16 + 2 * tg + 8];
    }

    float c[8][4];
#pragma unroll
    for (int j = 0; j < 8; j++)
#pragma unroll
        for (int r = 0; r < 4; r++) c[j][r] = 0.f;

    const int lB = (lane & 7) + ((lane >> 4) << 3);
    const int lBo = ((lane >> 3) & 1) * 4;

    for (int ch = 0; ch < 32; ch++) {
        const int buf = ch & 1;
        CPWAIT0();
        __syncthreads();
        if (ch < 31) { prefetchB(ch + 1, buf ^ 1); CPCOMMIT(); }
        const float k0a = smf[8704 + r0 * VPW + 2 * ch];
        const float k0b = smf[8704 + r0 * VPW + 2 * ch + 1];
        const float k1a = smf[8704 + r1 * VPW + 2 * ch];
        const float k1b = smf[8704 + r1 * VPW + 2 * ch + 1];
        const unsigned bbase = s_base + (17408 + buf * 4352) * 4;
#pragma unroll
        for (int s = 0; s < 8; s++) {
            const int s4 = s & 3;
            const float ka = (s < 4) ? k0a : k0b;
            const float kb = (s < 4) ? k1a : k1b;
            unsigned a[4];
            {
                __half2 h0 = __floats2half2_rn(ka * v0r[0][s4][0].x, ka * v0r[0][s4][0].y);
                __half2 h1 = __floats2half2_rn(kb * v0r[1][s4][0].x, kb * v0r[1][s4][0].y);
                __half2 h2 = __floats2half2_rn(ka * v0r[0][s4][1].x, ka * v0r[0][s4][1].y);
                __half2 h3 = __floats2half2_rn(kb * v0r[1][s4][1].x, kb * v0r[1][s4][1].y);
                a[0] = *(unsigned*)&h0; a[1] = *(unsigned*)&h1;
                a[2] = *(unsigned*)&h2; a[3] = *(unsigned*)&h3;
            }
            unsigned b[8][2];
#pragma unroll
            for (int ntp = 0; ntp < 4; ntp++) {
                unsigned r[4];
                ldsm4(r, bbase + ((ntp * 16 + lB) * VPW + s * 8 + lBo) * 4);
                b[2*ntp][0] = r[0]; b[2*ntp][1] = r[1]; b[2*ntp+1][0] = r[2]; b[2*ntp+1][1] = r[3];
            }
#pragma unroll
            for (int nt = 0; nt < 8; nt++)
                mma_f16(c[nt], a, b[nt]);
        }
    }
#pragma unroll
    for (int nt = 0; nt < 8; nt++)
#pragma unroll
        for (int rr = 0; rr < 2; rr++) {
            int t = tok0 + wid * 16 + g + rr * 8;
#pragma unroll
            for (int cc = 0; cc < 2; cc++) {
                int e = nt * 8 + 2 * tg + cc;
                g_v[t * HSn + e] = c[nt][rr * 2 + cc] + bv[e];
            }
        }
}

// ---------------- local scans: tails + level-0 segment sums ----------------
__global__ void scan_kernel() {
    int blk = blockIdx.x;
    int bh = blk >> 4, tb = blk & 15;
    const float* src = blockIdx.y ? g_v : g_k;
    float* tail = blockIdx.y ? g_vtail : g_ktail;
    float* seg  = blockIdx.y ? g_Vs : g_Ks;
    int d = threadIdx.x & 63, grp = threadIdx.x >> 6;
    int t0 = tb * 128 + grp * 16;
    int base = (bh * Tn + t0) * HSn + d;
    float acc = 0.f;
#pragma unroll
    for (int i = 0; i < 16; i++) {
        acc += src[base + i * HSn];
        tail[base + i * HSn] = acc;
    }
    int s0 = t0 >> 4;
    seg[(bh * NSEG + s0) * HSn + d] = acc;
}

// ---------------- level merge: levels 1..7 ----------------
__global__ void merge_kernel() {
    int bh = blockIdx.x;
    float* seg = blockIdx.y ? g_Vs : g_Ks;
    float* base = seg + bh * NSEG * HSn;
    for (int v = 1; v <= 7; v++) {
        int cnt = 128 >> v;
        int cs = 256 - (256 >> v);
        int ps = 256 - (256 >> (v - 1));
        __syncthreads();
        for (int idx = threadIdx.x; idx < cnt * HSn; idx += 256) {
            int i = idx >> 6, d = idx & 63;
            base[(cs + i) * HSn + d] =
                base[(ps + 2 * i) * HSn + d] + base[(ps + 2 * i + 1) * HSn + d];
        }
    }
}

// ---------------- convert segments to fp16 hi/lo (Ks rows, Vs transposed) ----------------
__global__ void seg_half_kernel() {
    int bh = blockIdx.x;
    for (int idx = threadIdx.x; idx < 256 * 64; idx += 256) {
        int s = idx >> 6, d = idx & 63;
        float kv = (s < NSEG) ? g_Ks[(bh * NSEG + s) * 64 + d] : 0.f;
        float vv = (s < NSEG) ? g_Vs[(bh * NSEG + s) * 64 + d] : 0.f;
        half kh = __float2half_rn(kv);
        g_Ksh[bh * 16384 + idx] = kh;
        g_Ksl[bh * 16384 + idx] = __float2half_rn(kv - __half2float(kh));
        half vh = __float2half_rn(vv);
        g_Vth[bh * 16384 + d * 256 + s] = vh;
        g_Vtl[bh * 16384 + d * 256 + s] = __float2half_rn(vv - __half2float(vh));
    }
}

// ================= tensor-core attention =================
// smem word layout:
//  qh @0 (32*36=1152), ql @1152, Ksh @2304 (256*36=9216), Ksl @11520,
//  Vth @20736 (64*132=8448), Vtl @29184, Ph @37632 (32*132=4224), Pl @41856,
//  lg @46080 (32*260=8320)  -> 54400 words
#define ATTN_SMEM_BYTES (54400*4)
#define TILES_PER_BLK 16
__global__ void __launch_bounds__(256) attn_kernel() {
    extern __shared__ unsigned sm[];
    float* lg = (float*)(sm + 46080);
    const unsigned s_base = sptr(sm);
    const int bh = blockIdx.y;
    const int tid = threadIdx.x, wid = tid >> 5, lane = tid & 31;
    const int wm = wid & 1, wn = wid >> 1;
    const int g = lane >> 2, tg = lane & 3;
    const float scale = 0.125f;
    const int lA = (lane & 15);
    const int lAo = (lane >> 4) * 4;
    const int lB = (lane & 7) + ((lane >> 4) << 3);
    const int lBo = ((lane >> 3) & 1) * 4;

    // ---- stage Ks hi/lo + Vt hi/lo (shared across tiles) ----
#pragma unroll
    for (int p = 0; p < 8; p++) {
        int idx = tid + p * 256;
        {
            int row = idx >> 3, ch = idx & 7;
            unsigned d = (2304 + row * 36 + ch * 4) * 4;
            CP16(s_base + d,               g_Ksh + bh * 16384 + idx * 8);
            CP16(s_base + d + 9216 * 4,    g_Ksl + bh * 16384 + idx * 8);
        }
        {
            int row = idx >> 5, ch = idx & 31;
            unsigned d = (20736 + row * 132 + ch * 4) * 4;
            CP16(s_base + d,               g_Vth + bh * 16384 + idx * 8);
            CP16(s_base + d + 8448 * 4,    g_Vtl + bh * 16384 + idx * 8);
        }
    }
    CPCOMMIT();
    CPWAIT0();
    __syncthreads();

    for (int it = 0; it < TILES_PER_BLK; it++) {
        const int t0g = (blockIdx.x * TILES_PER_BLK + it) * 32;
        // ---- stage q tile as fp16 hi/lo ----
#pragma unroll
        for (int u = 0; u < 4; u++) {
            int widx = tid * 4 + u;
            int row = widx >> 5, col2 = widx & 31;
            float2 f = *(const float2*)(g_q + (bh * Tn + t0g + row) * 64 + col2 * 2);
            __half2 h = __floats2half2_rn(f.x, f.y);
            float2 hf = __half22float2(h);
            __half2 l = __floats2half2_rn(f.x - hf.x, f.y - hf.y);
            sm[row * 36 + col2]        = *(unsigned*)&h;
            sm[1152 + row * 36 + col2] = *(unsigned*)&l;
        }
        __syncthreads();

        // ---- logits MMA: 32 x 256, K=64, fp16x3 ----
        {
            float cl[8][4];
#pragma unroll
            for (int j = 0; j < 8; j++)
#pragma unroll
                for (int r = 0; r < 4; r++) cl[j][r] = 0.f;
#pragma unroll
            for (int ks = 0; ks < 4; ks++) {
                unsigned ah[4], al[4], bhf[8][2], blf[8][2];
                unsigned aoff = ((wm * 16 + lA) * 36 + ks * 8 + lAo) * 4;
                ldsm4(ah, s_base + aoff);
                ldsm4(al, s_base + 1152 * 4 + aoff);
#pragma unroll
                for (int ntp = 0; ntp < 4; ntp++) {
                    unsigned boff = ((wn * 64 + ntp * 16 + lB) * 36 + ks * 8 + lBo) * 4;
                    unsigned r[4];
                    ldsm4(r, s_base + 2304 * 4 + boff);
                    bhf[2*ntp][0] = r[0]; bhf[2*ntp][1] = r[1];
                    bhf[2*ntp+1][0] = r[2]; bhf[2*ntp+1][1] = r[3];
                    ldsm4(r, s_base + 11520 * 4 + boff);
                    blf[2*ntp][0] = r[0]; blf[2*ntp][1] = r[1];
                    blf[2*ntp+1][0] = r[2]; blf[2*ntp+1][1] = r[3];
                }
#pragma unroll
                for (int nt = 0; nt < 8; nt++) {
                    mma_f16(cl[nt], ah, bhf[nt]);
                    mma_f16(cl[nt], ah, blf[nt]);
                    mma_f16(cl[nt], al, bhf[nt]);
                }
            }
            // mask + store to lg
#pragma unroll
            for (int nt = 0; nt < 8; nt++)
#pragma unroll
                for (int rr = 0; rr < 2; rr++) {
                    int tl = wm * 16 + g + rr * 8;
                    int tg2 = t0g + tl;
#pragma unroll
                    for (int cc = 0; cc < 2; cc++) {
                        int s = wn * 64 + nt * 8 + 2 * tg + cc;
                        float val = (tg2 >= g_ridx[s]) ? cl[nt][rr * 2 + cc] * scale : NEG_INF;
                        lg[tl * 260 + s] = val;
                    }
                }
        }
        __syncthreads();

        // ---- tail logit: 8 threads per token ----
        {
            int tl = tid >> 3, dl = (tid & 7) * 8;
            int tg2 = t0g + tl;
            const float* qrow = g_q     + (bh * Tn + tg2) * 64 + dl;
            const float* krow = g_ktail + (bh * Tn + tg2) * 64 + dl;
            float acc = 0.f;
#pragma unroll
            for (int d = 0; d < 8; d++) acc += qrow[d] * krow[d];
#pragma unroll
            for (int o = 4; o; o >>= 1) acc += __shfl_xor_sync(0xffffffffu, acc, o);
            if ((lane & 7) == 0) lg[tl * 260 + 255] = acc * scale;
        }
        __syncthreads();

        // ---- softmax over 256 entries ----
#pragma unroll
        for (int u = 0; u < 4; u++) {
            int t = wid * 4 + u;
            float m = NEG_INF;
            for (int s = lane; s < 256; s += 32) m = fmaxf(m, lg[t * 260 + s]);
#pragma unroll
            for (int o = 16; o; o >>= 1) m = fmaxf(m, __shfl_xor_sync(0xffffffffu, m, o));
            float sum = 0.f;
            for (int s = lane; s < 256; s += 32) {
                float p = __expf(lg[t * 260 + s] - m);
                lg[t * 260 + s] = p;
                sum += p;
            }
#pragma unroll
            for (int o = 16; o; o >>= 1) sum += __shfl_xor_sync(0xffffffffu, sum, o);
            float inv = 1.0f / sum;
            for (int s = lane; s < 256; s += 32) lg[t * 260 + s] *= inv;
        }
        __syncthreads();

        // ---- convert probs to fp16 hi/lo (zero tail column for MMA) ----
        {
            int tl = tid >> 3, s0 = (tid & 7) * 32;
#pragma unroll
            for (int u = 0; u < 16; u++) {
                int s = s0 + u * 2;
                float f0 = (s   == 255) ? 0.f : lg[tl * 260 + s];
                float f1 = (s+1 == 255) ? 0.f : lg[tl * 260 + s + 1];
                __half2 h = __floats2half2_rn(f0, f1);
                float2 hf = __half22float2(h);
                __half2 l = __floats2half2_rn(f0 - hf.x, f1 - hf.y);
                int w = tl * 132 + (s >> 1);
                sm[37632 + w] = *(unsigned*)&h;
                sm[41856 + w] = *(unsigned*)&l;
            }
        }
        __syncthreads();

        // ---- AV MMA: 32 x 64, K=256, fp16x3, + tail term ----
        {
            float cv[2][4];
#pragma unroll
            for (int j = 0; j < 2; j++)
#pragma unroll
                for (int r = 0; r < 4; r++) cv[j][r] = 0.f;
#pragma unroll
            for (int ks = 0; ks < 16; ks++) {
                unsigned aph[4], apl[4], bvh[2][2], bvl[2][2];
                unsigned aoff = ((wm * 16 + lA) * 132 + ks * 8 + lAo) * 4;
                ldsm4(aph, s_base + 37632 * 4 + aoff);
                ldsm4(apl, s_base + 41856 * 4 + aoff);
                unsigned boff = ((wn * 16 + lB) * 132 + ks * 8 + lBo) * 4;
                unsigned r[4];
                ldsm4(r, s_base + 20736 * 4 + boff);
                bvh[0][0] = r[0]; bvh[0][1] = r[1]; bvh[1][0] = r[2]; bvh[1][1] = r[3];
                ldsm4(r, s_base + 29184 * 4 + boff);
                bvl[0][0] = r[0]; bvl[0][1] = r[1]; bvl[1][0] = r[2]; bvl[1][1] = r[3];
#pragma unroll
                for (int nt = 0; nt < 2; nt++) {
                    mma_f16(cv[nt], aph, bvh[nt]);
                    mma_f16(cv[nt], aph, bvl[nt]);
                    mma_f16(cv[nt], apl, bvh[nt]);
                }
            }
#pragma unroll
            for (int nt = 0; nt < 2; nt++)
#pragma unroll
                for (int rr = 0; rr < 2; rr++) {
                    int tl = wm * 16 + g + rr * 8;
                    int tg2 = t0g + tl;
                    float pt = lg[tl * 260 + 255];
#pragma unroll
                    for (int cc = 0; cc < 2; cc++) {
                        int d = wn * 16 + nt * 8 + 2 * tg + cc;
                        float acc = cv[nt][rr * 2 + cc]
                                  + pt * g_vtail[(bh * Tn + tg2) * 64 + d];
                        int b = bh / NHn, h = bh - b * NHn;
                        int off = (b * Tn + tg2) * Cn + h * 64 + d;
                        __nv_bfloat16 hh = __float2bfloat16(acc);
                        g_yh[off] = hh;
                        g_yl[off] = __float2bfloat16(acc - __bfloat162float(hh));
                    }
                }
        }
        __syncthreads();
    }
}

// ---------------- launch ----------------
extern "C" void kernel_launch(void* const* d_in, const int* in_sizes, int n_in,
                              void* d_out, int out_size) {
    const float* x     = (const float*)d_in[0];
    const float* Wqkv  = (const float*)d_in[1];
    const float* Wproj = (const float*)d_in[2];
    const float* Wv    = (const float*)d_in[3];
    const float* bv    = (const float*)d_in[4];
    float* out = (float*)d_out;

    cudaFuncSetAttribute(gemm_big,    cudaFuncAttributeMaxDynamicSharedMemorySize, GB_SMEM_BYTES);
    cudaFuncSetAttribute(v0_mma,      cudaFuncAttributeMaxDynamicSharedMemorySize, V0_SMEM_BYTES);
    cudaFuncSetAttribute(vmix_mma,    cudaFuncAttributeMaxDynamicSharedMemorySize, VMIX_SMEM_BYTES);
    cudaFuncSetAttribute(attn_kernel, cudaFuncAttributeMaxDynamicSharedMemorySize, ATTN_SMEM_BYTES);

    init_sets_kernel<<<1, 256>>>();
    split_kernel<<<(Bn*Tn*Cn + 255) / 256, 256>>>(x, 0, Bn*Tn*Cn);
    split_kernel<<<(3*Cn*Cn + 255) / 256, 256>>>(Wqkv, 1, 3*Cn*Cn);
    split_kernel<<<(HSn*HSn*HSn + 255) / 256, 256>>>(Wv, 2, HSn*HSn*HSn);
    split_kernel<<<(Cn*Cn + 255) / 256, 256>>>(Wproj, 3, Cn*Cn);
    gemm_big<<<dim3(12, 128), 256, GB_SMEM_BYTES>>>(0, nullptr);   // qk
    v0_mma<<<dim3(12, 128), 256, V0_SMEM_BYTES>>>();
    vmix_mma<<<NTOK / 128, 256, VMIX_SMEM_BYTES>>>(bv);
    scan_kernel<<<dim3(BHn * 16, 2), 512>>>();
    merge_kernel<<<dim3(BHn, 2), 256>>>();
    seg_half_kernel<<<BHn, 256>>>();
    attn_kernel<<<dim3(Tn / 32 / TILES_PER_BLK, BHn), 256, ATTN_SMEM_BYTES>>>();
    gemm_big<<<dim3(6, 128), 256, GB_SMEM_BYTES>>>(1, out);        // proj
}

// round 12
// speedup vs baseline: 4.3966x; 1.0238x over previous
#include <cuda_runtime.h>
#include <cuda_bf16.h>
#include <cuda_fp16.h>

#define Bn 8
#define Tn 2048
#define Cn 768
#define NHn 12
#define HSn 64
#define BHn (Bn*NHn)        // 96
#define NSEG 255
#define LMIN 16
#define NTOK (BHn*Tn)       // 196608
#define NEG_INF __int_as_float(0xff800000u)

// ---------------- device scratch ----------------
__device__ float g_q    [NTOK*HSn];
__device__ float g_k    [NTOK*HSn];
__device__ float g_v0   [NTOK*HSn];
__device__ float g_v    [NTOK*HSn];
__device__ float g_ktail[NTOK*HSn];
__device__ float g_vtail[NTOK*HSn];
__device__ float g_Ks   [BHn*NSEG*HSn];
__device__ float g_Vs   [BHn*NSEG*HSn];
__device__ half  g_Ksh[BHn*256*HSn], g_Ksl[BHn*256*HSn];
__device__ half  g_Vth[BHn*HSn*256], g_Vtl[BHn*HSn*256];
__device__ half  g_yh16[Bn*Tn*Cn], g_yl16[Bn*Tn*Cn];
__device__ __nv_bfloat16 g_xh [Bn*Tn*Cn], g_xl [Bn*Tn*Cn];
__device__ half          g_x16[Bn*Tn*Cn];
__device__ __nv_bfloat16 g_wqh[3*Cn*Cn],  g_wql[3*Cn*Cn];
__device__ half          g_wq16[3*Cn*Cn];
__device__ half g_wp16[Cn*Cn];
__device__ half g_wv16[HSn*HSn*HSn];
__device__ int g_ridx[256];

// ---------------- PTX helpers ----------------
__device__ __forceinline__ unsigned sptr(const void* p) {
    return (unsigned)__cvta_generic_to_shared(p);
}
#define CP16(dst, src) asm volatile("cp.async.ca.shared.global [%0], [%1], 16;\n" :: "r"(dst), "l"(src))
#define CPCOMMIT()     asm volatile("cp.async.commit_group;\n")
#define CPWAIT0()      asm volatile("cp.async.wait_group 0;\n")

__device__ __forceinline__ void ldsm4(unsigned* r, unsigned addr) {
    asm volatile("ldmatrix.sync.aligned.m8n8.x4.shared.b16 {%0,%1,%2,%3}, [%4];\n"
                 : "=r"(r[0]), "=r"(r[1]), "=r"(r[2]), "=r"(r[3]) : "r"(addr));
}
__device__ __forceinline__ void mma_bf16(float* c, const unsigned* a, const unsigned* b) {
    asm volatile(
        "mma.sync.aligned.m16n8k16.row.col.f32.bf16.bf16.f32 "
        "{%0,%1,%2,%3}, {%4,%5,%6,%7}, {%8,%9}, {%0,%1,%2,%3};\n"
        : "+f"(c[0]), "+f"(c[1]), "+f"(c[2]), "+f"(c[3])
        : "r"(a[0]), "r"(a[1]), "r"(a[2]), "r"(a[3]), "r"(b[0]), "r"(b[1]));
}
__device__ __forceinline__ void mma_f16(float* c, const unsigned* a, const unsigned* b) {
    asm volatile(
        "mma.sync.aligned.m16n8k16.row.col.f32.f16.f16.f32 "
        "{%0,%1,%2,%3}, {%4,%5,%6,%7}, {%8,%9}, {%0,%1,%2,%3};\n"
        : "+f"(c[0]), "+f"(c[1]), "+f"(c[2]), "+f"(c[3])
        : "r"(a[0]), "r"(a[1]), "r"(a[2]), "r"(a[3]), "r"(b[0]), "r"(b[1]));
}

// ---------------- init segment r-index ----------------
__global__ void init_sets_kernel() {
    int s = threadIdx.x;
    if (s < NSEG) {
        int v = 0, rem = s;
        while (rem >= (128 >> v)) { rem -= (128 >> v); v++; }
        int L = LMIN << v;
        g_ridx[s] = (rem + 1) * L - 1;
    } else if (s == 255) {
        g_ridx[255] = 0x3fffffff;
    }
}

// ---------------- fused split: all four weight/input arrays in one launch ----------------
#define NX   (Bn*Tn*Cn)       // 12582912
#define NWQ  (3*Cn*Cn)        // 1769472
#define NWV  (HSn*HSn*HSn)    // 262144
#define NWP  (Cn*Cn)          // 589824
#define NSPLIT (NX + NWQ + NWV + NWP)
__global__ void split_all_kernel(const float* __restrict__ x, const float* __restrict__ wq,
                                 const float* __restrict__ wv, const float* __restrict__ wp) {
    int i = blockIdx.x * 256 + threadIdx.x;
    if (i >= NSPLIT) return;
    if (i < NX) {
        float v = x[i];
        __nv_bfloat16 hh = __float2bfloat16(v);
        g_xh[i] = hh;
        g_xl[i] = __float2bfloat16(v - __bfloat162float(hh));
        g_x16[i] = __float2half_rn(v);
        return;
    }
    i -= NX;
    if (i < NWQ) {
        float v = wq[i];
        __nv_bfloat16 hh = __float2bfloat16(v);
        g_wqh[i] = hh;
        g_wql[i] = __float2bfloat16(v - __bfloat162float(hh));
        g_wq16[i] = __float2half_rn(v);
        return;
    }
    i -= NWQ;
    if (i < NWV) { g_wv16[i] = __float2half_rn(wv[i]); return; }
    i -= NWV;
    g_wp16[i] = __float2half_rn(wp[i]);
}

// ================= qk GEMM (bf16x3, 128x128 tiles) =================
#define GB_SMEM_BYTES (20480*4)
__global__ void __launch_bounds__(256) qk_mma() {
    extern __shared__ unsigned sm[];
    const unsigned s_base = sptr(sm);
    const int m0 = blockIdx.y * 128, n0 = blockIdx.x * 128;
    const int tid = threadIdx.x, wid = tid >> 5, lane = tid & 31;
    const int wm = wid >> 1, wn = wid & 1;
    const int g = lane >> 2, tg = lane & 3;
    const int laneA = (lane & 15) * 20 + (lane >> 4) * 4;
    const int laneB = ((lane & 7) + ((lane >> 4) << 3)) * 20 + ((lane >> 3) & 1) * 4;
    const unsigned* ah32 = (const unsigned*)g_xh;
    const unsigned* al32 = (const unsigned*)g_xl;
    const unsigned* bh32 = (const unsigned*)g_wqh;
    const unsigned* bl32 = (const unsigned*)g_wql;

    auto prefetch = [&](int kc, int buf) {
        const int k0w = kc * 16;
#pragma unroll
        for (int p = 0; p < 2; p++) {
            int idx = tid + p * 256;
            int row = idx >> 2, c4 = idx & 3;
            unsigned d = (row * 20 + c4 * 4) * 4;
            CP16(s_base + buf * 2560 * 4 + d,             ah32 + (m0 + row) * 384 + k0w + c4 * 4);
            CP16(s_base + (5120 + buf * 2560) * 4 + d,    al32 + (m0 + row) * 384 + k0w + c4 * 4);
            CP16(s_base + (10240 + buf * 2560) * 4 + d,   bh32 + (n0 + row) * 384 + k0w + c4 * 4);
            CP16(s_base + (15360 + buf * 2560) * 4 + d,   bl32 + (n0 + row) * 384 + k0w + c4 * 4);
        }
    };

    float c[2][8][4];
#pragma unroll
    for (int i = 0; i < 2; i++)
#pragma unroll
        for (int j = 0; j < 8; j++)
#pragma unroll
            for (int r = 0; r < 4; r++) c[i][j][r] = 0.f;

    prefetch(0, 0);
    CPCOMMIT();
    for (int kc = 0; kc < 24; kc++) {
        const int buf = kc & 1;
        CPWAIT0();
        __syncthreads();
        if (kc < 23) { prefetch(kc + 1, buf ^ 1); CPCOMMIT(); }
        const unsigned ahb = s_base + (buf * 2560) * 4;
        const unsigned alb = s_base + (5120 + buf * 2560) * 4;
        const unsigned bhb = s_base + (10240 + buf * 2560) * 4;
        const unsigned blb = s_base + (15360 + buf * 2560) * 4;
#pragma unroll
        for (int ks = 0; ks < 2; ks++) {
            const int kw = ks * 8;
            unsigned ah[2][4], al[2][4], bh[8][2], bl[8][2];
#pragma unroll
            for (int mt = 0; mt < 2; mt++) {
                unsigned off = ((wm * 32 + mt * 16) * 20 + kw + laneA) * 4;
                ldsm4(ah[mt], ahb + off);
                ldsm4(al[mt], alb + off);
            }
#pragma unroll
            for (int ntp = 0; ntp < 4; ntp++) {
                unsigned off = ((wn * 64 + ntp * 16) * 20 + kw + laneB) * 4;
                unsigned r[4];
                ldsm4(r, bhb + off);
                bh[2*ntp][0] = r[0]; bh[2*ntp][1] = r[1]; bh[2*ntp+1][0] = r[2]; bh[2*ntp+1][1] = r[3];
                ldsm4(r, blb + off);
                bl[2*ntp][0] = r[0]; bl[2*ntp][1] = r[1]; bl[2*ntp+1][0] = r[2]; bl[2*ntp+1][1] = r[3];
            }
#pragma unroll
            for (int mt = 0; mt < 2; mt++)
#pragma unroll
                for (int nt = 0; nt < 8; nt++) {
                    mma_bf16(c[mt][nt], ah[mt], bh[nt]);
                    mma_bf16(c[mt][nt], ah[mt], bl[nt]);
                    mma_bf16(c[mt][nt], al[mt], bh[nt]);
                }
        }
    }
#pragma unroll
    for (int mt = 0; mt < 2; mt++)
#pragma unroll
        for (int nt = 0; nt < 8; nt++)
#pragma unroll
            for (int rr = 0; rr < 2; rr++) {
                int m = m0 + wm * 32 + mt * 16 + g + rr * 8;
                int b = m >> 11, t = m & 2047;
#pragma unroll
                for (int cc = 0; cc < 2; cc++) {
                    int n = n0 + wn * 64 + nt * 8 + 2 * tg + cc;
                    float val = c[mt][nt][rr * 2 + cc];
                    int which = (n >= Cn) ? 1 : 0;
                    int col = n - which * Cn;
                    int h = col >> 6, d = col & 63;
                    float* dst = which ? g_k : g_q;
                    dst[((b * NHn + h) * Tn + t) * HSn + d] = val;
                }
            }
}

// ================= proj GEMM (fp16x2: y hi/lo x single W), 128x128 tiles =================
// smem words: AH[2][2560]@0, AL[2][2560]@5120, B[2][2560]@10240 -> 15360
#define PROJ_SMEM_BYTES (15360*4)
__global__ void __launch_bounds__(256) proj_f16(float* __restrict__ outp) {
    extern __shared__ unsigned sm[];
    const unsigned s_base = sptr(sm);
    const int m0 = blockIdx.y * 128, n0 = blockIdx.x * 128;
    const int tid = threadIdx.x, wid = tid >> 5, lane = tid & 31;
    const int wm = wid >> 1, wn = wid & 1;
    const int g = lane >> 2, tg = lane & 3;
    const int laneA = (lane & 15) * 20 + (lane >> 4) * 4;
    const int laneB = ((lane & 7) + ((lane >> 4) << 3)) * 20 + ((lane >> 3) & 1) * 4;
    const unsigned* ah32 = (const unsigned*)g_yh16;
    const unsigned* al32 = (const unsigned*)g_yl16;
    const unsigned* b32  = (const unsigned*)g_wp16;

    auto prefetch = [&](int kc, int buf) {
        const int k0w = kc * 16;
#pragma unroll
        for (int p = 0; p < 2; p++) {
            int idx = tid + p * 256;
            int row = idx >> 2, c4 = idx & 3;
            unsigned d = (row * 20 + c4 * 4) * 4;
            CP16(s_base + buf * 2560 * 4 + d,            ah32 + (m0 + row) * 384 + k0w + c4 * 4);
            CP16(s_base + (5120 + buf * 2560) * 4 + d,   al32 + (m0 + row) * 384 + k0w + c4 * 4);
            CP16(s_base + (10240 + buf * 2560) * 4 + d,  b32  + (n0 + row) * 384 + k0w + c4 * 4);
        }
    };

    float c[2][8][4];
#pragma unroll
    for (int i = 0; i < 2; i++)
#pragma unroll
        for (int j = 0; j < 8; j++)
#pragma unroll
            for (int r = 0; r < 4; r++) c[i][j][r] = 0.f;

    prefetch(0, 0);
    CPCOMMIT();
    for (int kc = 0; kc < 24; kc++) {
        const int buf = kc & 1;
        CPWAIT0();
        __syncthreads();
        if (kc < 23) { prefetch(kc + 1, buf ^ 1); CPCOMMIT(); }
        const unsigned ahb = s_base + (buf * 2560) * 4;
        const unsigned alb = s_base + (5120 + buf * 2560) * 4;
        const unsigned bb  = s_base + (10240 + buf * 2560) * 4;
#pragma unroll
        for (int ks = 0; ks < 2; ks++) {
            const int kw = ks * 8;
            unsigned ah[2][4], al[2][4], b[8][2];
#pragma unroll
            for (int mt = 0; mt < 2; mt++) {
                unsigned off = ((wm * 32 + mt * 16) * 20 + kw + laneA) * 4;
                ldsm4(ah[mt], ahb + off);
                ldsm4(al[mt], alb + off);
            }
#pragma unroll
            for (int ntp = 0; ntp < 4; ntp++) {
                unsigned off = ((wn * 64 + ntp * 16) * 20 + kw + laneB) * 4;
                unsigned r[4];
                ldsm4(r, bb + off);
                b[2*ntp][0] = r[0]; b[2*ntp][1] = r[1]; b[2*ntp+1][0] = r[2]; b[2*ntp+1][1] = r[3];
            }
#pragma unroll
            for (int mt = 0; mt < 2; mt++)
#pragma unroll
                for (int nt = 0; nt < 8; nt++) {
                    mma_f16(c[mt][nt], ah[mt], b[nt]);
                    mma_f16(c[mt][nt], al[mt], b[nt]);
                }
        }
    }
#pragma unroll
    for (int mt = 0; mt < 2; mt++)
#pragma unroll
        for (int nt = 0; nt < 8; nt++)
#pragma unroll
            for (int rr = 0; rr < 2; rr++) {
                int m = m0 + wm * 32 + mt * 16 + g + rr * 8;
#pragma unroll
                for (int cc = 0; cc < 2; cc++) {
                    int n = n0 + wn * 64 + nt * 8 + 2 * tg + cc;
                    outp[m * Cn + n] = c[mt][nt][rr * 2 + cc];
                }
            }
}

// ================= v0 GEMM: 16384 x 768 x 768, single fp16 =================
#define V0_SMEM_BYTES (7680*4)
__global__ void __launch_bounds__(256) v0_mma() {
    extern __shared__ unsigned sm[];
    const unsigned s_base = sptr(sm);
    const int m0 = blockIdx.y * 128, n0 = blockIdx.x * 64;
    const int tid = threadIdx.x, wid = tid >> 5, lane = tid & 31;
    const int wm = wid >> 1, wn = wid & 1;
    const int g = lane >> 2, tg = lane & 3;
    const int laneA = (lane & 15) * 20 + (lane >> 4) * 4;
    const int laneB = ((lane & 7) + ((lane >> 4) << 3)) * 20 + ((lane >> 3) & 1) * 4;
    const unsigned* x32 = (const unsigned*)g_x16;
    const unsigned* w32 = (const unsigned*)(g_wq16 + 2 * Cn * Cn);  // v0 rows

    auto prefetch = [&](int kc, int buf) {
        const int k0w = kc * 16;
#pragma unroll
        for (int p = 0; p < 2; p++) {
            int idx = tid + p * 256;
            int row = idx >> 2, c4 = idx & 3;
            unsigned d = (row * 20 + c4 * 4) * 4;
            CP16(s_base + buf * 2560 * 4 + d, x32 + (m0 + row) * 384 + k0w + c4 * 4);
        }
        {
            int row = tid >> 2, c4 = tid & 3;
            unsigned d = (row * 20 + c4 * 4) * 4;
            CP16(s_base + (5120 + buf * 1280) * 4 + d, w32 + (n0 + row) * 384 + k0w + c4 * 4);
        }
    };

    float c[2][4][4];
#pragma unroll
    for (int i = 0; i < 2; i++)
#pragma unroll
        for (int j = 0; j < 4; j++)
#pragma unroll
            for (int r = 0; r < 4; r++) c[i][j][r] = 0.f;

    prefetch(0, 0);
    CPCOMMIT();
    for (int kc = 0; kc < 24; kc++) {
        const int buf = kc & 1;
        CPWAIT0();
        __syncthreads();
        if (kc < 23) { prefetch(kc + 1, buf ^ 1); CPCOMMIT(); }
        const unsigned ab = s_base + (buf * 2560) * 4;
        const unsigned bb = s_base + (5120 + buf * 1280) * 4;
#pragma unroll
        for (int ks = 0; ks < 2; ks++) {
            const int kw = ks * 8;
            unsigned a[2][4], b[4][2];
#pragma unroll
            for (int mt = 0; mt < 2; mt++)
                ldsm4(a[mt], ab + ((wm * 32 + mt * 16) * 20 + kw + laneA) * 4);
#pragma unroll
            for (int ntp = 0; ntp < 2; ntp++) {
                unsigned r[4];
                ldsm4(r, bb + ((wn * 32 + ntp * 16) * 20 + kw + laneB) * 4);
                b[2*ntp][0] = r[0]; b[2*ntp][1] = r[1]; b[2*ntp+1][0] = r[2]; b[2*ntp+1][1] = r[3];
            }
#pragma unroll
            for (int mt = 0; mt < 2; mt++)
#pragma unroll
                for (int nt = 0; nt < 4; nt++)
                    mma_f16(c[mt][nt], a[mt], b[nt]);
        }
    }
#pragma unroll
    for (int mt = 0; mt < 2; mt++)
#pragma unroll
        for (int nt = 0; nt < 4; nt++)
#pragma unroll
            for (int rr = 0; rr < 2; rr++) {
                int m = m0 + wm * 32 + mt * 16 + g + rr * 8;
                int b2 = m >> 11, t = m & 2047;
#pragma unroll
                for (int cc = 0; cc < 2; cc++) {
                    int n = n0 + wn * 32 + nt * 8 + 2 * tg + cc;
                    int h = n >> 6, d = n & 63;
                    g_v0[((b2 * NHn + h) * Tn + t) * HSn + d] = c[mt][nt][rr * 2 + cc];
                }
            }
}

// ================= vmix: 196608 x 64 x 4096, fp16, half2 A-gen, k128 chunks =================
#define VMIX_SMEM_BYTES (26112*4)
#define VPW 68
__global__ void __launch_bounds__(256) vmix_mma(const float* __restrict__ bv) {
    extern __shared__ unsigned sm[];
    float* smf = (float*)sm;
    const unsigned s_base = sptr(sm);
    const int tok0 = blockIdx.x * 128;
    const int tid = threadIdx.x, wid = tid >> 5, lane = tid & 31;
    const int g = lane >> 2, tg = lane & 3;

#pragma unroll
    for (int p = 0; p < 8; p++) {
        int q = tid + p * 256;
        int row = q >> 4, col = (q & 15) * 4;
        *(float4*)&smf[row * VPW + col]        = *(const float4*)(g_v0 + (tok0 + row) * HSn + col);
        *(float4*)&smf[8704 + row * VPW + col] = *(const float4*)(g_k  + (tok0 + row) * HSn + col);
    }

    auto prefetchB = [&](int ch, int buf) {
#pragma unroll
        for (int p = 0; p < 4; p++) {
            int idx = tid + p * 256;
            int row = idx >> 4, c16 = idx & 15;
            CP16(s_base + (17408 + buf * 4352 + row * VPW + c16 * 4) * 4,
                 g_wv16 + row * 4096 + ch * 128 + c16 * 8);
        }
    };

    prefetchB(0, 0);
    CPCOMMIT();
    __syncthreads();

    const int r0 = wid * 16 + g, r1 = r0 + 8;
    __half2 v0h[2][4][2];
#pragma unroll
    for (int s4 = 0; s4 < 4; s4++) {
        float2 f;
        f = *(const float2*)&smf[r0 * VPW + s4 * 16 + 2 * tg];     v0h[0][s4][0] = __floats2half2_rn(f.x, f.y);
        f = *(const float2*)&smf[r0 * VPW + s4 * 16 + 2 * tg + 8]; v0h[0][s4][1] = __floats2half2_rn(f.x, f.y);
        f = *(const float2*)&smf[r1 * VPW + s4 * 16 + 2 * tg];     v0h[1][s4][0] = __floats2half2_rn(f.x, f.y);
        f = *(const float2*)&smf[r1 * VPW + s4 * 16 + 2 * tg + 8]; v0h[1][s4][1] = __floats2half2_rn(f.x, f.y);
    }

    float c[8][4];
#pragma unroll
    for (int j = 0; j < 8; j++)
#pragma unroll
        for (int r = 0; r < 4; r++) c[j][r] = 0.f;

    const int lB = (lane & 7) + ((lane >> 4) << 3);
    const int lBo = ((lane >> 3) & 1) * 4;

    for (int ch = 0; ch < 32; ch++) {
        const int buf = ch & 1;
        CPWAIT0();
        __syncthreads();
        if (ch < 31) { prefetchB(ch + 1, buf ^ 1); CPCOMMIT(); }
        const __half2 k0a2 = __float2half2_rn(smf[8704 + r0 * VPW + 2 * ch]);
        const __half2 k0b2 = __float2half2_rn(smf[8704 + r0 * VPW + 2 * ch + 1]);
        const __half2 k1a2 = __float2half2_rn(smf[8704 + r1 * VPW + 2 * ch]);
        const __half2 k1b2 = __float2half2_rn(smf[8704 + r1 * VPW + 2 * ch + 1]);
        const unsigned bbase = s_base + (17408 + buf * 4352) * 4;
#pragma unroll
        for (int s = 0; s < 8; s++) {
            const int s4 = s & 3;
            const __half2 ka2 = (s < 4) ? k0a2 : k0b2;
            const __half2 kb2 = (s < 4) ? k1a2 : k1b2;
            unsigned a[4];
            {
                __half2 h0 = __hmul2(ka2, v0h[0][s4][0]);
                __half2 h1 = __hmul2(kb2, v0h[1][s4][0]);
                __half2 h2 = __hmul2(ka2, v0h[0][s4][1]);
                __half2 h3 = __hmul2(kb2, v0h[1][s4][1]);
                a[0] = *(unsigned*)&h0; a[1] = *(unsigned*)&h1;
                a[2] = *(unsigned*)&h2; a[3] = *(unsigned*)&h3;
            }
            unsigned b[8][2];
#pragma unroll
            for (int ntp = 0; ntp < 4; ntp++) {
                unsigned r[4];
                ldsm4(r, bbase + ((ntp * 16 + lB) * VPW + s * 8 + lBo) * 4);
                b[2*ntp][0] = r[0]; b[2*ntp][1] = r[1]; b[2*ntp+1][0] = r[2]; b[2*ntp+1][1] = r[3];
            }
#pragma unroll
            for (int nt = 0; nt < 8; nt++)
                mma_f16(c[nt], a, b[nt]);
        }
    }
#pragma unroll
    for (int nt = 0; nt < 8; nt++)
#pragma unroll
        for (int rr = 0; rr < 2; rr++) {
            int t = tok0 + wid * 16 + g + rr * 8;
#pragma unroll
            for (int cc = 0; cc < 2; cc++) {
                int e = nt * 8 + 2 * tg + cc;
                g_v[t * HSn + e] = c[nt][rr * 2 + cc] + bv[e];
            }
        }
}

// ---------------- local scans: tails + level-0 segment sums ----------------
__global__ void scan_kernel() {
    int blk = blockIdx.x;
    int bh = blk >> 4, tb = blk & 15;
    const float* src = blockIdx.y ? g_v : g_k;
    float* tail = blockIdx.y ? g_vtail : g_ktail;
    float* seg  = blockIdx.y ? g_Vs : g_Ks;
    int d = threadIdx.x & 63, grp = threadIdx.x >> 6;
    int t0 = tb * 128 + grp * 16;
    int base = (bh * Tn + t0) * HSn + d;
    float acc = 0.f;
#pragma unroll
    for (int i = 0; i < 16; i++) {
        acc += src[base + i * HSn];
        tail[base + i * HSn] = acc;
    }
    int s0 = t0 >> 4;
    seg[(bh * NSEG + s0) * HSn + d] = acc;
}

// ---------------- level merge + fp16 hi/lo conversion (fused) ----------------
__global__ void merge_kernel() {
    int bh = blockIdx.x;
    int isv = blockIdx.y;
    float* seg = isv ? g_Vs : g_Ks;
    float* base = seg + bh * NSEG * HSn;
    for (int v = 1; v <= 7; v++) {
        int cnt = 128 >> v;
        int cs = 256 - (256 >> v);
        int ps = 256 - (256 >> (v - 1));
        __syncthreads();
        for (int idx = threadIdx.x; idx < cnt * HSn; idx += 256) {
            int i = idx >> 6, d = idx & 63;
            base[(cs + i) * HSn + d] =
                base[(ps + 2 * i) * HSn + d] + base[(ps + 2 * i + 1) * HSn + d];
        }
    }
    __syncthreads();
    if (isv == 0) {
        for (int idx = threadIdx.x; idx < 256 * 64; idx += 256) {
            int s = idx >> 6;
            float kv = (s < NSEG) ? base[idx] : 0.f;
            half kh = __float2half_rn(kv);
            g_Ksh[bh * 16384 + idx] = kh;
            g_Ksl[bh * 16384 + idx] = __float2half_rn(kv - __half2float(kh));
        }
    } else {
        for (int idx = threadIdx.x; idx < 256 * 64; idx += 256) {
            int s = idx >> 6, d = idx & 63;
            float vv = (s < NSEG) ? base[s * 64 + d] : 0.f;
            half vh = __float2half_rn(vv);
            g_Vth[bh * 16384 + d * 256 + s] = vh;
            g_Vtl[bh * 16384 + d * 256 + s] = __float2half_rn(vv - __half2float(vh));
        }
    }
}

// ================= tensor-core attention =================
// smem word layout:
//  qh @0 (32*36=1152), ql @1152, Ksh @2304 (256*36=9216), Ksl @11520,
//  Vth @20736 (64*132=8448), Vtl @29184, Ph @37632 (32*132=4224), Pl @41856,
//  lg @46080 (32*260=8320)  -> 54400 words
#define ATTN_SMEM_BYTES (54400*4)
#define TILES_PER_BLK 16
__global__ void __launch_bounds__(256) attn_kernel() {
    extern __shared__ unsigned sm[];
    float* lg = (float*)(sm + 46080);
    const unsigned s_base = sptr(sm);
    const int bh = blockIdx.y;
    const int tid = threadIdx.x, wid = tid >> 5, lane = tid & 31;
    const int wm = wid & 1, wn = wid >> 1;
    const int g = lane >> 2, tg = lane & 3;
    const float scale = 0.125f;
    const int lA = (lane & 15);
    const int lAo = (lane >> 4) * 4;
    const int lB = (lane & 7) + ((lane >> 4) << 3);
    const int lBo = ((lane >> 3) & 1) * 4;

    // ---- stage Ks hi/lo + Vt hi/lo (shared across tiles) ----
#pragma unroll
    for (int p = 0; p < 8; p++) {
        int idx = tid + p * 256;
        {
            int row = idx >> 3, ch = idx & 7;
            unsigned d = (2304 + row * 36 + ch * 4) * 4;
            CP16(s_base + d,               g_Ksh + bh * 16384 + idx * 8);
            CP16(s_base + d + 9216 * 4,    g_Ksl + bh * 16384 + idx * 8);
        }
        {
            int row = idx >> 5, ch = idx & 31;
            unsigned d = (20736 + row * 132 + ch * 4) * 4;
            CP16(s_base + d,               g_Vth + bh * 16384 + idx * 8);
            CP16(s_base + d + 8448 * 4,    g_Vtl + bh * 16384 + idx * 8);
        }
    }
    CPCOMMIT();
    CPWAIT0();
    __syncthreads();

    for (int it = 0; it < TILES_PER_BLK; it++) {
        const int t0g = (blockIdx.x * TILES_PER_BLK + it) * 32;
        // ---- stage q tile as fp16 hi/lo ----
#pragma unroll
        for (int u = 0; u < 4; u++) {
            int widx = tid * 4 + u;
            int row = widx >> 5, col2 = widx & 31;
            float2 f = *(const float2*)(g_q + (bh * Tn + t0g + row) * 64 + col2 * 2);
            __half2 h = __floats2half2_rn(f.x, f.y);
            float2 hf = __half22float2(h);
            __half2 l = __floats2half2_rn(f.x - hf.x, f.y - hf.y);
            sm[row * 36 + col2]        = *(unsigned*)&h;
            sm[1152 + row * 36 + col2] = *(unsigned*)&l;
        }
        __syncthreads();

        // ---- logits MMA: 32 x 256, K=64, fp16x3 ----
        {
            float cl[8][4];
#pragma unroll
            for (int j = 0; j < 8; j++)
#pragma unroll
                for (int r = 0; r < 4; r++) cl[j][r] = 0.f;
#pragma unroll
            for (int ks = 0; ks < 4; ks++) {
                unsigned ah[4], al[4], bhf[8][2], blf[8][2];
                unsigned aoff = ((wm * 16 + lA) * 36 + ks * 8 + lAo) * 4;
                ldsm4(ah, s_base + aoff);
                ldsm4(al, s_base + 1152 * 4 + aoff);
#pragma unroll
                for (int ntp = 0; ntp < 4; ntp++) {
                    unsigned boff = ((wn * 64 + ntp * 16 + lB) * 36 + ks * 8 + lBo) * 4;
                    unsigned r[4];
                    ldsm4(r, s_base + 2304 * 4 + boff);
                    bhf[2*ntp][0] = r[0]; bhf[2*ntp][1] = r[1];
                    bhf[2*ntp+1][0] = r[2]; bhf[2*ntp+1][1] = r[3];
                    ldsm4(r, s_base + 11520 * 4 + boff);
                    blf[2*ntp][0] = r[0]; blf[2*ntp][1] = r[1];
                    blf[2*ntp+1][0] = r[2]; blf[2*ntp+1][1] = r[3];
                }
#pragma unroll
                for (int nt = 0; nt < 8; nt++) {
                    mma_f16(cl[nt], ah, bhf[nt]);
                    mma_f16(cl[nt], ah, blf[nt]);
                    mma_f16(cl[nt], al, bhf[nt]);
                }
            }
            // mask + store to lg
#pragma unroll
            for (int nt = 0; nt < 8; nt++)
#pragma unroll
                for (int rr = 0; rr < 2; rr++) {
                    int tl = wm * 16 + g + rr * 8;
                    int tg2 = t0g + tl;
#pragma unroll
                    for (int cc = 0; cc < 2; cc++) {
                        int s = wn * 64 + nt * 8 + 2 * tg + cc;
                        float val = (tg2 >= g_ridx[s]) ? cl[nt][rr * 2 + cc] * scale : NEG_INF;
                        lg[tl * 260 + s] = val;
                    }
                }
        }
        __syncthreads();

        // ---- tail logit: 8 threads per token ----
        {
            int tl = tid >> 3, dl = (tid & 7) * 8;
            int tg2 = t0g + tl;
            const float* qrow = g_q     + (bh * Tn + tg2) * 64 + dl;
            const float* krow = g_ktail + (bh * Tn + tg2) * 64 + dl;
            float acc = 0.f;
#pragma unroll
            for (int d = 0; d < 8; d++) acc += qrow[d] * krow[d];
#pragma unroll
            for (int o = 4; o; o >>= 1) acc += __shfl_xor_sync(0xffffffffu, acc, o);
            if ((lane & 7) == 0) lg[tl * 260 + 255] = acc * scale;
        }
        __syncthreads();

        // ---- softmax over 256 entries ----
#pragma unroll
        for (int u = 0; u < 4; u++) {
            int t = wid * 4 + u;
            float m = NEG_INF;
            for (int s = lane; s < 256; s += 32) m = fmaxf(m, lg[t * 260 + s]);
#pragma unroll
            for (int o = 16; o; o >>= 1) m = fmaxf(m, __shfl_xor_sync(0xffffffffu, m, o));
            float sum = 0.f;
            for (int s = lane; s < 256; s += 32) {
                float p = __expf(lg[t * 260 + s] - m);
                lg[t * 260 + s] = p;
                sum += p;
            }
#pragma unroll
            for (int o = 16; o; o >>= 1) sum += __shfl_xor_sync(0xffffffffu, sum, o);
            float inv = 1.0f / sum;
            for (int s = lane; s < 256; s += 32) lg[t * 260 + s] *= inv;
        }
        __syncthreads();

        // ---- convert probs to fp16 hi/lo (zero tail column for MMA) ----
        {
            int tl = tid >> 3, s0 = (tid & 7) * 32;
#pragma unroll
            for (int u = 0; u < 16; u++) {
                int s = s0 + u * 2;
                float f0 = (s   == 255) ? 0.f : lg[tl * 260 + s];
                float f1 = (s+1 == 255) ? 0.f : lg[tl * 260 + s + 1];
                __half2 h = __floats2half2_rn(f0, f1);
                float2 hf = __half22float2(h);
                __half2 l = __floats2half2_rn(f0 - hf.x, f1 - hf.y);
                int w = tl * 132 + (s >> 1);
                sm[37632 + w] = *(unsigned*)&h;
                sm[41856 + w] = *(unsigned*)&l;
            }
        }
        __syncthreads();

        // ---- AV MMA: 32 x 64, K=256, fp16x3, + tail term ----
        {
            float cv[2][4];
#pragma unroll
            for (int j = 0; j < 2; j++)
#pragma unroll
                for (int r = 0; r < 4; r++) cv[j][r] = 0.f;
#pragma unroll
            for (int ks = 0; ks < 16; ks++) {
                unsigned aph[4], apl[4], bvh[2][2], bvl[2][2];
                unsigned aoff = ((wm * 16 + lA) * 132 + ks * 8 + lAo) * 4;
                ldsm4(aph, s_base + 37632 * 4 + aoff);
                ldsm4(apl, s_base + 41856 * 4 + aoff);
                unsigned boff = ((wn * 16 + lB) * 132 + ks * 8 + lBo) * 4;
                unsigned r[4];
                ldsm4(r, s_base + 20736 * 4 + boff);
                bvh[0][0] = r[0]; bvh[0][1] = r[1]; bvh[1][0] = r[2]; bvh[1][1] = r[3];
                ldsm4(r, s_base + 29184 * 4 + boff);
                bvl[0][0] = r[0]; bvl[0][1] = r[1]; bvl[1][0] = r[2]; bvl[1][1] = r[3];
#pragma unroll
                for (int nt = 0; nt < 2; nt++) {
                    mma_f16(cv[nt], aph, bvh[nt]);
                    mma_f16(cv[nt], aph, bvl[nt]);
                    mma_f16(cv[nt], apl, bvh[nt]);
                }
            }
#pragma unroll
            for (int nt = 0; nt < 2; nt++)
#pragma unroll
                for (int rr = 0; rr < 2; rr++) {
                    int tl = wm * 16 + g + rr * 8;
                    int tg2 = t0g + tl;
                    float pt = lg[tl * 260 + 255];
#pragma unroll
                    for (int cc = 0; cc < 2; cc++) {
                        int d = wn * 16 + nt * 8 + 2 * tg + cc;
                        float acc = cv[nt][rr * 2 + cc]
                                  + pt * g_vtail[(bh * Tn + tg2) * 64 + d];
                        int b = bh / NHn, h = bh - b * NHn;
                        int off = (b * Tn + tg2) * Cn + h * 64 + d;
                        half hh = __float2half_rn(acc);
                        g_yh16[off] = hh;
                        g_yl16[off] = __float2half_rn(acc - __half2float(hh));
                    }
                }
        }
        __syncthreads();
    }
}

// ---------------- launch ----------------
extern "C" void kernel_launch(void* const* d_in, const int* in_sizes, int n_in,
                              void* d_out, int out_size) {
    const float* x     = (const float*)d_in[0];
    const float* Wqkv  = (const float*)d_in[1];
    const float* Wproj = (const float*)d_in[2];
    const float* Wv    = (const float*)d_in[3];
    const float* bv    = (const float*)d_in[4];
    float* out = (float*)d_out;

    cudaFuncSetAttribute(qk_mma,      cudaFuncAttributeMaxDynamicSharedMemorySize, GB_SMEM_BYTES);
    cudaFuncSetAttribute(proj_f16,    cudaFuncAttributeMaxDynamicSharedMemorySize, PROJ_SMEM_BYTES);
    cudaFuncSetAttribute(v0_mma,      cudaFuncAttributeMaxDynamicSharedMemorySize, V0_SMEM_BYTES);
    cudaFuncSetAttribute(vmix_mma,    cudaFuncAttributeMaxDynamicSharedMemorySize, VMIX_SMEM_BYTES);
    cudaFuncSetAttribute(attn_kernel, cudaFuncAttributeMaxDynamicSharedMemorySize, ATTN_SMEM_BYTES);

    init_sets_kernel<<<1, 256>>>();
    split_all_kernel<<<(NSPLIT + 255) / 256, 256>>>(x, Wqkv, Wv, Wproj);
    qk_mma<<<dim3(12, 128), 256, GB_SMEM_BYTES>>>();
    v0_mma<<<dim3(12, 128), 256, V0_SMEM_BYTES>>>();
    vmix_mma<<<NTOK / 128, 256, VMIX_SMEM_BYTES>>>(bv);
    scan_kernel<<<dim3(BHn * 16, 2), 512>>>();
    merge_kernel<<<dim3(BHn, 2), 256>>>();
    attn_kernel<<<dim3(Tn / 32 / TILES_PER_BLK, BHn), 256, ATTN_SMEM_BYTES>>>();
    proj_f16<<<dim3(6, 128), 256, PROJ_SMEM_BYTES>>>(out);
}